// round 10
// baseline (speedup 1.0000x reference)
#include <cuda_runtime.h>
#include <cuda_bf16.h>
#include <cstdint>
#include <math.h>

#define NN   20000
#define EE   100000
#define F1   167
#define HIDD 1024
#define EDK  10
#define EAC  12
#define BNCH 40

// ---------------- scratch (device globals) ----------------
__device__ float g_lin[(size_t)NN * HIDD];
__device__ float g_hg [(size_t)NN * HIDD];
__device__ float g_h  [(size_t)NN * HIDD];
__device__ float g_logw[(size_t)EE * 4];
__device__ float g_ssrc[(size_t)NN * 4];
__device__ float g_sdst[(size_t)NN * 4];
__device__ float g_part1[BNCH * HIDD];
__device__ float g_part2[BNCH * HIDD];
__device__ float g_scale[HIDD];
__device__ float g_shift[HIDD];
__device__ float g_ve[EDK * 4];
__device__ int   g_deg[NN];
__device__ int   g_off[NN + 1];
__device__ int   g_cur[NN];
__device__ int   g_eid[EE];
__device__ __nv_bfloat16 g_Ah[(size_t)NN * HIDD];
__device__ __nv_bfloat16 g_Al[(size_t)NN * HIDD];
__device__ __nv_bfloat16 g_B1h[(size_t)HIDD * HIDD];
__device__ __nv_bfloat16 g_B1l[(size_t)HIDD * HIDD];
__device__ __nv_bfloat16 g_B2h[(size_t)HIDD * HIDD];
__device__ __nv_bfloat16 g_B2l[(size_t)HIDD * HIDD];

// ---------------- BatchNorm: partials (no pre-zero needed) ----------------
__global__ void k_bnstat(const float* __restrict__ x, float* __restrict__ p1,
                         float* __restrict__ p2, int F) {
    int c = blockIdx.x * blockDim.x + threadIdx.x;
    if (c >= F) return;
    int chunk = (NN + BNCH - 1) / BNCH;
    int r0 = blockIdx.y * chunk;
    int r1 = r0 + chunk; if (r1 > NN) r1 = NN;
    float a = 0.f, b = 0.f;
    for (int r = r0; r < r1; r++) {
        float v = x[(size_t)r * F + c];
        a += v; b += v * v;
    }
    p1[blockIdx.y * F + c] = a;
    p2[blockIdx.y * F + c] = b;
}

__global__ void k_bnfin(const float* __restrict__ p1, const float* __restrict__ p2,
                        const float* __restrict__ g, const float* __restrict__ b,
                        float* __restrict__ scale, float* __restrict__ shift, int F) {
    int c = blockIdx.x * blockDim.x + threadIdx.x;
    if (c >= F) return;
    float a = 0.f, s = 0.f;
    for (int y = 0; y < BNCH; y++) { a += p1[y * F + c]; s += p2[y * F + c]; }
    float invN = 1.f / (float)NN;
    float mu = a * invN;
    float var = s * invN - mu * mu;
    float rstd = rsqrtf(var + 1e-5f);
    float sc = rstd * g[c];
    scale[c] = sc;
    shift[c] = b[c] - mu * sc;
}

// ---------------- fused prep: A-split + both B-splits + zero ssrc/sdst ----------------
__global__ void k_prep(const float* __restrict__ x, const float* __restrict__ scale,
                       const float* __restrict__ shift,
                       __nv_bfloat16* __restrict__ Ah, __nv_bfloat16* __restrict__ Al,
                       const float* __restrict__ W1, const float* __restrict__ W2,
                       __nv_bfloat16* __restrict__ B1h, __nv_bfloat16* __restrict__ B1l,
                       __nv_bfloat16* __restrict__ B2h, __nv_bfloat16* __restrict__ B2l,
                       float* __restrict__ ssrc, float* __restrict__ sdst,
                       int F, int Kp) {
    size_t na = (size_t)NN * Kp;
    size_t nb = (size_t)HIDD * Kp;
    size_t i = (size_t)blockIdx.x * blockDim.x + threadIdx.x;
    if (i < na) {
        int m = (int)(i / Kp), k = (int)(i % Kp);
        float v = 0.f;
        if (k < F) v = x[(size_t)m * F + k] * scale[k] + shift[k];
        __nv_bfloat16 h = __float2bfloat16(v);
        Ah[i] = h;
        Al[i] = __float2bfloat16(v - __bfloat162float(h));
    } else if (i < na + 2 * nb) {
        size_t j = i - na;
        const float* W = (j < nb) ? W1 : W2;
        __nv_bfloat16* Bh = (j < nb) ? B1h : B2h;
        __nv_bfloat16* Bl = (j < nb) ? B1l : B2l;
        if (j >= nb) j -= nb;
        int n = (int)(j / Kp), k = (int)(j % Kp);
        float v = (k < F) ? W[(size_t)k * HIDD + n] : 0.f;
        __nv_bfloat16 h = __float2bfloat16(v);
        Bh[j] = h;
        Bl[j] = __float2bfloat16(v - __bfloat162float(h));
    } else if (i < na + 2 * nb + (size_t)NN * 4) {
        ssrc[i - na - 2 * nb] = 0.f;
    } else if (i < na + 2 * nb + (size_t)NN * 8) {
        sdst[i - na - 2 * nb - (size_t)NN * 4] = 0.f;
    }
}

// ---------------- mma.sync helpers ----------------
__device__ __forceinline__ uint32_t smem_u32(const void* p) {
    uint32_t a;
    asm("{ .reg .u64 t; cvta.to.shared.u64 t, %1; cvt.u32.u64 %0, t; }" : "=r"(a) : "l"(p));
    return a;
}
__device__ __forceinline__ void sts128(uint32_t addr, uint4 v) {
    asm volatile("st.shared.v4.b32 [%0], {%1,%2,%3,%4};"
                 :: "r"(addr), "r"(v.x), "r"(v.y), "r"(v.z), "r"(v.w) : "memory");
}
__device__ __forceinline__ void cpasync16(uint32_t s, const void* g) {
    asm volatile("cp.async.cg.shared.global [%0], [%1], 16;" :: "r"(s), "l"(g));
}
#define CP_COMMIT() asm volatile("cp.async.commit_group;" ::: "memory")
#define CP_WAIT0()  asm volatile("cp.async.wait_group 0;" ::: "memory")
#define SWZ(x) ((x) ^ (((x) >> 3) & 0x70))

#define LDSM4(r0, r1, r2, r3, addr) \
    asm volatile("ldmatrix.sync.aligned.m8n8.x4.shared.b16 {%0,%1,%2,%3}, [%4];" \
                 : "=r"(r0), "=r"(r1), "=r"(r2), "=r"(r3) : "r"(addr))

#define MMA_BF16(d, a0, a1, a2, a3, b0, b1) \
    asm volatile("mma.sync.aligned.m16n8k16.row.col.f32.bf16.bf16.f32 " \
                 "{%0,%1,%2,%3}, {%4,%5,%6,%7}, {%8,%9}, {%0,%1,%2,%3};" \
                 : "+f"((d)[0]), "+f"((d)[1]), "+f"((d)[2]), "+f"((d)[3]) \
                 : "r"(a0), "r"(a1), "r"(a2), "r"(a3), "r"(b0), "r"(b1))

// ---------------- split-bf16 GEMM: 128x256 CTA tile, 512 threads ----------------
// warp grid 2x8, warp tile 64x32. acc = 64 regs/thread -> no spills, 4 warps/SMSP.
// grid.x = 8 n-tiles: 0-3 -> (B1 -> C1), 4-7 -> (B2 -> C2, + fused attn dots).
#define STAGE_BYTES 98304   // A: 2*16KB, B: 2*32KB
#define GT_SMEM (2 * STAGE_BYTES + 1024)

__global__ __launch_bounds__(512, 1) void gemm_mma(
    const __nv_bfloat16* __restrict__ Ah, const __nv_bfloat16* __restrict__ Al, int Kp,
    const __nv_bfloat16* __restrict__ B1h, const __nv_bfloat16* __restrict__ B1l,
    const __nv_bfloat16* __restrict__ B2h, const __nv_bfloat16* __restrict__ B2l,
    float* __restrict__ C1, float* __restrict__ C2, int M,
    const float* __restrict__ attn, float* __restrict__ ssrc, float* __restrict__ sdst)
{
    extern __shared__ char smraw[];
    uint32_t sb = (smem_u32(smraw) + 1023) & ~1023u;
    int tid = threadIdx.x, lane = tid & 31, wid = tid >> 5;
    int nt = blockIdx.x, mt = blockIdx.y;

    const __nv_bfloat16 *Bh, *Bl;
    float* C;
    int coloff;
    if (nt < 4) { Bh = B1h; Bl = B1l; C = C1; coloff = nt * 256; }
    else        { Bh = B2h; Bl = B2l; C = C2; coloff = (nt - 4) * 256; }

    int wm = wid & 1, wn = wid >> 1;   // 2 x 8 warp grid; warp tile 64x32

    float acc[4][4][4];
#pragma unroll
    for (int a = 0; a < 4; a++)
#pragma unroll
        for (int b = 0; b < 4; b++)
#pragma unroll
            for (int cc = 0; cc < 4; cc++) acc[a][b][cc] = 0.f;

    // raw (un-swizzled) ldmatrix base offsets for k16=0
    uint32_t rawA[4];   // [mi]
    uint32_t rawB[2];   // [pp]
#pragma unroll
    for (int mi = 0; mi < 4; mi++) {
        int row = wm * 64 + mi * 16 + (lane & 15);
        rawA[mi] = (uint32_t)(row * 128 + (lane >> 4) * 16);
    }
#pragma unroll
    for (int p = 0; p < 2; p++) {
        int row = wn * 32 + p * 16 + ((lane >> 4) << 3) + (lane & 7);
        rawB[p] = (uint32_t)(row * 128 + (((lane >> 3) & 1) << 4));
    }

    int q = tid & 7;
    int rr = tid >> 3;   // 0..63
    int chunks = Kp >> 6;

    auto load_stage = [&](int c) {
        uint32_t base = sb + (uint32_t)(c & 1) * STAGE_BYTES;
        uint32_t bAh = base, bAl = base + 16384, bBh = base + 32768, bBl = base + 65536;
        size_t kel = (size_t)c * 64 + q * 8;
#pragma unroll
        for (int i = 0; i < 2; i++) {
            int row = rr + i * 64;
            uint32_t soff = SWZ((uint32_t)(row * 128 + q * 16));
            int m = mt * 128 + row;
            if (m < M) {
                cpasync16(bAh + soff, Ah + (size_t)m * Kp + kel);
                cpasync16(bAl + soff, Al + (size_t)m * Kp + kel);
            } else {
                uint4 z = make_uint4(0, 0, 0, 0);
                sts128(bAh + soff, z);
                sts128(bAl + soff, z);
            }
        }
#pragma unroll
        for (int i = 0; i < 4; i++) {
            int row = rr + i * 64;
            uint32_t soff = SWZ((uint32_t)(row * 128 + q * 16));
            int nr = coloff + row;
            cpasync16(bBh + soff, Bh + (size_t)nr * Kp + kel);
            cpasync16(bBl + soff, Bl + (size_t)nr * Kp + kel);
        }
        CP_COMMIT();
    };

    load_stage(0);

    for (int c = 0; c < chunks; c++) {
        CP_WAIT0();
        __syncthreads();                 // stage c ready; buffer (c+1)&1 free
        if (c + 1 < chunks) load_stage(c + 1);

        uint32_t cur = sb + (uint32_t)(c & 1) * STAGE_BYTES;
        uint32_t cAh = cur, cAl = cur + 16384, cBh = cur + 32768, cBl = cur + 65536;
#pragma unroll 1
        for (int k16 = 0; k16 < 4; k16++) {
            uint32_t kb = (uint32_t)k16 * 32;
            uint32_t bh0[4], bh1[4], bl0[4], bl1[4];
#pragma unroll
            for (int pp = 0; pp < 2; pp++) {
                uint32_t addr = SWZ(rawB[pp] + kb);
                uint32_t r0_, r1_, r2_, r3_;
                LDSM4(r0_, r1_, r2_, r3_, cBh + addr);
                bh0[pp * 2] = r0_; bh1[pp * 2] = r1_;
                bh0[pp * 2 + 1] = r2_; bh1[pp * 2 + 1] = r3_;
                LDSM4(r0_, r1_, r2_, r3_, cBl + addr);
                bl0[pp * 2] = r0_; bl1[pp * 2] = r1_;
                bl0[pp * 2 + 1] = r2_; bl1[pp * 2 + 1] = r3_;
            }
#pragma unroll
            for (int mi = 0; mi < 4; mi++) {
                uint32_t addr = SWZ(rawA[mi] + kb);
                uint32_t a0, a1, a2, a3, l0, l1, l2, l3;
                LDSM4(a0, a1, a2, a3, cAh + addr);
                LDSM4(l0, l1, l2, l3, cAl + addr);
#pragma unroll
                for (int ni = 0; ni < 4; ni++) {
                    MMA_BF16(acc[mi][ni], a0, a1, a2, a3, bh0[ni], bh1[ni]);
                    MMA_BF16(acc[mi][ni], a0, a1, a2, a3, bl0[ni], bl1[ni]);
                    MMA_BF16(acc[mi][ni], l0, l1, l2, l3, bh0[ni], bh1[ni]);
                }
            }
        }
    }

    // epilogue: stores + fused s_src/s_dst dots for the hg half (nt>=4)
    int doAttn = (nt >= 4);
    int hh = nt - 4;
    const float* a0p = attn + (size_t)hh * 256;
    const float* a1p = attn + (size_t)(4 + hh) * 256;
#pragma unroll
    for (int mi = 0; mi < 4; mi++) {
        int gr = mt * 128 + wm * 64 + mi * 16 + (lane >> 2);
        float s0 = 0.f, d0 = 0.f, s1 = 0.f, d1 = 0.f;
#pragma unroll
        for (int ni = 0; ni < 4; ni++) {
            int cw = wn * 32 + ni * 8 + ((lane & 3) << 1);   // col within head
            int gc = coloff + cw;
            if (gr < M)
                *(float2*)(C + (size_t)gr * HIDD + gc) = make_float2(acc[mi][ni][0], acc[mi][ni][1]);
            if (gr + 8 < M)
                *(float2*)(C + (size_t)(gr + 8) * HIDD + gc) = make_float2(acc[mi][ni][2], acc[mi][ni][3]);
            if (doAttn) {
                float2 av = *(const float2*)(a0p + cw);
                float2 bv = *(const float2*)(a1p + cw);
                s0 += acc[mi][ni][0] * av.x + acc[mi][ni][1] * av.y;
                d0 += acc[mi][ni][0] * bv.x + acc[mi][ni][1] * bv.y;
                s1 += acc[mi][ni][2] * av.x + acc[mi][ni][3] * av.y;
                d1 += acc[mi][ni][2] * bv.x + acc[mi][ni][3] * bv.y;
            }
        }
        if (doAttn) {
#pragma unroll
            for (int o = 1; o < 4; o <<= 1) {
                s0 += __shfl_xor_sync(0xFFFFFFFFu, s0, o);
                d0 += __shfl_xor_sync(0xFFFFFFFFu, d0, o);
                s1 += __shfl_xor_sync(0xFFFFFFFFu, s1, o);
                d1 += __shfl_xor_sync(0xFFFFFFFFu, d1, o);
            }
            if ((lane & 3) == 0) {
                if (gr < M) {
                    atomicAdd(&ssrc[gr * 4 + hh], s0);
                    atomicAdd(&sdst[gr * 4 + hh], d0);
                }
                if (gr + 8 < M) {
                    atomicAdd(&ssrc[(gr + 8) * 4 + hh], s1);
                    atomicAdd(&sdst[(gr + 8) * 4 + hh], d1);
                }
            }
        }
    }
}

// ---------------- CSR build ----------------
__global__ void k_init(int* deg, int* cur) {
    int i = blockIdx.x * blockDim.x + threadIdx.x;
    if (i < NN) { deg[i] = 0; cur[i] = 0; }
}
__global__ void k_hist(const int* __restrict__ dst, int* __restrict__ deg) {
    int e = blockIdx.x * blockDim.x + threadIdx.x;
    if (e < EE) atomicAdd(&deg[dst[e]], 1);
}
__global__ void k_scan(const int* __restrict__ deg, int* __restrict__ off, int n) {
    __shared__ int sh[1024];
    __shared__ int carry;
    int t = threadIdx.x;
    if (t == 0) { carry = 0; off[0] = 0; }
    __syncthreads();
    for (int base = 0; base < n; base += 1024) {
        int v = (base + t < n) ? deg[base + t] : 0;
        sh[t] = v;
        __syncthreads();
        for (int d = 1; d < 1024; d <<= 1) {
            int add = (t >= d) ? sh[t - d] : 0;
            __syncthreads();
            sh[t] += add;
            __syncthreads();
        }
        if (base + t < n) off[base + t + 1] = carry + sh[t];
        __syncthreads();
        if (t == 0) carry += sh[1023];
        __syncthreads();
    }
}
__global__ void k_scatter(const int* __restrict__ dst, const int* __restrict__ off,
                          int* __restrict__ cur, int* __restrict__ eid) {
    int e = blockIdx.x * blockDim.x + threadIdx.x;
    if (e >= EE) return;
    int d = dst[e];
    int p = atomicAdd(&cur[d], 1);
    eid[off[d] + p] = e;
}

// ---------------- layer-3 tiny GEMM (BN inline, fp32) ----------------
__global__ __launch_bounds__(128) void k_gemm_small(
    const float* __restrict__ h, const float* __restrict__ scale,
    const float* __restrict__ shift,
    const float* __restrict__ lw, const float* __restrict__ wg,
    float* __restrict__ lin, float* __restrict__ hg)
{
    int n = blockIdx.x, t = threadIdx.x;
    const float* hr = h + (size_t)n * HIDD;
    float a0 = 0, a1 = 0, a2 = 0, a3 = 0;
    for (int k = t; k < HIDD; k += 128) {
        float a = hr[k] * scale[k] + shift[k];
        a0 += a * lw[k * 2];
        a1 += a * lw[k * 2 + 1];
        a2 += a * wg[k * 2];
        a3 += a * wg[k * 2 + 1];
    }
#pragma unroll
    for (int s = 16; s; s >>= 1) {
        a0 += __shfl_down_sync(0xFFFFFFFFu, a0, s);
        a1 += __shfl_down_sync(0xFFFFFFFFu, a1, s);
        a2 += __shfl_down_sync(0xFFFFFFFFu, a2, s);
        a3 += __shfl_down_sync(0xFFFFFFFFu, a3, s);
    }
    __shared__ float sm[4][4];
    if ((t & 31) == 0) {
        sm[t >> 5][0] = a0; sm[t >> 5][1] = a1; sm[t >> 5][2] = a2; sm[t >> 5][3] = a3;
    }
    __syncthreads();
    if (t == 0) {
        lin[(size_t)n * 2]     = sm[0][0] + sm[1][0] + sm[2][0] + sm[3][0];
        lin[(size_t)n * 2 + 1] = sm[0][1] + sm[1][1] + sm[2][1] + sm[3][1];
        hg [(size_t)n * 2]     = sm[0][2] + sm[1][2] + sm[2][2] + sm[3][2];
        hg [(size_t)n * 2 + 1] = sm[0][3] + sm[1][3] + sm[2][3] + sm[3][3];
    }
}

// ---------------- GAT pieces ----------------
__global__ void k_ve(const float* __restrict__ We, const float* __restrict__ attn,
                     float* __restrict__ ve, int H, int O) {
    int t = threadIdx.x;
    if (t >= H * EDK) return;
    int h = t / EDK, k = t % EDK;
    const float* a2 = attn + (size_t)(2 * H + h) * O;
    const float* w = We + (size_t)k * H * O + (size_t)h * O;
    float s = 0.f;
    for (int d = 0; d < O; d++) s += w[d] * a2[d];
    ve[k * H + h] = s;
}

__global__ void k_sdots(const float* __restrict__ hg, const float* __restrict__ attn,
                        float* __restrict__ ssrc, float* __restrict__ sdst, int H, int O) {
    int gw = (blockIdx.x * blockDim.x + threadIdx.x) >> 5;
    int lane = threadIdx.x & 31;
    if (gw >= NN * H) return;
    int n = gw / H, h = gw % H;
    const float* hr = hg + (size_t)n * H * O + (size_t)h * O;
    const float* a0 = attn + (size_t)h * O;
    const float* a1 = attn + (size_t)(H + h) * O;
    float d0 = 0.f, d1 = 0.f;
    for (int d = lane; d < O; d += 32) {
        float v = hr[d];
        d0 += v * a0[d];
        d1 += v * a1[d];
    }
#pragma unroll
    for (int s = 16; s; s >>= 1) {
        d0 += __shfl_down_sync(0xFFFFFFFFu, d0, s);
        d1 += __shfl_down_sync(0xFFFFFFFFu, d1, s);
    }
    if (lane == 0) { ssrc[gw] = d0; sdst[gw] = d1; }
}

__global__ void k_logits(const int* __restrict__ ei, const float* __restrict__ ea,
                         const float* __restrict__ ssrc, const float* __restrict__ sdst,
                         const float* __restrict__ ve, const float* __restrict__ at,
                         float* __restrict__ logw, int H) {
    int idx = blockIdx.x * blockDim.x + threadIdx.x;
    if (idx >= EE * H) return;
    int e = idx / H, h = idx % H;
    int s = ei[e], d = ei[EE + e];
    const float* row = ea + (size_t)e * EAC;
    float t = row[0];
    float se = 0.f;
#pragma unroll
    for (int k = 0; k < EDK; k++) se += row[1 + k] * ve[k * H + h];
    float l = ssrc[s * H + h] + sdst[d * H + h] + se + t * at[h];
    logw[idx] = (l > 0.f) ? l : 0.2f * l;
}

__global__ void k_softmax4(const int* __restrict__ off, const int* __restrict__ eid,
                           float4* __restrict__ w4) {
    int n = blockIdx.x * blockDim.x + threadIdx.x;
    if (n >= NN) return;
    int d0 = off[n], d1 = off[n + 1];
    if (d0 == d1) return;
    float4 m = make_float4(-INFINITY, -INFINITY, -INFINITY, -INFINITY);
    for (int i = d0; i < d1; i++) {
        float4 v = w4[eid[i]];
        m.x = fmaxf(m.x, v.x); m.y = fmaxf(m.y, v.y);
        m.z = fmaxf(m.z, v.z); m.w = fmaxf(m.w, v.w);
    }
    float4 s = make_float4(0.f, 0.f, 0.f, 0.f);
    for (int i = d0; i < d1; i++) {
        float4 v = w4[eid[i]];
        v.x = expf(v.x - m.x); v.y = expf(v.y - m.y);
        v.z = expf(v.z - m.z); v.w = expf(v.w - m.w);
        w4[eid[i]] = v;
        s.x += v.x; s.y += v.y; s.z += v.z; s.w += v.w;
    }
    float4 inv = make_float4(1.f / (s.x + 1e-16f), 1.f / (s.y + 1e-16f),
                             1.f / (s.z + 1e-16f), 1.f / (s.w + 1e-16f));
    for (int i = d0; i < d1; i++) {
        float4 v = w4[eid[i]];
        v.x *= inv.x; v.y *= inv.y; v.z *= inv.z; v.w *= inv.w;
        w4[eid[i]] = v;
    }
}

__global__ void k_softmax1(const int* __restrict__ off, const int* __restrict__ eid,
                           float* __restrict__ logw) {
    int n = blockIdx.x * blockDim.x + threadIdx.x;
    if (n >= NN) return;
    int d0 = off[n], d1 = off[n + 1];
    if (d0 == d1) return;
    float m = -INFINITY;
    for (int i = d0; i < d1; i++) m = fmaxf(m, logw[eid[i]]);
    float s = 0.f;
    for (int i = d0; i < d1; i++) {
        float p = expf(logw[eid[i]] - m);
        logw[eid[i]] = p;
        s += p;
    }
    float inv = 1.f / (s + 1e-16f);
    for (int i = d0; i < d1; i++) logw[eid[i]] *= inv;
}

__global__ __launch_bounds__(256) void k_agg_big(
    const float* __restrict__ hg, const float* __restrict__ w,
    const int* __restrict__ off, const int* __restrict__ eid,
    const float* __restrict__ ea, const int* __restrict__ src,
    const float* __restrict__ We, const float* __restrict__ lin,
    const float* __restrict__ lb, const float* __restrict__ cb,
    float* __restrict__ out)
{
    int n = blockIdx.x;
    int t = threadIdx.x;
    __shared__ float qs[40];
    if (t < 40) qs[t] = 0.f;
    float acc0 = 0.f, acc1 = 0.f, acc2 = 0.f, acc3 = 0.f;
    int d0 = off[n], d1 = off[n + 1];
    for (int i = d0; i < d1; i++) {
        int e = eid[i];
        int s = src[e];
        float4 wv = *(const float4*)(w + (size_t)e * 4);
        const float* hr = hg + (size_t)s * 1024;
        acc0 += wv.x * hr[t];
        acc1 += wv.y * hr[t + 256];
        acc2 += wv.z * hr[t + 512];
        acc3 += wv.w * hr[t + 768];
        if (t < 40) {
            int h = t / 10, k = t % 10;
            float wh = (h == 0) ? wv.x : (h == 1) ? wv.y : (h == 2) ? wv.z : wv.w;
            qs[t] += wh * ea[(size_t)e * EAC + 1 + k];
        }
    }
    __syncthreads();
    float acch[4] = {acc0, acc1, acc2, acc3};
#pragma unroll
    for (int h = 0; h < 4; h++) {
        int f = h * 256 + t;
        float et = 0.f;
#pragma unroll
        for (int k = 0; k < 10; k++) et += qs[h * 10 + k] * We[k * 1024 + f];
        float v = lin[(size_t)n * 1024 + f] + lb[f] + cb[f] + acch[h] + et;
        out[(size_t)n * 1024 + f] = fmaxf(v, 0.f);
    }
}

__global__ void k_agg_small(
    const float* __restrict__ hg, const float* __restrict__ w,
    const int* __restrict__ off, const int* __restrict__ eid,
    const float* __restrict__ ea, const int* __restrict__ src,
    const float* __restrict__ We, const float* __restrict__ lin,
    const float* __restrict__ lb, const float* __restrict__ cb,
    float* __restrict__ out)
{
    int n = blockIdx.x * blockDim.x + threadIdx.x;
    if (n >= NN) return;
    float a0 = 0.f, a1 = 0.f;
    float q[10];
#pragma unroll
    for (int k = 0; k < 10; k++) q[k] = 0.f;
    int d0 = off[n], d1 = off[n + 1];
    for (int i = d0; i < d1; i++) {
        int e = eid[i];
        int s = src[e];
        float wv = w[e];
        a0 += wv * hg[(size_t)s * 2];
        a1 += wv * hg[(size_t)s * 2 + 1];
        const float* row = ea + (size_t)e * EAC;
#pragma unroll
        for (int k = 0; k < 10; k++) q[k] += wv * row[1 + k];
    }
    float e0 = 0.f, e1 = 0.f;
#pragma unroll
    for (int k = 0; k < 10; k++) { e0 += q[k] * We[k * 2]; e1 += q[k] * We[k * 2 + 1]; }
    float v0 = lin[(size_t)n * 2] + lb[0] + cb[0] + a0 + e0;
    float v1 = lin[(size_t)n * 2 + 1] + lb[1] + cb[1] + a1 + e1;
    out[(size_t)n * 2] = fmaxf(v0, 0.f);
    out[(size_t)n * 2 + 1] = fmaxf(v1, 0.f);
}

// ---------------- host driver ----------------
static inline int cdiv(int a, int b) { return (a + b - 1) / b; }

struct Scratch {
    float *lin, *hg, *h, *logw, *ssrc, *sdst, *scale, *shift, *ve, *p1, *p2;
    int *deg, *off, *cur, *eid;
    __nv_bfloat16 *Ah, *Al, *B1h, *B1l, *B2h, *B2l;
};

extern "C" void kernel_launch(void* const* d_in, const int* in_sizes, int n_in,
                              void* d_out, int out_size)
{
    const float* x  = (const float*)d_in[0];
    const int*   ei = (const int*)d_in[1];
    const float* ea = (const float*)d_in[2];

    const float *Wg[3], *We[3], *attn[3], *at[3], *cb[3];
    const float *lw[3], *lb[3], *gg[3], *bb[3];

    if (in_sizes[8] == 1048576) {
        for (int i = 0; i < 3; i++) {
            Wg[i]   = (const float*)d_in[3 + 5 * i];
            We[i]   = (const float*)d_in[4 + 5 * i];
            attn[i] = (const float*)d_in[5 + 5 * i];
            at[i]   = (const float*)d_in[6 + 5 * i];
            cb[i]   = (const float*)d_in[7 + 5 * i];
            lw[i]   = (const float*)d_in[18 + 4 * i];
            lb[i]   = (const float*)d_in[19 + 4 * i];
            gg[i]   = (const float*)d_in[20 + 4 * i];
            bb[i]   = (const float*)d_in[21 + 4 * i];
        }
    } else {
        for (int i = 0; i < 3; i++) {
            Wg[i]   = (const float*)d_in[3 + 9 * i];
            We[i]   = (const float*)d_in[4 + 9 * i];
            attn[i] = (const float*)d_in[5 + 9 * i];
            at[i]   = (const float*)d_in[6 + 9 * i];
            cb[i]   = (const float*)d_in[7 + 9 * i];
            lw[i]   = (const float*)d_in[8 + 9 * i];
            lb[i]   = (const float*)d_in[9 + 9 * i];
            gg[i]   = (const float*)d_in[10 + 9 * i];
            bb[i]   = (const float*)d_in[11 + 9 * i];
        }
    }

    Scratch S;
    cudaGetSymbolAddress((void**)&S.lin, g_lin);
    cudaGetSymbolAddress((void**)&S.hg, g_hg);
    cudaGetSymbolAddress((void**)&S.h, g_h);
    cudaGetSymbolAddress((void**)&S.logw, g_logw);
    cudaGetSymbolAddress((void**)&S.ssrc, g_ssrc);
    cudaGetSymbolAddress((void**)&S.sdst, g_sdst);
    cudaGetSymbolAddress((void**)&S.p1, g_part1);
    cudaGetSymbolAddress((void**)&S.p2, g_part2);
    cudaGetSymbolAddress((void**)&S.scale, g_scale);
    cudaGetSymbolAddress((void**)&S.shift, g_shift);
    cudaGetSymbolAddress((void**)&S.ve, g_ve);
    cudaGetSymbolAddress((void**)&S.deg, g_deg);
    cudaGetSymbolAddress((void**)&S.off, g_off);
    cudaGetSymbolAddress((void**)&S.cur, g_cur);
    cudaGetSymbolAddress((void**)&S.eid, g_eid);
    cudaGetSymbolAddress((void**)&S.Ah, g_Ah);
    cudaGetSymbolAddress((void**)&S.Al, g_Al);
    cudaGetSymbolAddress((void**)&S.B1h, g_B1h);
    cudaGetSymbolAddress((void**)&S.B1l, g_B1l);
    cudaGetSymbolAddress((void**)&S.B2h, g_B2h);
    cudaGetSymbolAddress((void**)&S.B2l, g_B2l);

    cudaFuncSetAttribute(gemm_mma, cudaFuncAttributeMaxDynamicSharedMemorySize, GT_SMEM);

    // ======== layer 1 (GEMM is the 4th launch -> profiled) ========
    {
        int F = F1, Kp = 192;
        k_bnstat<<<dim3(cdiv(F, 256), BNCH), 256>>>(x, S.p1, S.p2, F);
        k_bnfin<<<cdiv(F, 256), 256>>>(S.p1, S.p2, gg[0], bb[0], S.scale, S.shift, F);
        size_t tp = (size_t)NN * Kp + 2 * (size_t)HIDD * Kp + (size_t)NN * 8;
        k_prep<<<(int)((tp + 255) / 256), 256>>>(x, S.scale, S.shift, S.Ah, S.Al,
                                                 lw[0], Wg[0], S.B1h, S.B1l, S.B2h, S.B2l,
                                                 S.ssrc, S.sdst, F, Kp);
        gemm_mma<<<dim3(8, cdiv(NN, 128)), 512, GT_SMEM>>>(
            S.Ah, S.Al, Kp, S.B1h, S.B1l, S.B2h, S.B2l, S.lin, S.hg, NN,
            attn[0], S.ssrc, S.sdst);
        // CSR build (needed from softmax on)
        k_init<<<cdiv(NN, 256), 256>>>(S.deg, S.cur);
        k_hist<<<cdiv(EE, 256), 256>>>(ei + EE, S.deg);
        k_scan<<<1, 1024>>>(S.deg, S.off, NN);
        k_scatter<<<cdiv(EE, 256), 256>>>(ei + EE, S.off, S.cur, S.eid);
        k_ve<<<1, 64>>>(We[0], attn[0], S.ve, 4, 256);
        k_logits<<<cdiv(EE * 4, 256), 256>>>(ei, ea, S.ssrc, S.sdst, S.ve, at[0], S.logw, 4);
        k_softmax4<<<cdiv(NN, 256), 256>>>(S.off, S.eid, (float4*)S.logw);
        k_agg_big<<<NN, 256>>>(S.hg, S.logw, S.off, S.eid, ea, ei, We[0], S.lin, lb[0], cb[0], S.h);
    }
    // ======== layer 2 ========
    {
        int F = HIDD, Kp = HIDD;
        k_bnstat<<<dim3(cdiv(F, 256), BNCH), 256>>>(S.h, S.p1, S.p2, F);
        k_bnfin<<<cdiv(F, 256), 256>>>(S.p1, S.p2, gg[1], bb[1], S.scale, S.shift, F);
        size_t tp = (size_t)NN * Kp + 2 * (size_t)HIDD * Kp + (size_t)NN * 8;
        k_prep<<<(int)((tp + 255) / 256), 256>>>(S.h, S.scale, S.shift, S.Ah, S.Al,
                                                 lw[1], Wg[1], S.B1h, S.B1l, S.B2h, S.B2l,
                                                 S.ssrc, S.sdst, F, Kp);
        gemm_mma<<<dim3(8, cdiv(NN, 128)), 512, GT_SMEM>>>(
            S.Ah, S.Al, Kp, S.B1h, S.B1l, S.B2h, S.B2l, S.lin, S.hg, NN,
            attn[1], S.ssrc, S.sdst);
        k_ve<<<1, 64>>>(We[1], attn[1], S.ve, 4, 256);
        k_logits<<<cdiv(EE * 4, 256), 256>>>(ei, ea, S.ssrc, S.sdst, S.ve, at[1], S.logw, 4);
        k_softmax4<<<cdiv(NN, 256), 256>>>(S.off, S.eid, (float4*)S.logw);
        k_agg_big<<<NN, 256>>>(S.hg, S.logw, S.off, S.eid, ea, ei, We[1], S.lin, lb[1], cb[1], S.h);
    }
    // ======== layer 3 ========
    {
        k_bnstat<<<dim3(cdiv(HIDD, 256), BNCH), 256>>>(S.h, S.p1, S.p2, HIDD);
        k_bnfin<<<cdiv(HIDD, 256), 256>>>(S.p1, S.p2, gg[2], bb[2], S.scale, S.shift, HIDD);
        k_gemm_small<<<NN, 128>>>(S.h, S.scale, S.shift, lw[2], Wg[2], S.lin, S.hg);
        k_ve<<<1, 64>>>(We[2], attn[2], S.ve, 1, 2);
        k_sdots<<<cdiv(NN * 1 * 32, 256), 256>>>(S.hg, attn[2], S.ssrc, S.sdst, 1, 2);
        k_logits<<<cdiv(EE * 1, 256), 256>>>(ei, ea, S.ssrc, S.sdst, S.ve, at[2], S.logw, 1);
        k_softmax1<<<cdiv(NN, 256), 256>>>(S.off, S.eid, S.logw);
        k_agg_small<<<cdiv(NN, 256), 256>>>(S.hg, S.logw, S.off, S.eid, ea, ei, We[2], S.lin, lb[2], cb[2], (float*)d_out);
    }
}

// round 11
// speedup vs baseline: 1.0351x; 1.0351x over previous
#include <cuda_runtime.h>
#include <cuda_bf16.h>
#include <cstdint>
#include <math.h>

#define NN   20000
#define EE   100000
#define F1   167
#define HIDD 1024
#define EDK  10
#define EAC  12
#define BNCH 40

// ---------------- scratch (device globals) ----------------
__device__ float g_lin[(size_t)NN * HIDD];
__device__ float g_hg [(size_t)NN * HIDD];
__device__ float g_h  [(size_t)NN * HIDD];
__device__ float g_logw[(size_t)EE * 4];
__device__ float g_ssrc[(size_t)NN * 4];
__device__ float g_sdst[(size_t)NN * 4];
__device__ float g_part1[BNCH * HIDD];
__device__ float g_part2[BNCH * HIDD];
__device__ float g_scale[HIDD];
__device__ float g_shift[HIDD];
__device__ float g_ve[EDK * 4];
__device__ int   g_deg[NN];
__device__ int   g_off[NN + 1];
__device__ int   g_cur[NN];
__device__ int   g_eid[EE];
__device__ __nv_bfloat16 g_Ah[(size_t)NN * HIDD];
__device__ __nv_bfloat16 g_Al[(size_t)NN * HIDD];
__device__ __nv_bfloat16 g_B1h[(size_t)HIDD * HIDD];
__device__ __nv_bfloat16 g_B1l[(size_t)HIDD * HIDD];
__device__ __nv_bfloat16 g_B2h[(size_t)HIDD * HIDD];
__device__ __nv_bfloat16 g_B2l[(size_t)HIDD * HIDD];

// ---------------- BatchNorm: partials ----------------
__global__ void k_bnstat(const float* __restrict__ x, float* __restrict__ p1,
                         float* __restrict__ p2, int F) {
    int c = blockIdx.x * blockDim.x + threadIdx.x;
    if (c >= F) return;
    int chunk = (NN + BNCH - 1) / BNCH;
    int r0 = blockIdx.y * chunk;
    int r1 = r0 + chunk; if (r1 > NN) r1 = NN;
    float a = 0.f, b = 0.f;
    for (int r = r0; r < r1; r++) {
        float v = x[(size_t)r * F + c];
        a += v; b += v * v;
    }
    p1[blockIdx.y * F + c] = a;
    p2[blockIdx.y * F + c] = b;
}

__global__ void k_bnfin(const float* __restrict__ p1, const float* __restrict__ p2,
                        const float* __restrict__ g, const float* __restrict__ b,
                        float* __restrict__ scale, float* __restrict__ shift, int F) {
    int c = blockIdx.x * blockDim.x + threadIdx.x;
    if (c >= F) return;
    float a = 0.f, s = 0.f;
    for (int y = 0; y < BNCH; y++) { a += p1[y * F + c]; s += p2[y * F + c]; }
    float invN = 1.f / (float)NN;
    float mu = a * invN;
    float var = s * invN - mu * mu;
    float rstd = rsqrtf(var + 1e-5f);
    float sc = rstd * g[c];
    scale[c] = sc;
    shift[c] = b[c] - mu * sc;
}

// ---------------- fused prep: A-split + both B-splits + zero ssrc/sdst ----------------
__global__ void k_prep(const float* __restrict__ x, const float* __restrict__ scale,
                       const float* __restrict__ shift,
                       __nv_bfloat16* __restrict__ Ah, __nv_bfloat16* __restrict__ Al,
                       const float* __restrict__ W1, const float* __restrict__ W2,
                       __nv_bfloat16* __restrict__ B1h, __nv_bfloat16* __restrict__ B1l,
                       __nv_bfloat16* __restrict__ B2h, __nv_bfloat16* __restrict__ B2l,
                       float* __restrict__ ssrc, float* __restrict__ sdst,
                       int F, int Kp) {
    size_t na = (size_t)NN * Kp;
    size_t nb = (size_t)HIDD * Kp;
    size_t i = (size_t)blockIdx.x * blockDim.x + threadIdx.x;
    if (i < na) {
        int m = (int)(i / Kp), k = (int)(i % Kp);
        float v = 0.f;
        if (k < F) v = x[(size_t)m * F + k] * scale[k] + shift[k];
        __nv_bfloat16 h = __float2bfloat16(v);
        Ah[i] = h;
        Al[i] = __float2bfloat16(v - __bfloat162float(h));
    } else if (i < na + 2 * nb) {
        size_t j = i - na;
        const float* W = (j < nb) ? W1 : W2;
        __nv_bfloat16* Bh = (j < nb) ? B1h : B2h;
        __nv_bfloat16* Bl = (j < nb) ? B1l : B2l;
        if (j >= nb) j -= nb;
        int n = (int)(j / Kp), k = (int)(j % Kp);
        float v = (k < F) ? W[(size_t)k * HIDD + n] : 0.f;
        __nv_bfloat16 h = __float2bfloat16(v);
        Bh[j] = h;
        Bl[j] = __float2bfloat16(v - __bfloat162float(h));
    } else if (i < na + 2 * nb + (size_t)NN * 4) {
        ssrc[i - na - 2 * nb] = 0.f;
    } else if (i < na + 2 * nb + (size_t)NN * 8) {
        sdst[i - na - 2 * nb - (size_t)NN * 4] = 0.f;
    }
}

// ---------------- mma.sync helpers ----------------
__device__ __forceinline__ uint32_t smem_u32(const void* p) {
    uint32_t a;
    asm("{ .reg .u64 t; cvta.to.shared.u64 t, %1; cvt.u32.u64 %0, t; }" : "=r"(a) : "l"(p));
    return a;
}
__device__ __forceinline__ void sts128(uint32_t addr, uint4 v) {
    asm volatile("st.shared.v4.b32 [%0], {%1,%2,%3,%4};"
                 :: "r"(addr), "r"(v.x), "r"(v.y), "r"(v.z), "r"(v.w) : "memory");
}
__device__ __forceinline__ void cpasync16(uint32_t s, const void* g) {
    asm volatile("cp.async.cg.shared.global [%0], [%1], 16;" :: "r"(s), "l"(g));
}
#define CP_COMMIT() asm volatile("cp.async.commit_group;" ::: "memory")
#define CP_WAIT0()  asm volatile("cp.async.wait_group 0;" ::: "memory")
// SW64 swizzle for 64-byte rows (8 rows -> distinct bank groups for ldmatrix)
#define SWZ64(x) ((x) ^ (((x) >> 3) & 0x30))

#define LDSM4(r0, r1, r2, r3, addr) \
    asm volatile("ldmatrix.sync.aligned.m8n8.x4.shared.b16 {%0,%1,%2,%3}, [%4];" \
                 : "=r"(r0), "=r"(r1), "=r"(r2), "=r"(r3) : "r"(addr))

#define MMA_BF16(d, a0, a1, a2, a3, b0, b1) \
    asm volatile("mma.sync.aligned.m16n8k16.row.col.f32.bf16.bf16.f32 " \
                 "{%0,%1,%2,%3}, {%4,%5,%6,%7}, {%8,%9}, {%0,%1,%2,%3};" \
                 : "+f"((d)[0]), "+f"((d)[1]), "+f"((d)[2]), "+f"((d)[3]) \
                 : "r"(a0), "r"(a1), "r"(a2), "r"(a3), "r"(b0), "r"(b1))

// ---------------- split-bf16 GEMM: 128x128 tile, 256 thr, K-chunk 32, 2 CTA/SM ----
// grid.x = 16 n-tiles: 0-7 -> (B1 -> C1), 8-15 -> (B2 -> C2, + fused attn dots).
#define STAGE_BYTES 32768   // Ah 8K | Al 8K | Bh 8K | Bl 8K  (64B rows, SW64)
#define GT_SMEM (2 * STAGE_BYTES + 512)

__global__ __launch_bounds__(256, 2) void gemm_mma(
    const __nv_bfloat16* __restrict__ Ah, const __nv_bfloat16* __restrict__ Al, int Kp,
    const __nv_bfloat16* __restrict__ B1h, const __nv_bfloat16* __restrict__ B1l,
    const __nv_bfloat16* __restrict__ B2h, const __nv_bfloat16* __restrict__ B2l,
    float* __restrict__ C1, float* __restrict__ C2, int M,
    const float* __restrict__ attn, float* __restrict__ ssrc, float* __restrict__ sdst)
{
    extern __shared__ char smraw[];
    uint32_t sb = (smem_u32(smraw) + 255) & ~255u;
    int tid = threadIdx.x, lane = tid & 31, wid = tid >> 5;
    int nt = blockIdx.x, mt = blockIdx.y;

    const __nv_bfloat16 *Bh, *Bl;
    float* C;
    int coloff;
    if (nt < 8) { Bh = B1h; Bl = B1l; C = C1; coloff = nt * 128; }
    else        { Bh = B2h; Bl = B2l; C = C2; coloff = (nt - 8) * 128; }

    int wm = wid & 1, wn = wid >> 1;   // 2 x 4 warp grid; warp tile 64x32

    float acc[4][4][4];
#pragma unroll
    for (int a = 0; a < 4; a++)
#pragma unroll
        for (int b = 0; b < 4; b++)
#pragma unroll
            for (int cc = 0; cc < 4; cc++) acc[a][b][cc] = 0.f;

    // raw (un-swizzled) ldmatrix base offsets within an 8KB (128 x 64B) region
    uint32_t rawA[4];   // [mi]
    uint32_t rawB[2];   // [pp]
#pragma unroll
    for (int mi = 0; mi < 4; mi++) {
        int row = wm * 64 + mi * 16 + (lane & 15);
        rawA[mi] = (uint32_t)(row * 64 + (lane >> 4) * 16);
    }
#pragma unroll
    for (int p = 0; p < 2; p++) {
        int row = wn * 32 + p * 16 + ((lane >> 4) << 3) + (lane & 7);
        rawB[p] = (uint32_t)(row * 64 + (((lane >> 3) & 1) << 4));
    }

    int q = tid & 3;          // 16B segment within 64B row
    int rr = tid >> 2;        // 0..63 -> rows rr, rr+64
    int chunks = Kp >> 5;     // K-chunk = 32

    auto load_stage = [&](int c) {
        uint32_t base = sb + (uint32_t)(c & 1) * STAGE_BYTES;
        uint32_t bAh = base, bAl = base + 8192, bBh = base + 16384, bBl = base + 24576;
        size_t kel = (size_t)c * 32 + q * 8;
#pragma unroll
        for (int i = 0; i < 2; i++) {
            int row = rr + i * 64;
            uint32_t soff = SWZ64((uint32_t)(row * 64 + q * 16));
            int m = mt * 128 + row;
            if (m < M) {
                cpasync16(bAh + soff, Ah + (size_t)m * Kp + kel);
                cpasync16(bAl + soff, Al + (size_t)m * Kp + kel);
            } else {
                uint4 z = make_uint4(0, 0, 0, 0);
                sts128(bAh + soff, z);
                sts128(bAl + soff, z);
            }
            int nr = coloff + row;
            cpasync16(bBh + soff, Bh + (size_t)nr * Kp + kel);
            cpasync16(bBl + soff, Bl + (size_t)nr * Kp + kel);
        }
        CP_COMMIT();
    };

    load_stage(0);

    for (int c = 0; c < chunks; c++) {
        CP_WAIT0();
        __syncthreads();                 // stage c ready; buffer (c+1)&1 free
        if (c + 1 < chunks) load_stage(c + 1);

        uint32_t cur = sb + (uint32_t)(c & 1) * STAGE_BYTES;
        uint32_t cAh = cur, cAl = cur + 8192, cBh = cur + 16384, cBl = cur + 24576;
#pragma unroll 1
        for (int k16 = 0; k16 < 2; k16++) {
            uint32_t kb = (uint32_t)k16 * 32;
            uint32_t bh0[4], bh1[4], bl0[4], bl1[4];
#pragma unroll
            for (int pp = 0; pp < 2; pp++) {
                uint32_t addr = SWZ64(rawB[pp] + kb);
                uint32_t r0_, r1_, r2_, r3_;
                LDSM4(r0_, r1_, r2_, r3_, cBh + addr);
                bh0[pp * 2] = r0_; bh1[pp * 2] = r1_;
                bh0[pp * 2 + 1] = r2_; bh1[pp * 2 + 1] = r3_;
                LDSM4(r0_, r1_, r2_, r3_, cBl + addr);
                bl0[pp * 2] = r0_; bl1[pp * 2] = r1_;
                bl0[pp * 2 + 1] = r2_; bl1[pp * 2 + 1] = r3_;
            }
#pragma unroll
            for (int mi = 0; mi < 4; mi++) {
                uint32_t addr = SWZ64(rawA[mi] + kb);
                uint32_t a0, a1, a2, a3, l0, l1, l2, l3;
                LDSM4(a0, a1, a2, a3, cAh + addr);
                LDSM4(l0, l1, l2, l3, cAl + addr);
#pragma unroll
                for (int ni = 0; ni < 4; ni++) {
                    MMA_BF16(acc[mi][ni], a0, a1, a2, a3, bh0[ni], bh1[ni]);
                    MMA_BF16(acc[mi][ni], a0, a1, a2, a3, bl0[ni], bl1[ni]);
                    MMA_BF16(acc[mi][ni], l0, l1, l2, l3, bh0[ni], bh1[ni]);
                }
            }
        }
    }

    // epilogue: stores + fused s_src/s_dst dots for the hg half (nt>=8)
    int doAttn = (nt >= 8);
    int hh = (coloff >> 8) & 3;                 // head index (256 cols per head)
    int hcbase = coloff & 255;                  // column base within head
    const float* a0p = attn + (size_t)hh * 256;
    const float* a1p = attn + (size_t)(4 + hh) * 256;
#pragma unroll
    for (int mi = 0; mi < 4; mi++) {
        int gr = mt * 128 + wm * 64 + mi * 16 + (lane >> 2);
        float s0 = 0.f, d0 = 0.f, s1 = 0.f, d1 = 0.f;
#pragma unroll
        for (int ni = 0; ni < 4; ni++) {
            int cl = wn * 32 + ni * 8 + ((lane & 3) << 1);    // col within 128-tile
            int gc = coloff + cl;
            if (gr < M)
                *(float2*)(C + (size_t)gr * HIDD + gc) = make_float2(acc[mi][ni][0], acc[mi][ni][1]);
            if (gr + 8 < M)
                *(float2*)(C + (size_t)(gr + 8) * HIDD + gc) = make_float2(acc[mi][ni][2], acc[mi][ni][3]);
            if (doAttn) {
                int cw = hcbase + cl;
                float2 av = *(const float2*)(a0p + cw);
                float2 bv = *(const float2*)(a1p + cw);
                s0 += acc[mi][ni][0] * av.x + acc[mi][ni][1] * av.y;
                d0 += acc[mi][ni][0] * bv.x + acc[mi][ni][1] * bv.y;
                s1 += acc[mi][ni][2] * av.x + acc[mi][ni][3] * av.y;
                d1 += acc[mi][ni][2] * bv.x + acc[mi][ni][3] * bv.y;
            }
        }
        if (doAttn) {
#pragma unroll
            for (int o = 1; o < 4; o <<= 1) {
                s0 += __shfl_xor_sync(0xFFFFFFFFu, s0, o);
                d0 += __shfl_xor_sync(0xFFFFFFFFu, d0, o);
                s1 += __shfl_xor_sync(0xFFFFFFFFu, s1, o);
                d1 += __shfl_xor_sync(0xFFFFFFFFu, d1, o);
            }
            if ((lane & 3) == 0) {
                if (gr < M) {
                    atomicAdd(&ssrc[gr * 4 + hh], s0);
                    atomicAdd(&sdst[gr * 4 + hh], d0);
                }
                if (gr + 8 < M) {
                    atomicAdd(&ssrc[(gr + 8) * 4 + hh], s1);
                    atomicAdd(&sdst[(gr + 8) * 4 + hh], d1);
                }
            }
        }
    }
}

// ---------------- CSR build ----------------
__global__ void k_init(int* deg, int* cur) {
    int i = blockIdx.x * blockDim.x + threadIdx.x;
    if (i < NN) { deg[i] = 0; cur[i] = 0; }
}
__global__ void k_hist(const int* __restrict__ dst, int* __restrict__ deg) {
    int e = blockIdx.x * blockDim.x + threadIdx.x;
    if (e < EE) atomicAdd(&deg[dst[e]], 1);
}
__global__ void k_scan(const int* __restrict__ deg, int* __restrict__ off, int n) {
    __shared__ int sh[1024];
    __shared__ int carry;
    int t = threadIdx.x;
    if (t == 0) { carry = 0; off[0] = 0; }
    __syncthreads();
    for (int base = 0; base < n; base += 1024) {
        int v = (base + t < n) ? deg[base + t] : 0;
        sh[t] = v;
        __syncthreads();
        for (int d = 1; d < 1024; d <<= 1) {
            int add = (t >= d) ? sh[t - d] : 0;
            __syncthreads();
            sh[t] += add;
            __syncthreads();
        }
        if (base + t < n) off[base + t + 1] = carry + sh[t];
        __syncthreads();
        if (t == 0) carry += sh[1023];
        __syncthreads();
    }
}
__global__ void k_scatter(const int* __restrict__ dst, const int* __restrict__ off,
                          int* __restrict__ cur, int* __restrict__ eid) {
    int e = blockIdx.x * blockDim.x + threadIdx.x;
    if (e >= EE) return;
    int d = dst[e];
    int p = atomicAdd(&cur[d], 1);
    eid[off[d] + p] = e;
}

// ---------------- layer-3 tiny GEMM (BN inline, fp32) ----------------
__global__ __launch_bounds__(128) void k_gemm_small(
    const float* __restrict__ h, const float* __restrict__ scale,
    const float* __restrict__ shift,
    const float* __restrict__ lw, const float* __restrict__ wg,
    float* __restrict__ lin, float* __restrict__ hg)
{
    int n = blockIdx.x, t = threadIdx.x;
    const float* hr = h + (size_t)n * HIDD;
    float a0 = 0, a1 = 0, a2 = 0, a3 = 0;
    for (int k = t; k < HIDD; k += 128) {
        float a = hr[k] * scale[k] + shift[k];
        a0 += a * lw[k * 2];
        a1 += a * lw[k * 2 + 1];
        a2 += a * wg[k * 2];
        a3 += a * wg[k * 2 + 1];
    }
#pragma unroll
    for (int s = 16; s; s >>= 1) {
        a0 += __shfl_down_sync(0xFFFFFFFFu, a0, s);
        a1 += __shfl_down_sync(0xFFFFFFFFu, a1, s);
        a2 += __shfl_down_sync(0xFFFFFFFFu, a2, s);
        a3 += __shfl_down_sync(0xFFFFFFFFu, a3, s);
    }
    __shared__ float sm[4][4];
    if ((t & 31) == 0) {
        sm[t >> 5][0] = a0; sm[t >> 5][1] = a1; sm[t >> 5][2] = a2; sm[t >> 5][3] = a3;
    }
    __syncthreads();
    if (t == 0) {
        lin[(size_t)n * 2]     = sm[0][0] + sm[1][0] + sm[2][0] + sm[3][0];
        lin[(size_t)n * 2 + 1] = sm[0][1] + sm[1][1] + sm[2][1] + sm[3][1];
        hg [(size_t)n * 2]     = sm[0][2] + sm[1][2] + sm[2][2] + sm[3][2];
        hg [(size_t)n * 2 + 1] = sm[0][3] + sm[1][3] + sm[2][3] + sm[3][3];
    }
}

// ---------------- GAT pieces ----------------
__global__ void k_ve(const float* __restrict__ We, const float* __restrict__ attn,
                     float* __restrict__ ve, int H, int O) {
    int t = threadIdx.x;
    if (t >= H * EDK) return;
    int h = t / EDK, k = t % EDK;
    const float* a2 = attn + (size_t)(2 * H + h) * O;
    const float* w = We + (size_t)k * H * O + (size_t)h * O;
    float s = 0.f;
    for (int d = 0; d < O; d++) s += w[d] * a2[d];
    ve[k * H + h] = s;
}

__global__ void k_sdots(const float* __restrict__ hg, const float* __restrict__ attn,
                        float* __restrict__ ssrc, float* __restrict__ sdst, int H, int O) {
    int gw = (blockIdx.x * blockDim.x + threadIdx.x) >> 5;
    int lane = threadIdx.x & 31;
    if (gw >= NN * H) return;
    int n = gw / H, h = gw % H;
    const float* hr = hg + (size_t)n * H * O + (size_t)h * O;
    const float* a0 = attn + (size_t)h * O;
    const float* a1 = attn + (size_t)(H + h) * O;
    float d0 = 0.f, d1 = 0.f;
    for (int d = lane; d < O; d += 32) {
        float v = hr[d];
        d0 += v * a0[d];
        d1 += v * a1[d];
    }
#pragma unroll
    for (int s = 16; s; s >>= 1) {
        d0 += __shfl_down_sync(0xFFFFFFFFu, d0, s);
        d1 += __shfl_down_sync(0xFFFFFFFFu, d1, s);
    }
    if (lane == 0) { ssrc[gw] = d0; sdst[gw] = d1; }
}

__global__ void k_logits(const int* __restrict__ ei, const float* __restrict__ ea,
                         const float* __restrict__ ssrc, const float* __restrict__ sdst,
                         const float* __restrict__ ve, const float* __restrict__ at,
                         float* __restrict__ logw, int H) {
    int idx = blockIdx.x * blockDim.x + threadIdx.x;
    if (idx >= EE * H) return;
    int e = idx / H, h = idx % H;
    int s = ei[e], d = ei[EE + e];
    const float* row = ea + (size_t)e * EAC;
    float t = row[0];
    float se = 0.f;
#pragma unroll
    for (int k = 0; k < EDK; k++) se += row[1 + k] * ve[k * H + h];
    float l = ssrc[s * H + h] + sdst[d * H + h] + se + t * at[h];
    logw[idx] = (l > 0.f) ? l : 0.2f * l;
}

__global__ void k_softmax4(const int* __restrict__ off, const int* __restrict__ eid,
                           float4* __restrict__ w4) {
    int n = blockIdx.x * blockDim.x + threadIdx.x;
    if (n >= NN) return;
    int d0 = off[n], d1 = off[n + 1];
    if (d0 == d1) return;
    float4 m = make_float4(-INFINITY, -INFINITY, -INFINITY, -INFINITY);
    for (int i = d0; i < d1; i++) {
        float4 v = w4[eid[i]];
        m.x = fmaxf(m.x, v.x); m.y = fmaxf(m.y, v.y);
        m.z = fmaxf(m.z, v.z); m.w = fmaxf(m.w, v.w);
    }
    float4 s = make_float4(0.f, 0.f, 0.f, 0.f);
    for (int i = d0; i < d1; i++) {
        float4 v = w4[eid[i]];
        v.x = expf(v.x - m.x); v.y = expf(v.y - m.y);
        v.z = expf(v.z - m.z); v.w = expf(v.w - m.w);
        w4[eid[i]] = v;
        s.x += v.x; s.y += v.y; s.z += v.z; s.w += v.w;
    }
    float4 inv = make_float4(1.f / (s.x + 1e-16f), 1.f / (s.y + 1e-16f),
                             1.f / (s.z + 1e-16f), 1.f / (s.w + 1e-16f));
    for (int i = d0; i < d1; i++) {
        float4 v = w4[eid[i]];
        v.x *= inv.x; v.y *= inv.y; v.z *= inv.z; v.w *= inv.w;
        w4[eid[i]] = v;
    }
}

__global__ void k_softmax1(const int* __restrict__ off, const int* __restrict__ eid,
                           float* __restrict__ logw) {
    int n = blockIdx.x * blockDim.x + threadIdx.x;
    if (n >= NN) return;
    int d0 = off[n], d1 = off[n + 1];
    if (d0 == d1) return;
    float m = -INFINITY;
    for (int i = d0; i < d1; i++) m = fmaxf(m, logw[eid[i]]);
    float s = 0.f;
    for (int i = d0; i < d1; i++) {
        float p = expf(logw[eid[i]] - m);
        logw[eid[i]] = p;
        s += p;
    }
    float inv = 1.f / (s + 1e-16f);
    for (int i = d0; i < d1; i++) logw[eid[i]] *= inv;
}

__global__ __launch_bounds__(256) void k_agg_big(
    const float* __restrict__ hg, const float* __restrict__ w,
    const int* __restrict__ off, const int* __restrict__ eid,
    const float* __restrict__ ea, const int* __restrict__ src,
    const float* __restrict__ We, const float* __restrict__ lin,
    const float* __restrict__ lb, const float* __restrict__ cb,
    float* __restrict__ out)
{
    int n = blockIdx.x;
    int t = threadIdx.x;
    __shared__ float qs[40];
    if (t < 40) qs[t] = 0.f;
    float acc0 = 0.f, acc1 = 0.f, acc2 = 0.f, acc3 = 0.f;
    int d0 = off[n], d1 = off[n + 1];
    for (int i = d0; i < d1; i++) {
        int e = eid[i];
        int s = src[e];
        float4 wv = *(const float4*)(w + (size_t)e * 4);
        const float* hr = hg + (size_t)s * 1024;
        acc0 += wv.x * hr[t];
        acc1 += wv.y * hr[t + 256];
        acc2 += wv.z * hr[t + 512];
        acc3 += wv.w * hr[t + 768];
        if (t < 40) {
            int h = t / 10, k = t % 10;
            float wh = (h == 0) ? wv.x : (h == 1) ? wv.y : (h == 2) ? wv.z : wv.w;
            qs[t] += wh * ea[(size_t)e * EAC + 1 + k];
        }
    }
    __syncthreads();
    float acch[4] = {acc0, acc1, acc2, acc3};
#pragma unroll
    for (int h = 0; h < 4; h++) {
        int f = h * 256 + t;
        float et = 0.f;
#pragma unroll
        for (int k = 0; k < 10; k++) et += qs[h * 10 + k] * We[k * 1024 + f];
        float v = lin[(size_t)n * 1024 + f] + lb[f] + cb[f] + acch[h] + et;
        out[(size_t)n * 1024 + f] = fmaxf(v, 0.f);
    }
}

__global__ void k_agg_small(
    const float* __restrict__ hg, const float* __restrict__ w,
    const int* __restrict__ off, const int* __restrict__ eid,
    const float* __restrict__ ea, const int* __restrict__ src,
    const float* __restrict__ We, const float* __restrict__ lin,
    const float* __restrict__ lb, const float* __restrict__ cb,
    float* __restrict__ out)
{
    int n = blockIdx.x * blockDim.x + threadIdx.x;
    if (n >= NN) return;
    float a0 = 0.f, a1 = 0.f;
    float q[10];
#pragma unroll
    for (int k = 0; k < 10; k++) q[k] = 0.f;
    int d0 = off[n], d1 = off[n + 1];
    for (int i = d0; i < d1; i++) {
        int e = eid[i];
        int s = src[e];
        float wv = w[e];
        a0 += wv * hg[(size_t)s * 2];
        a1 += wv * hg[(size_t)s * 2 + 1];
        const float* row = ea + (size_t)e * EAC;
#pragma unroll
        for (int k = 0; k < 10; k++) q[k] += wv * row[1 + k];
    }
    float e0 = 0.f, e1 = 0.f;
#pragma unroll
    for (int k = 0; k < 10; k++) { e0 += q[k] * We[k * 2]; e1 += q[k] * We[k * 2 + 1]; }
    float v0 = lin[(size_t)n * 2] + lb[0] + cb[0] + a0 + e0;
    float v1 = lin[(size_t)n * 2 + 1] + lb[1] + cb[1] + a1 + e1;
    out[(size_t)n * 2] = fmaxf(v0, 0.f);
    out[(size_t)n * 2 + 1] = fmaxf(v1, 0.f);
}

// ---------------- host driver ----------------
static inline int cdiv(int a, int b) { return (a + b - 1) / b; }

struct Scratch {
    float *lin, *hg, *h, *logw, *ssrc, *sdst, *scale, *shift, *ve, *p1, *p2;
    int *deg, *off, *cur, *eid;
    __nv_bfloat16 *Ah, *Al, *B1h, *B1l, *B2h, *B2l;
};

extern "C" void kernel_launch(void* const* d_in, const int* in_sizes, int n_in,
                              void* d_out, int out_size)
{
    const float* x  = (const float*)d_in[0];
    const int*   ei = (const int*)d_in[1];
    const float* ea = (const float*)d_in[2];

    const float *Wg[3], *We[3], *attn[3], *at[3], *cb[3];
    const float *lw[3], *lb[3], *gg[3], *bb[3];

    if (in_sizes[8] == 1048576) {
        for (int i = 0; i < 3; i++) {
            Wg[i]   = (const float*)d_in[3 + 5 * i];
            We[i]   = (const float*)d_in[4 + 5 * i];
            attn[i] = (const float*)d_in[5 + 5 * i];
            at[i]   = (const float*)d_in[6 + 5 * i];
            cb[i]   = (const float*)d_in[7 + 5 * i];
            lw[i]   = (const float*)d_in[18 + 4 * i];
            lb[i]   = (const float*)d_in[19 + 4 * i];
            gg[i]   = (const float*)d_in[20 + 4 * i];
            bb[i]   = (const float*)d_in[21 + 4 * i];
        }
    } else {
        for (int i = 0; i < 3; i++) {
            Wg[i]   = (const float*)d_in[3 + 9 * i];
            We[i]   = (const float*)d_in[4 + 9 * i];
            attn[i] = (const float*)d_in[5 + 9 * i];
            at[i]   = (const float*)d_in[6 + 9 * i];
            cb[i]   = (const float*)d_in[7 + 9 * i];
            lw[i]   = (const float*)d_in[8 + 9 * i];
            lb[i]   = (const float*)d_in[9 + 9 * i];
            gg[i]   = (const float*)d_in[10 + 9 * i];
            bb[i]   = (const float*)d_in[11 + 9 * i];
        }
    }

    Scratch S;
    cudaGetSymbolAddress((void**)&S.lin, g_lin);
    cudaGetSymbolAddress((void**)&S.hg, g_hg);
    cudaGetSymbolAddress((void**)&S.h, g_h);
    cudaGetSymbolAddress((void**)&S.logw, g_logw);
    cudaGetSymbolAddress((void**)&S.ssrc, g_ssrc);
    cudaGetSymbolAddress((void**)&S.sdst, g_sdst);
    cudaGetSymbolAddress((void**)&S.p1, g_part1);
    cudaGetSymbolAddress((void**)&S.p2, g_part2);
    cudaGetSymbolAddress((void**)&S.scale, g_scale);
    cudaGetSymbolAddress((void**)&S.shift, g_shift);
    cudaGetSymbolAddress((void**)&S.ve, g_ve);
    cudaGetSymbolAddress((void**)&S.deg, g_deg);
    cudaGetSymbolAddress((void**)&S.off, g_off);
    cudaGetSymbolAddress((void**)&S.cur, g_cur);
    cudaGetSymbolAddress((void**)&S.eid, g_eid);
    cudaGetSymbolAddress((void**)&S.Ah, g_Ah);
    cudaGetSymbolAddress((void**)&S.Al, g_Al);
    cudaGetSymbolAddress((void**)&S.B1h, g_B1h);
    cudaGetSymbolAddress((void**)&S.B1l, g_B1l);
    cudaGetSymbolAddress((void**)&S.B2h, g_B2h);
    cudaGetSymbolAddress((void**)&S.B2l, g_B2l);

    cudaFuncSetAttribute(gemm_mma, cudaFuncAttributeMaxDynamicSharedMemorySize, GT_SMEM);

    // ======== layer 1 (GEMM is the 4th launch -> profiled) ========
    {
        int F = F1, Kp = 192;
        k_bnstat<<<dim3(cdiv(F, 256), BNCH), 256>>>(x, S.p1, S.p2, F);
        k_bnfin<<<cdiv(F, 256), 256>>>(S.p1, S.p2, gg[0], bb[0], S.scale, S.shift, F);
        size_t tp = (size_t)NN * Kp + 2 * (size_t)HIDD * Kp + (size_t)NN * 8;
        k_prep<<<(int)((tp + 255) / 256), 256>>>(x, S.scale, S.shift, S.Ah, S.Al,
                                                 lw[0], Wg[0], S.B1h, S.B1l, S.B2h, S.B2l,
                                                 S.ssrc, S.sdst, F, Kp);
        gemm_mma<<<dim3(16, cdiv(NN, 128)), 256, GT_SMEM>>>(
            S.Ah, S.Al, Kp, S.B1h, S.B1l, S.B2h, S.B2l, S.lin, S.hg, NN,
            attn[0], S.ssrc, S.sdst);
        k_init<<<cdiv(NN, 256), 256>>>(S.deg, S.cur);
        k_hist<<<cdiv(EE, 256), 256>>>(ei + EE, S.deg);
        k_scan<<<1, 1024>>>(S.deg, S.off, NN);
        k_scatter<<<cdiv(EE, 256), 256>>>(ei + EE, S.off, S.cur, S.eid);
        k_ve<<<1, 64>>>(We[0], attn[0], S.ve, 4, 256);
        k_logits<<<cdiv(EE * 4, 256), 256>>>(ei, ea, S.ssrc, S.sdst, S.ve, at[0], S.logw, 4);
        k_softmax4<<<cdiv(NN, 256), 256>>>(S.off, S.eid, (float4*)S.logw);
        k_agg_big<<<NN, 256>>>(S.hg, S.logw, S.off, S.eid, ea, ei, We[0], S.lin, lb[0], cb[0], S.h);
    }
    // ======== layer 2 ========
    {
        int F = HIDD, Kp = HIDD;
        k_bnstat<<<dim3(cdiv(F, 256), BNCH), 256>>>(S.h, S.p1, S.p2, F);
        k_bnfin<<<cdiv(F, 256), 256>>>(S.p1, S.p2, gg[1], bb[1], S.scale, S.shift, F);
        size_t tp = (size_t)NN * Kp + 2 * (size_t)HIDD * Kp + (size_t)NN * 8;
        k_prep<<<(int)((tp + 255) / 256), 256>>>(S.h, S.scale, S.shift, S.Ah, S.Al,
                                                 lw[1], Wg[1], S.B1h, S.B1l, S.B2h, S.B2l,
                                                 S.ssrc, S.sdst, F, Kp);
        gemm_mma<<<dim3(16, cdiv(NN, 128)), 256, GT_SMEM>>>(
            S.Ah, S.Al, Kp, S.B1h, S.B1l, S.B2h, S.B2l, S.lin, S.hg, NN,
            attn[1], S.ssrc, S.sdst);
        k_ve<<<1, 64>>>(We[1], attn[1], S.ve, 4, 256);
        k_logits<<<cdiv(EE * 4, 256), 256>>>(ei, ea, S.ssrc, S.sdst, S.ve, at[1], S.logw, 4);
        k_softmax4<<<cdiv(NN, 256), 256>>>(S.off, S.eid, (float4*)S.logw);
        k_agg_big<<<NN, 256>>>(S.hg, S.logw, S.off, S.eid, ea, ei, We[1], S.lin, lb[1], cb[1], S.h);
    }
    // ======== layer 3 ========
    {
        k_bnstat<<<dim3(cdiv(HIDD, 256), BNCH), 256>>>(S.h, S.p1, S.p2, HIDD);
        k_bnfin<<<cdiv(HIDD, 256), 256>>>(S.p1, S.p2, gg[2], bb[2], S.scale, S.shift, HIDD);
        k_gemm_small<<<NN, 128>>>(S.h, S.scale, S.shift, lw[2], Wg[2], S.lin, S.hg);
        k_ve<<<1, 64>>>(We[2], attn[2], S.ve, 1, 2);
        k_sdots<<<cdiv(NN * 1 * 32, 256), 256>>>(S.hg, attn[2], S.ssrc, S.sdst, 1, 2);
        k_logits<<<cdiv(EE * 1, 256), 256>>>(ei, ea, S.ssrc, S.sdst, S.ve, at[2], S.logw, 1);
        k_softmax1<<<cdiv(NN, 256), 256>>>(S.off, S.eid, S.logw);
        k_agg_small<<<cdiv(NN, 256), 256>>>(S.hg, S.logw, S.off, S.eid, ea, ei, We[2], S.lin, lb[2], cb[2], (float*)d_out);
    }
}

// round 12
// speedup vs baseline: 1.2065x; 1.1656x over previous
#include <cuda_runtime.h>
#include <cuda_bf16.h>
#include <cuda_fp16.h>
#include <cstdint>
#include <math.h>

#define NN   20000
#define EE   100000
#define F1   167
#define HIDD 1024
#define EDK  10
#define EAC  12
#define BNCH 40

// ---------------- scratch (device globals) ----------------
__device__ float g_lin[(size_t)NN * HIDD];
__device__ float g_hg [(size_t)NN * HIDD];
__device__ float g_h  [(size_t)NN * HIDD];
__device__ float g_logw[(size_t)EE * 4];
__device__ float g_ssrc[(size_t)NN * 4];
__device__ float g_sdst[(size_t)NN * 4];
__device__ float g_part1[BNCH * HIDD];
__device__ float g_part2[BNCH * HIDD];
__device__ float g_scale[HIDD];
__device__ float g_shift[HIDD];
__device__ float g_ve[EDK * 4];
__device__ int   g_deg[NN];
__device__ int   g_off[NN + 1];
__device__ int   g_cur[NN];
__device__ int   g_eid[EE];
__device__ __half g_Ah[(size_t)NN * HIDD];
__device__ __half g_B1h[(size_t)HIDD * HIDD];
__device__ __half g_B1l[(size_t)HIDD * HIDD];
__device__ __half g_B2h[(size_t)HIDD * HIDD];
__device__ __half g_B2l[(size_t)HIDD * HIDD];

// ---------------- BatchNorm: partials ----------------
__global__ void k_bnstat(const float* __restrict__ x, float* __restrict__ p1,
                         float* __restrict__ p2, int F) {
    int c = blockIdx.x * blockDim.x + threadIdx.x;
    if (c >= F) return;
    int chunk = (NN + BNCH - 1) / BNCH;
    int r0 = blockIdx.y * chunk;
    int r1 = r0 + chunk; if (r1 > NN) r1 = NN;
    float a = 0.f, b = 0.f;
    for (int r = r0; r < r1; r++) {
        float v = x[(size_t)r * F + c];
        a += v; b += v * v;
    }
    p1[blockIdx.y * F + c] = a;
    p2[blockIdx.y * F + c] = b;
}

__global__ void k_bnfin(const float* __restrict__ p1, const float* __restrict__ p2,
                        const float* __restrict__ g, const float* __restrict__ b,
                        float* __restrict__ scale, float* __restrict__ shift, int F) {
    int c = blockIdx.x * blockDim.x + threadIdx.x;
    if (c >= F) return;
    float a = 0.f, s = 0.f;
    for (int y = 0; y < BNCH; y++) { a += p1[y * F + c]; s += p2[y * F + c]; }
    float invN = 1.f / (float)NN;
    float mu = a * invN;
    float var = s * invN - mu * mu;
    float rstd = rsqrtf(var + 1e-5f);
    float sc = rstd * g[c];
    scale[c] = sc;
    shift[c] = b[c] - mu * sc;
}

// ---------------- fused prep: A fp16 + both B fp16-splits + zero ssrc/sdst ------
__global__ void k_prep(const float* __restrict__ x, const float* __restrict__ scale,
                       const float* __restrict__ shift,
                       __half* __restrict__ Ah,
                       const float* __restrict__ W1, const float* __restrict__ W2,
                       __half* __restrict__ B1h, __half* __restrict__ B1l,
                       __half* __restrict__ B2h, __half* __restrict__ B2l,
                       float* __restrict__ ssrc, float* __restrict__ sdst,
                       int F, int Kp) {
    size_t na = (size_t)NN * Kp;
    size_t nb = (size_t)HIDD * Kp;
    size_t i = (size_t)blockIdx.x * blockDim.x + threadIdx.x;
    if (i < na) {
        int m = (int)(i / Kp), k = (int)(i % Kp);
        float v = 0.f;
        if (k < F) v = x[(size_t)m * F + k] * scale[k] + shift[k];
        Ah[i] = __float2half_rn(v);
    } else if (i < na + 2 * nb) {
        size_t j = i - na;
        const float* W = (j < nb) ? W1 : W2;
        __half* Bh = (j < nb) ? B1h : B2h;
        __half* Bl = (j < nb) ? B1l : B2l;
        if (j >= nb) j -= nb;
        int n = (int)(j / Kp), k = (int)(j % Kp);
        float v = (k < F) ? W[(size_t)k * HIDD + n] : 0.f;
        __half h = __float2half_rn(v);
        Bh[j] = h;
        Bl[j] = __float2half_rn(v - __half2float(h));
    } else if (i < na + 2 * nb + (size_t)NN * 4) {
        ssrc[i - na - 2 * nb] = 0.f;
    } else if (i < na + 2 * nb + (size_t)NN * 8) {
        sdst[i - na - 2 * nb - (size_t)NN * 4] = 0.f;
    }
}

// ---------------- mma.sync helpers ----------------
__device__ __forceinline__ uint32_t smem_u32(const void* p) {
    uint32_t a;
    asm("{ .reg .u64 t; cvta.to.shared.u64 t, %1; cvt.u32.u64 %0, t; }" : "=r"(a) : "l"(p));
    return a;
}
__device__ __forceinline__ void sts128(uint32_t addr, uint4 v) {
    asm volatile("st.shared.v4.b32 [%0], {%1,%2,%3,%4};"
                 :: "r"(addr), "r"(v.x), "r"(v.y), "r"(v.z), "r"(v.w) : "memory");
}
__device__ __forceinline__ void cpasync16(uint32_t s, const void* g) {
    asm volatile("cp.async.cg.shared.global [%0], [%1], 16;" :: "r"(s), "l"(g));
}
#define CP_COMMIT() asm volatile("cp.async.commit_group;" ::: "memory")
#define CP_WAIT0()  asm volatile("cp.async.wait_group 0;" ::: "memory")
// SW64 swizzle for 64-byte rows
#define SWZ64(x) ((x) ^ (((x) >> 3) & 0x30))

#define LDSM4(r0, r1, r2, r3, addr) \
    asm volatile("ldmatrix.sync.aligned.m8n8.x4.shared.b16 {%0,%1,%2,%3}, [%4];" \
                 : "=r"(r0), "=r"(r1), "=r"(r2), "=r"(r3) : "r"(addr))

#define MMA_F16(d, a0, a1, a2, a3, b0, b1) \
    asm volatile("mma.sync.aligned.m16n8k16.row.col.f32.f16.f16.f32 " \
                 "{%0,%1,%2,%3}, {%4,%5,%6,%7}, {%8,%9}, {%0,%1,%2,%3};" \
                 : "+f"((d)[0]), "+f"((d)[1]), "+f"((d)[2]), "+f"((d)[3]) \
                 : "r"(a0), "r"(a1), "r"(a2), "r"(a3), "r"(b0), "r"(b1))

// ---------------- fp16 2-pass GEMM: 128x128 tile, 256 thr, K-chunk 32, 2 CTA/SM --
// acc += Ah*Bh + Ah*Bl (A plain fp16; B split keeps weights exact)
// grid.x = 16 n-tiles: 0-7 -> (B1 -> C1), 8-15 -> (B2 -> C2, + fused attn dots).
#define STAGE_BYTES 24576   // Ah 8K | Bh 8K | Bl 8K  (64B rows, SW64)
#define GT_SMEM (2 * STAGE_BYTES + 512)

__global__ __launch_bounds__(256, 2) void gemm_mma(
    const __half* __restrict__ Ah, int Kp,
    const __half* __restrict__ B1h, const __half* __restrict__ B1l,
    const __half* __restrict__ B2h, const __half* __restrict__ B2l,
    float* __restrict__ C1, float* __restrict__ C2, int M,
    const float* __restrict__ attn, float* __restrict__ ssrc, float* __restrict__ sdst)
{
    extern __shared__ char smraw[];
    uint32_t sb = (smem_u32(smraw) + 255) & ~255u;
    int tid = threadIdx.x, lane = tid & 31, wid = tid >> 5;
    int nt = blockIdx.x, mt = blockIdx.y;

    const __half *Bh, *Bl;
    float* C;
    int coloff;
    if (nt < 8) { Bh = B1h; Bl = B1l; C = C1; coloff = nt * 128; }
    else        { Bh = B2h; Bl = B2l; C = C2; coloff = (nt - 8) * 128; }

    int wm = wid & 1, wn = wid >> 1;   // 2 x 4 warp grid; warp tile 64x32

    float acc[4][4][4];
#pragma unroll
    for (int a = 0; a < 4; a++)
#pragma unroll
        for (int b = 0; b < 4; b++)
#pragma unroll
            for (int cc = 0; cc < 4; cc++) acc[a][b][cc] = 0.f;

    // raw (un-swizzled) ldmatrix base offsets within an 8KB (128 x 64B) region
    uint32_t rawA[4];   // [mi]
    uint32_t rawB[2];   // [pp]
#pragma unroll
    for (int mi = 0; mi < 4; mi++) {
        int row = wm * 64 + mi * 16 + (lane & 15);
        rawA[mi] = (uint32_t)(row * 64 + (lane >> 4) * 16);
    }
#pragma unroll
    for (int p = 0; p < 2; p++) {
        int row = wn * 32 + p * 16 + ((lane >> 4) << 3) + (lane & 7);
        rawB[p] = (uint32_t)(row * 64 + (((lane >> 3) & 1) << 4));
    }

    int q = tid & 3;          // 16B segment within 64B row
    int rr = tid >> 2;        // 0..63 -> rows rr, rr+64
    int chunks = Kp >> 5;     // K-chunk = 32

    auto load_stage = [&](int c) {
        uint32_t base = sb + (uint32_t)(c & 1) * STAGE_BYTES;
        uint32_t bAh = base, bBh = base + 8192, bBl = base + 16384;
        size_t kel = (size_t)c * 32 + q * 8;
#pragma unroll
        for (int i = 0; i < 2; i++) {
            int row = rr + i * 64;
            uint32_t soff = SWZ64((uint32_t)(row * 64 + q * 16));
            int m = mt * 128 + row;
            if (m < M) {
                cpasync16(bAh + soff, Ah + (size_t)m * Kp + kel);
            } else {
                uint4 z = make_uint4(0, 0, 0, 0);
                sts128(bAh + soff, z);
            }
            int nr = coloff + row;
            cpasync16(bBh + soff, Bh + (size_t)nr * Kp + kel);
            cpasync16(bBl + soff, Bl + (size_t)nr * Kp + kel);
        }
        CP_COMMIT();
    };

    load_stage(0);

    for (int c = 0; c < chunks; c++) {
        CP_WAIT0();
        __syncthreads();                 // stage c ready; buffer (c+1)&1 free
        if (c + 1 < chunks) load_stage(c + 1);

        uint32_t cur = sb + (uint32_t)(c & 1) * STAGE_BYTES;
        uint32_t cAh = cur, cBh = cur + 8192, cBl = cur + 16384;
#pragma unroll 1
        for (int k16 = 0; k16 < 2; k16++) {
            uint32_t kb = (uint32_t)k16 * 32;
            uint32_t bh0[4], bh1[4], bl0[4], bl1[4];
#pragma unroll
            for (int pp = 0; pp < 2; pp++) {
                uint32_t addr = SWZ64(rawB[pp] + kb);
                uint32_t r0_, r1_, r2_, r3_;
                LDSM4(r0_, r1_, r2_, r3_, cBh + addr);
                bh0[pp * 2] = r0_; bh1[pp * 2] = r1_;
                bh0[pp * 2 + 1] = r2_; bh1[pp * 2 + 1] = r3_;
                LDSM4(r0_, r1_, r2_, r3_, cBl + addr);
                bl0[pp * 2] = r0_; bl1[pp * 2] = r1_;
                bl0[pp * 2 + 1] = r2_; bl1[pp * 2 + 1] = r3_;
            }
#pragma unroll
            for (int mi = 0; mi < 4; mi++) {
                uint32_t addr = SWZ64(rawA[mi] + kb);
                uint32_t a0, a1, a2, a3;
                LDSM4(a0, a1, a2, a3, cAh + addr);
#pragma unroll
                for (int ni = 0; ni < 4; ni++) {
                    MMA_F16(acc[mi][ni], a0, a1, a2, a3, bh0[ni], bh1[ni]);
                    MMA_F16(acc[mi][ni], a0, a1, a2, a3, bl0[ni], bl1[ni]);
                }
            }
        }
    }

    // epilogue: stores + fused s_src/s_dst dots for the hg half (nt>=8)
    int doAttn = (nt >= 8);
    int hh = (coloff >> 8) & 3;                 // head index (256 cols per head)
    int hcbase = coloff & 255;                  // column base within head
    const float* a0p = attn + (size_t)hh * 256;
    const float* a1p = attn + (size_t)(4 + hh) * 256;
#pragma unroll
    for (int mi = 0; mi < 4; mi++) {
        int gr = mt * 128 + wm * 64 + mi * 16 + (lane >> 2);
        float s0 = 0.f, d0 = 0.f, s1 = 0.f, d1 = 0.f;
#pragma unroll
        for (int ni = 0; ni < 4; ni++) {
            int cl = wn * 32 + ni * 8 + ((lane & 3) << 1);    // col within 128-tile
            int gc = coloff + cl;
            if (gr < M)
                *(float2*)(C + (size_t)gr * HIDD + gc) = make_float2(acc[mi][ni][0], acc[mi][ni][1]);
            if (gr + 8 < M)
                *(float2*)(C + (size_t)(gr + 8) * HIDD + gc) = make_float2(acc[mi][ni][2], acc[mi][ni][3]);
            if (doAttn) {
                int cw = hcbase + cl;
                float2 av = *(const float2*)(a0p + cw);
                float2 bv = *(const float2*)(a1p + cw);
                s0 += acc[mi][ni][0] * av.x + acc[mi][ni][1] * av.y;
                d0 += acc[mi][ni][0] * bv.x + acc[mi][ni][1] * bv.y;
                s1 += acc[mi][ni][2] * av.x + acc[mi][ni][3] * av.y;
                d1 += acc[mi][ni][2] * bv.x + acc[mi][ni][3] * bv.y;
            }
        }
        if (doAttn) {
#pragma unroll
            for (int o = 1; o < 4; o <<= 1) {
                s0 += __shfl_xor_sync(0xFFFFFFFFu, s0, o);
                d0 += __shfl_xor_sync(0xFFFFFFFFu, d0, o);
                s1 += __shfl_xor_sync(0xFFFFFFFFu, s1, o);
                d1 += __shfl_xor_sync(0xFFFFFFFFu, d1, o);
            }
            if ((lane & 3) == 0) {
                if (gr < M) {
                    atomicAdd(&ssrc[gr * 4 + hh], s0);
                    atomicAdd(&sdst[gr * 4 + hh], d0);
                }
                if (gr + 8 < M) {
                    atomicAdd(&ssrc[(gr + 8) * 4 + hh], s1);
                    atomicAdd(&sdst[(gr + 8) * 4 + hh], d1);
                }
            }
        }
    }
}

// ---------------- CSR build ----------------
__global__ void k_init(int* deg, int* cur) {
    int i = blockIdx.x * blockDim.x + threadIdx.x;
    if (i < NN) { deg[i] = 0; cur[i] = 0; }
}
__global__ void k_hist(const int* __restrict__ dst, int* __restrict__ deg) {
    int e = blockIdx.x * blockDim.x + threadIdx.x;
    if (e < EE) atomicAdd(&deg[dst[e]], 1);
}
__global__ void k_scan(const int* __restrict__ deg, int* __restrict__ off, int n) {
    __shared__ int sh[1024];
    __shared__ int carry;
    int t = threadIdx.x;
    if (t == 0) { carry = 0; off[0] = 0; }
    __syncthreads();
    for (int base = 0; base < n; base += 1024) {
        int v = (base + t < n) ? deg[base + t] : 0;
        sh[t] = v;
        __syncthreads();
        for (int d = 1; d < 1024; d <<= 1) {
            int add = (t >= d) ? sh[t - d] : 0;
            __syncthreads();
            sh[t] += add;
            __syncthreads();
        }
        if (base + t < n) off[base + t + 1] = carry + sh[t];
        __syncthreads();
        if (t == 0) carry += sh[1023];
        __syncthreads();
    }
}
__global__ void k_scatter(const int* __restrict__ dst, const int* __restrict__ off,
                          int* __restrict__ cur, int* __restrict__ eid) {
    int e = blockIdx.x * blockDim.x + threadIdx.x;
    if (e >= EE) return;
    int d = dst[e];
    int p = atomicAdd(&cur[d], 1);
    eid[off[d] + p] = e;
}

// ---------------- layer-3 tiny GEMM (BN inline, fp32) ----------------
__global__ __launch_bounds__(128) void k_gemm_small(
    const float* __restrict__ h, const float* __restrict__ scale,
    const float* __restrict__ shift,
    const float* __restrict__ lw, const float* __restrict__ wg,
    float* __restrict__ lin, float* __restrict__ hg)
{
    int n = blockIdx.x, t = threadIdx.x;
    const float* hr = h + (size_t)n * HIDD;
    float a0 = 0, a1 = 0, a2 = 0, a3 = 0;
    for (int k = t; k < HIDD; k += 128) {
        float a = hr[k] * scale[k] + shift[k];
        a0 += a * lw[k * 2];
        a1 += a * lw[k * 2 + 1];
        a2 += a * wg[k * 2];
        a3 += a * wg[k * 2 + 1];
    }
#pragma unroll
    for (int s = 16; s; s >>= 1) {
        a0 += __shfl_down_sync(0xFFFFFFFFu, a0, s);
        a1 += __shfl_down_sync(0xFFFFFFFFu, a1, s);
        a2 += __shfl_down_sync(0xFFFFFFFFu, a2, s);
        a3 += __shfl_down_sync(0xFFFFFFFFu, a3, s);
    }
    __shared__ float sm[4][4];
    if ((t & 31) == 0) {
        sm[t >> 5][0] = a0; sm[t >> 5][1] = a1; sm[t >> 5][2] = a2; sm[t >> 5][3] = a3;
    }
    __syncthreads();
    if (t == 0) {
        lin[(size_t)n * 2]     = sm[0][0] + sm[1][0] + sm[2][0] + sm[3][0];
        lin[(size_t)n * 2 + 1] = sm[0][1] + sm[1][1] + sm[2][1] + sm[3][1];
        hg [(size_t)n * 2]     = sm[0][2] + sm[1][2] + sm[2][2] + sm[3][2];
        hg [(size_t)n * 2 + 1] = sm[0][3] + sm[1][3] + sm[2][3] + sm[3][3];
    }
}

// ---------------- GAT pieces ----------------
__global__ void k_ve(const float* __restrict__ We, const float* __restrict__ attn,
                     float* __restrict__ ve, int H, int O) {
    int t = threadIdx.x;
    if (t >= H * EDK) return;
    int h = t / EDK, k = t % EDK;
    const float* a2 = attn + (size_t)(2 * H + h) * O;
    const float* w = We + (size_t)k * H * O + (size_t)h * O;
    float s = 0.f;
    for (int d = 0; d < O; d++) s += w[d] * a2[d];
    ve[k * H + h] = s;
}

__global__ void k_sdots(const float* __restrict__ hg, const float* __restrict__ attn,
                        float* __restrict__ ssrc, float* __restrict__ sdst, int H, int O) {
    int gw = (blockIdx.x * blockDim.x + threadIdx.x) >> 5;
    int lane = threadIdx.x & 31;
    if (gw >= NN * H) return;
    int n = gw / H, h = gw % H;
    const float* hr = hg + (size_t)n * H * O + (size_t)h * O;
    const float* a0 = attn + (size_t)h * O;
    const float* a1 = attn + (size_t)(H + h) * O;
    float d0 = 0.f, d1 = 0.f;
    for (int d = lane; d < O; d += 32) {
        float v = hr[d];
        d0 += v * a0[d];
        d1 += v * a1[d];
    }
#pragma unroll
    for (int s = 16; s; s >>= 1) {
        d0 += __shfl_down_sync(0xFFFFFFFFu, d0, s);
        d1 += __shfl_down_sync(0xFFFFFFFFu, d1, s);
    }
    if (lane == 0) { ssrc[gw] = d0; sdst[gw] = d1; }
}

__global__ void k_logits(const int* __restrict__ ei, const float* __restrict__ ea,
                         const float* __restrict__ ssrc, const float* __restrict__ sdst,
                         const float* __restrict__ ve, const float* __restrict__ at,
                         float* __restrict__ logw, int H) {
    int idx = blockIdx.x * blockDim.x + threadIdx.x;
    if (idx >= EE * H) return;
    int e = idx / H, h = idx % H;
    int s = ei[e], d = ei[EE + e];
    const float* row = ea + (size_t)e * EAC;
    float t = row[0];
    float se = 0.f;
#pragma unroll
    for (int k = 0; k < EDK; k++) se += row[1 + k] * ve[k * H + h];
    float l = ssrc[s * H + h] + sdst[d * H + h] + se + t * at[h];
    logw[idx] = (l > 0.f) ? l : 0.2f * l;
}

__global__ void k_softmax4(const int* __restrict__ off, const int* __restrict__ eid,
                           float4* __restrict__ w4) {
    int n = blockIdx.x * blockDim.x + threadIdx.x;
    if (n >= NN) return;
    int d0 = off[n], d1 = off[n + 1];
    if (d0 == d1) return;
    float4 m = make_float4(-INFINITY, -INFINITY, -INFINITY, -INFINITY);
    for (int i = d0; i < d1; i++) {
        float4 v = w4[eid[i]];
        m.x = fmaxf(m.x, v.x); m.y = fmaxf(m.y, v.y);
        m.z = fmaxf(m.z, v.z); m.w = fmaxf(m.w, v.w);
    }
    float4 s = make_float4(0.f, 0.f, 0.f, 0.f);
    for (int i = d0; i < d1; i++) {
        float4 v = w4[eid[i]];
        v.x = expf(v.x - m.x); v.y = expf(v.y - m.y);
        v.z = expf(v.z - m.z); v.w = expf(v.w - m.w);
        w4[eid[i]] = v;
        s.x += v.x; s.y += v.y; s.z += v.z; s.w += v.w;
    }
    float4 inv = make_float4(1.f / (s.x + 1e-16f), 1.f / (s.y + 1e-16f),
                             1.f / (s.z + 1e-16f), 1.f / (s.w + 1e-16f));
    for (int i = d0; i < d1; i++) {
        float4 v = w4[eid[i]];
        v.x *= inv.x; v.y *= inv.y; v.z *= inv.z; v.w *= inv.w;
        w4[eid[i]] = v;
    }
}

__global__ void k_softmax1(const int* __restrict__ off, const int* __restrict__ eid,
                           float* __restrict__ logw) {
    int n = blockIdx.x * blockDim.x + threadIdx.x;
    if (n >= NN) return;
    int d0 = off[n], d1 = off[n + 1];
    if (d0 == d1) return;
    float m = -INFINITY;
    for (int i = d0; i < d1; i++) m = fmaxf(m, logw[eid[i]]);
    float s = 0.f;
    for (int i = d0; i < d1; i++) {
        float p = expf(logw[eid[i]] - m);
        logw[eid[i]] = p;
        s += p;
    }
    float inv = 1.f / (s + 1e-16f);
    for (int i = d0; i < d1; i++) logw[eid[i]] *= inv;
}

__global__ __launch_bounds__(256) void k_agg_big(
    const float* __restrict__ hg, const float* __restrict__ w,
    const int* __restrict__ off, const int* __restrict__ eid,
    const float* __restrict__ ea, const int* __restrict__ src,
    const float* __restrict__ We, const float* __restrict__ lin,
    const float* __restrict__ lb, const float* __restrict__ cb,
    float* __restrict__ out)
{
    int n = blockIdx.x;
    int t = threadIdx.x;
    __shared__ float qs[40];
    if (t < 40) qs[t] = 0.f;
    float acc0 = 0.f, acc1 = 0.f, acc2 = 0.f, acc3 = 0.f;
    int d0 = off[n], d1 = off[n + 1];
    for (int i = d0; i < d1; i++) {
        int e = eid[i];
        int s = src[e];
        float4 wv = *(const float4*)(w + (size_t)e * 4);
        const float* hr = hg + (size_t)s * 1024;
        acc0 += wv.x * hr[t];
        acc1 += wv.y * hr[t + 256];
        acc2 += wv.z * hr[t + 512];
        acc3 += wv.w * hr[t + 768];
        if (t < 40) {
            int h = t / 10, k = t % 10;
            float wh = (h == 0) ? wv.x : (h == 1) ? wv.y : (h == 2) ? wv.z : wv.w;
            qs[t] += wh * ea[(size_t)e * EAC + 1 + k];
        }
    }
    __syncthreads();
    float acch[4] = {acc0, acc1, acc2, acc3};
#pragma unroll
    for (int h = 0; h < 4; h++) {
        int f = h * 256 + t;
        float et = 0.f;
#pragma unroll
        for (int k = 0; k < 10; k++) et += qs[h * 10 + k] * We[k * 1024 + f];
        float v = lin[(size_t)n * 1024 + f] + lb[f] + cb[f] + acch[h] + et;
        out[(size_t)n * 1024 + f] = fmaxf(v, 0.f);
    }
}

__global__ void k_agg_small(
    const float* __restrict__ hg, const float* __restrict__ w,
    const int* __restrict__ off, const int* __restrict__ eid,
    const float* __restrict__ ea, const int* __restrict__ src,
    const float* __restrict__ We, const float* __restrict__ lin,
    const float* __restrict__ lb, const float* __restrict__ cb,
    float* __restrict__ out)
{
    int n = blockIdx.x * blockDim.x + threadIdx.x;
    if (n >= NN) return;
    float a0 = 0.f, a1 = 0.f;
    float q[10];
#pragma unroll
    for (int k = 0; k < 10; k++) q[k] = 0.f;
    int d0 = off[n], d1 = off[n + 1];
    for (int i = d0; i < d1; i++) {
        int e = eid[i];
        int s = src[e];
        float wv = w[e];
        a0 += wv * hg[(size_t)s * 2];
        a1 += wv * hg[(size_t)s * 2 + 1];
        const float* row = ea + (size_t)e * EAC;
#pragma unroll
        for (int k = 0; k < 10; k++) q[k] += wv * row[1 + k];
    }
    float e0 = 0.f, e1 = 0.f;
#pragma unroll
    for (int k = 0; k < 10; k++) { e0 += q[k] * We[k * 2]; e1 += q[k] * We[k * 2 + 1]; }
    float v0 = lin[(size_t)n * 2] + lb[0] + cb[0] + a0 + e0;
    float v1 = lin[(size_t)n * 2 + 1] + lb[1] + cb[1] + a1 + e1;
    out[(size_t)n * 2] = fmaxf(v0, 0.f);
    out[(size_t)n * 2 + 1] = fmaxf(v1, 0.f);
}

// ---------------- host driver ----------------
static inline int cdiv(int a, int b) { return (a + b - 1) / b; }

struct Scratch {
    float *lin, *hg, *h, *logw, *ssrc, *sdst, *scale, *shift, *ve, *p1, *p2;
    int *deg, *off, *cur, *eid;
    __half *Ah, *B1h, *B1l, *B2h, *B2l;
};

extern "C" void kernel_launch(void* const* d_in, const int* in_sizes, int n_in,
                              void* d_out, int out_size)
{
    const float* x  = (const float*)d_in[0];
    const int*   ei = (const int*)d_in[1];
    const float* ea = (const float*)d_in[2];

    const float *Wg[3], *We[3], *attn[3], *at[3], *cb[3];
    const float *lw[3], *lb[3], *gg[3], *bb[3];

    if (in_sizes[8] == 1048576) {
        for (int i = 0; i < 3; i++) {
            Wg[i]   = (const float*)d_in[3 + 5 * i];
            We[i]   = (const float*)d_in[4 + 5 * i];
            attn[i] = (const float*)d_in[5 + 5 * i];
            at[i]   = (const float*)d_in[6 + 5 * i];
            cb[i]   = (const float*)d_in[7 + 5 * i];
            lw[i]   = (const float*)d_in[18 + 4 * i];
            lb[i]   = (const float*)d_in[19 + 4 * i];
            gg[i]   = (const float*)d_in[20 + 4 * i];
            bb[i]   = (const float*)d_in[21 + 4 * i];
        }
    } else {
        for (int i = 0; i < 3; i++) {
            Wg[i]   = (const float*)d_in[3 + 9 * i];
            We[i]   = (const float*)d_in[4 + 9 * i];
            attn[i] = (const float*)d_in[5 + 9 * i];
            at[i]   = (const float*)d_in[6 + 9 * i];
            cb[i]   = (const float*)d_in[7 + 9 * i];
            lw[i]   = (const float*)d_in[8 + 9 * i];
            lb[i]   = (const float*)d_in[9 + 9 * i];
            gg[i]   = (const float*)d_in[10 + 9 * i];
            bb[i]   = (const float*)d_in[11 + 9 * i];
        }
    }

    Scratch S;
    cudaGetSymbolAddress((void**)&S.lin, g_lin);
    cudaGetSymbolAddress((void**)&S.hg, g_hg);
    cudaGetSymbolAddress((void**)&S.h, g_h);
    cudaGetSymbolAddress((void**)&S.logw, g_logw);
    cudaGetSymbolAddress((void**)&S.ssrc, g_ssrc);
    cudaGetSymbolAddress((void**)&S.sdst, g_sdst);
    cudaGetSymbolAddress((void**)&S.p1, g_part1);
    cudaGetSymbolAddress((void**)&S.p2, g_part2);
    cudaGetSymbolAddress((void**)&S.scale, g_scale);
    cudaGetSymbolAddress((void**)&S.shift, g_shift);
    cudaGetSymbolAddress((void**)&S.ve, g_ve);
    cudaGetSymbolAddress((void**)&S.deg, g_deg);
    cudaGetSymbolAddress((void**)&S.off, g_off);
    cudaGetSymbolAddress((void**)&S.cur, g_cur);
    cudaGetSymbolAddress((void**)&S.eid, g_eid);
    cudaGetSymbolAddress((void**)&S.Ah, g_Ah);
    cudaGetSymbolAddress((void**)&S.B1h, g_B1h);
    cudaGetSymbolAddress((void**)&S.B1l, g_B1l);
    cudaGetSymbolAddress((void**)&S.B2h, g_B2h);
    cudaGetSymbolAddress((void**)&S.B2l, g_B2l);

    cudaFuncSetAttribute(gemm_mma, cudaFuncAttributeMaxDynamicSharedMemorySize, GT_SMEM);

    // ======== layer 1 (GEMM is the 4th launch -> profiled) ========
    {
        int F = F1, Kp = 192;
        k_bnstat<<<dim3(cdiv(F, 256), BNCH), 256>>>(x, S.p1, S.p2, F);
        k_bnfin<<<cdiv(F, 256), 256>>>(S.p1, S.p2, gg[0], bb[0], S.scale, S.shift, F);
        size_t tp = (size_t)NN * Kp + 2 * (size_t)HIDD * Kp + (size_t)NN * 8;
        k_prep<<<(int)((tp + 255) / 256), 256>>>(x, S.scale, S.shift, S.Ah,
                                                 lw[0], Wg[0], S.B1h, S.B1l, S.B2h, S.B2l,
                                                 S.ssrc, S.sdst, F, Kp);
        gemm_mma<<<dim3(16, cdiv(NN, 128)), 256, GT_SMEM>>>(
            S.Ah, Kp, S.B1h, S.B1l, S.B2h, S.B2l, S.lin, S.hg, NN,
            attn[0], S.ssrc, S.sdst);
        k_init<<<cdiv(NN, 256), 256>>>(S.deg, S.cur);
        k_hist<<<cdiv(EE, 256), 256>>>(ei + EE, S.deg);
        k_scan<<<1, 1024>>>(S.deg, S.off, NN);
        k_scatter<<<cdiv(EE, 256), 256>>>(ei + EE, S.off, S.cur, S.eid);
        k_ve<<<1, 64>>>(We[0], attn[0], S.ve, 4, 256);
        k_logits<<<cdiv(EE * 4, 256), 256>>>(ei, ea, S.ssrc, S.sdst, S.ve, at[0], S.logw, 4);
        k_softmax4<<<cdiv(NN, 256), 256>>>(S.off, S.eid, (float4*)S.logw);
        k_agg_big<<<NN, 256>>>(S.hg, S.logw, S.off, S.eid, ea, ei, We[0], S.lin, lb[0], cb[0], S.h);
    }
    // ======== layer 2 ========
    {
        int F = HIDD, Kp = HIDD;
        k_bnstat<<<dim3(cdiv(F, 256), BNCH), 256>>>(S.h, S.p1, S.p2, F);
        k_bnfin<<<cdiv(F, 256), 256>>>(S.p1, S.p2, gg[1], bb[1], S.scale, S.shift, F);
        size_t tp = (size_t)NN * Kp + 2 * (size_t)HIDD * Kp + (size_t)NN * 8;
        k_prep<<<(int)((tp + 255) / 256), 256>>>(S.h, S.scale, S.shift, S.Ah,
                                                 lw[1], Wg[1], S.B1h, S.B1l, S.B2h, S.B2l,
                                                 S.ssrc, S.sdst, F, Kp);
        gemm_mma<<<dim3(16, cdiv(NN, 128)), 256, GT_SMEM>>>(
            S.Ah, Kp, S.B1h, S.B1l, S.B2h, S.B2l, S.lin, S.hg, NN,
            attn[1], S.ssrc, S.sdst);
        k_ve<<<1, 64>>>(We[1], attn[1], S.ve, 4, 256);
        k_logits<<<cdiv(EE * 4, 256), 256>>>(ei, ea, S.ssrc, S.sdst, S.ve, at[1], S.logw, 4);
        k_softmax4<<<cdiv(NN, 256), 256>>>(S.off, S.eid, (float4*)S.logw);
        k_agg_big<<<NN, 256>>>(S.hg, S.logw, S.off, S.eid, ea, ei, We[1], S.lin, lb[1], cb[1], S.h);
    }
    // ======== layer 3 ========
    {
        k_bnstat<<<dim3(cdiv(HIDD, 256), BNCH), 256>>>(S.h, S.p1, S.p2, HIDD);
        k_bnfin<<<cdiv(HIDD, 256), 256>>>(S.p1, S.p2, gg[2], bb[2], S.scale, S.shift, HIDD);
        k_gemm_small<<<NN, 128>>>(S.h, S.scale, S.shift, lw[2], Wg[2], S.lin, S.hg);
        k_ve<<<1, 64>>>(We[2], attn[2], S.ve, 1, 2);
        k_sdots<<<cdiv(NN * 1 * 32, 256), 256>>>(S.hg, attn[2], S.ssrc, S.sdst, 1, 2);
        k_logits<<<cdiv(EE * 1, 256), 256>>>(ei, ea, S.ssrc, S.sdst, S.ve, at[2], S.logw, 1);
        k_softmax1<<<cdiv(NN, 256), 256>>>(S.off, S.eid, S.logw);
        k_agg_small<<<cdiv(NN, 256), 256>>>(S.hg, S.logw, S.off, S.eid, ea, ei, We[2], S.lin, lb[2], cb[2], (float*)d_out);
    }
}

// round 13
// speedup vs baseline: 1.2083x; 1.0015x over previous
#include <cuda_runtime.h>
#include <cuda_bf16.h>
#include <cuda_fp16.h>
#include <cstdint>
#include <math.h>

#define NN   20000
#define EE   100000
#define F1   167
#define HIDD 1024
#define EDK  10
#define EAC  12
#define BNCH 40

// ---------------- scratch (device globals) ----------------
__device__ float g_lin[(size_t)NN * HIDD];
__device__ float g_hg [(size_t)NN * HIDD];
__device__ float g_h  [(size_t)NN * HIDD];
__device__ float g_logw[(size_t)EE * 4];
__device__ float g_ssrc[(size_t)NN * 4];
__device__ float g_sdst[(size_t)NN * 4];
__device__ float g_part1[BNCH * HIDD];
__device__ float g_part2[BNCH * HIDD];
__device__ float g_scale[HIDD];
__device__ float g_shift[HIDD];
__device__ float g_ve[EDK * 4];
__device__ int   g_deg[NN];
__device__ int   g_off[NN + 1];
__device__ int   g_cur[NN];
__device__ int   g_eid[EE];
__device__ __half g_Ah[(size_t)NN * HIDD];
__device__ __half g_B1h[(size_t)HIDD * HIDD];
__device__ __half g_B1l[(size_t)HIDD * HIDD];
__device__ __half g_B2h[(size_t)HIDD * HIDD];
__device__ __half g_B2l[(size_t)HIDD * HIDD];

// ---------------- BatchNorm: partials ----------------
__global__ void k_bnstat(const float* __restrict__ x, float* __restrict__ p1,
                         float* __restrict__ p2, int F) {
    int c = blockIdx.x * blockDim.x + threadIdx.x;
    if (c >= F) return;
    int chunk = (NN + BNCH - 1) / BNCH;
    int r0 = blockIdx.y * chunk;
    int r1 = r0 + chunk; if (r1 > NN) r1 = NN;
    float a = 0.f, b = 0.f;
    for (int r = r0; r < r1; r++) {
        float v = x[(size_t)r * F + c];
        a += v; b += v * v;
    }
    p1[blockIdx.y * F + c] = a;
    p2[blockIdx.y * F + c] = b;
}

__global__ void k_bnfin(const float* __restrict__ p1, const float* __restrict__ p2,
                        const float* __restrict__ g, const float* __restrict__ b,
                        float* __restrict__ scale, float* __restrict__ shift, int F) {
    int c = blockIdx.x * blockDim.x + threadIdx.x;
    if (c >= F) return;
    float a = 0.f, s = 0.f;
    for (int y = 0; y < BNCH; y++) { a += p1[y * F + c]; s += p2[y * F + c]; }
    float invN = 1.f / (float)NN;
    float mu = a * invN;
    float var = s * invN - mu * mu;
    float rstd = rsqrtf(var + 1e-5f);
    float sc = rstd * g[c];
    scale[c] = sc;
    shift[c] = b[c] - mu * sc;
}

// ---------------- prep A (fp16, BN fused) + zero ssrc/sdst ----------------
__global__ void k_prep(const float* __restrict__ x, const float* __restrict__ scale,
                       const float* __restrict__ shift, __half* __restrict__ Ah,
                       float* __restrict__ ssrc, float* __restrict__ sdst,
                       int F, int Kp) {
    size_t na = (size_t)NN * Kp;
    size_t i = (size_t)blockIdx.x * blockDim.x + threadIdx.x;
    if (i < na) {
        int m = (int)(i / Kp), k = (int)(i % Kp);
        float v = 0.f;
        if (k < F) v = x[(size_t)m * F + k] * scale[k] + shift[k];
        Ah[i] = __float2half_rn(v);
    } else if (i < na + (size_t)NN * 4) {
        ssrc[i - na] = 0.f;
    } else if (i < na + (size_t)NN * 8) {
        sdst[i - na - (size_t)NN * 4] = 0.f;
    }
}

// ---------------- prep B: coalesced transpose + fp16 split ----------------
// grid (Kp/32, HIDD/32, 2), block (32, 8)
__global__ void k_prepB_t(const float* __restrict__ W1, const float* __restrict__ W2,
                          __half* __restrict__ B1h, __half* __restrict__ B1l,
                          __half* __restrict__ B2h, __half* __restrict__ B2l,
                          int F, int Kp) {
    __shared__ float tile[32][33];
    const float* W = blockIdx.z ? W2 : W1;
    __half* Bh = blockIdx.z ? B2h : B1h;
    __half* Bl = blockIdx.z ? B2l : B1l;
    int k0 = blockIdx.x * 32, n0 = blockIdx.y * 32;
    int tx = threadIdx.x, ty = threadIdx.y;
#pragma unroll
    for (int r = ty; r < 32; r += 8) {
        int k = k0 + r;
        tile[r][tx] = (k < F) ? W[(size_t)k * HIDD + n0 + tx] : 0.f;
    }
    __syncthreads();
#pragma unroll
    for (int r = ty; r < 32; r += 8) {
        int n = n0 + r, k = k0 + tx;
        float v = tile[tx][r];
        __half h = __float2half_rn(v);
        Bh[(size_t)n * Kp + k] = h;
        Bl[(size_t)n * Kp + k] = __float2half_rn(v - __half2float(h));
    }
}

// ---------------- mma.sync helpers ----------------
__device__ __forceinline__ uint32_t smem_u32(const void* p) {
    uint32_t a;
    asm("{ .reg .u64 t; cvta.to.shared.u64 t, %1; cvt.u32.u64 %0, t; }" : "=r"(a) : "l"(p));
    return a;
}
__device__ __forceinline__ void sts128(uint32_t addr, uint4 v) {
    asm volatile("st.shared.v4.b32 [%0], {%1,%2,%3,%4};"
                 :: "r"(addr), "r"(v.x), "r"(v.y), "r"(v.z), "r"(v.w) : "memory");
}
__device__ __forceinline__ void cpasync16(uint32_t s, const void* g) {
    asm volatile("cp.async.cg.shared.global [%0], [%1], 16;" :: "r"(s), "l"(g));
}
#define CP_COMMIT() asm volatile("cp.async.commit_group;" ::: "memory")
#define CP_WAIT0()  asm volatile("cp.async.wait_group 0;" ::: "memory")
#define CP_WAIT1()  asm volatile("cp.async.wait_group 1;" ::: "memory")
#define SWZ64(x) ((x) ^ (((x) >> 3) & 0x30))

#define LDSM4(r0, r1, r2, r3, addr) \
    asm volatile("ldmatrix.sync.aligned.m8n8.x4.shared.b16 {%0,%1,%2,%3}, [%4];" \
                 : "=r"(r0), "=r"(r1), "=r"(r2), "=r"(r3) : "r"(addr))

#define MMA_F16(d, a0, a1, a2, a3, b0, b1) \
    asm volatile("mma.sync.aligned.m16n8k16.row.col.f32.f16.f16.f32 " \
                 "{%0,%1,%2,%3}, {%4,%5,%6,%7}, {%8,%9}, {%0,%1,%2,%3};" \
                 : "+f"((d)[0]), "+f"((d)[1]), "+f"((d)[2]), "+f"((d)[3]) \
                 : "r"(a0), "r"(a1), "r"(a2), "r"(a3), "r"(b0), "r"(b1))

// ---------------- fp16 2-pass GEMM: 128x128 tile, 256 thr, 3-stage, 2 CTA/SM ----
#define STAGE_BYTES 24576   // Ah 8K | Bh 8K | Bl 8K
#define GT_SMEM (3 * STAGE_BYTES + 512)

__global__ __launch_bounds__(256, 2) void gemm_mma(
    const __half* __restrict__ Ah, int Kp,
    const __half* __restrict__ B1h, const __half* __restrict__ B1l,
    const __half* __restrict__ B2h, const __half* __restrict__ B2l,
    float* __restrict__ C1, float* __restrict__ C2, int M,
    const float* __restrict__ attn, float* __restrict__ ssrc, float* __restrict__ sdst)
{
    extern __shared__ char smraw[];
    uint32_t sb = (smem_u32(smraw) + 255) & ~255u;
    int tid = threadIdx.x, lane = tid & 31, wid = tid >> 5;
    int nt = blockIdx.x, mt = blockIdx.y;

    const __half *Bh, *Bl;
    float* C;
    int coloff;
    if (nt < 8) { Bh = B1h; Bl = B1l; C = C1; coloff = nt * 128; }
    else        { Bh = B2h; Bl = B2l; C = C2; coloff = (nt - 8) * 128; }

    int wm = wid & 1, wn = wid >> 1;   // 2 x 4 warp grid; warp tile 64x32

    float acc[4][4][4];
#pragma unroll
    for (int a = 0; a < 4; a++)
#pragma unroll
        for (int b = 0; b < 4; b++)
#pragma unroll
            for (int cc = 0; cc < 4; cc++) acc[a][b][cc] = 0.f;

    // precomputed swizzled ldmatrix offsets for both k16 values
    uint32_t adA[4][2];
    uint32_t adB[2][2];
#pragma unroll
    for (int mi = 0; mi < 4; mi++) {
        int row = wm * 64 + mi * 16 + (lane & 15);
        uint32_t raw = (uint32_t)(row * 64 + (lane >> 4) * 16);
        adA[mi][0] = SWZ64(raw);
        adA[mi][1] = SWZ64(raw + 32);
    }
#pragma unroll
    for (int p = 0; p < 2; p++) {
        int row = wn * 32 + p * 16 + ((lane >> 4) << 3) + (lane & 7);
        uint32_t raw = (uint32_t)(row * 64 + (((lane >> 3) & 1) << 4));
        adB[p][0] = SWZ64(raw);
        adB[p][1] = SWZ64(raw + 32);
    }

    int q = tid & 3;
    int rr = tid >> 2;
    int chunks = Kp >> 5;

    auto load_stage = [&](int c) {
        uint32_t base = sb + (uint32_t)(c % 3) * STAGE_BYTES;
        uint32_t bAh = base, bBh = base + 8192, bBl = base + 16384;
        size_t kel = (size_t)c * 32 + q * 8;
#pragma unroll
        for (int i = 0; i < 2; i++) {
            int row = rr + i * 64;
            uint32_t soff = SWZ64((uint32_t)(row * 64 + q * 16));
            int m = mt * 128 + row;
            if (m < M) {
                cpasync16(bAh + soff, Ah + (size_t)m * Kp + kel);
            } else {
                uint4 z = make_uint4(0, 0, 0, 0);
                sts128(bAh + soff, z);
            }
            int nr = coloff + row;
            cpasync16(bBh + soff, Bh + (size_t)nr * Kp + kel);
            cpasync16(bBl + soff, Bl + (size_t)nr * Kp + kel);
        }
        CP_COMMIT();
    };

    load_stage(0);
    if (chunks > 1) load_stage(1);

    for (int c = 0; c < chunks; c++) {
        if (c + 1 < chunks) { CP_WAIT1(); } else { CP_WAIT0(); }
        __syncthreads();
        if (c + 2 < chunks) load_stage(c + 2);

        uint32_t cur = sb + (uint32_t)(c % 3) * STAGE_BYTES;
        uint32_t cAh = cur, cBh = cur + 8192, cBl = cur + 16384;
#pragma unroll
        for (int k16 = 0; k16 < 2; k16++) {
            uint32_t af0[4], af1[4], af2[4], af3[4];
#pragma unroll
            for (int mi = 0; mi < 4; mi++)
                LDSM4(af0[mi], af1[mi], af2[mi], af3[mi], cAh + adA[mi][k16]);
            uint32_t bh0[4], bh1[4], bl0[4], bl1[4];
#pragma unroll
            for (int pp = 0; pp < 2; pp++) {
                uint32_t r0_, r1_, r2_, r3_;
                LDSM4(r0_, r1_, r2_, r3_, cBh + adB[pp][k16]);
                bh0[pp * 2] = r0_; bh1[pp * 2] = r1_;
                bh0[pp * 2 + 1] = r2_; bh1[pp * 2 + 1] = r3_;
                LDSM4(r0_, r1_, r2_, r3_, cBl + adB[pp][k16]);
                bl0[pp * 2] = r0_; bl1[pp * 2] = r1_;
                bl0[pp * 2 + 1] = r2_; bl1[pp * 2 + 1] = r3_;
            }
#pragma unroll
            for (int mi = 0; mi < 4; mi++)
#pragma unroll
                for (int ni = 0; ni < 4; ni++)
                    MMA_F16(acc[mi][ni], af0[mi], af1[mi], af2[mi], af3[mi], bh0[ni], bh1[ni]);
#pragma unroll
            for (int mi = 0; mi < 4; mi++)
#pragma unroll
                for (int ni = 0; ni < 4; ni++)
                    MMA_F16(acc[mi][ni], af0[mi], af1[mi], af2[mi], af3[mi], bl0[ni], bl1[ni]);
        }
    }

    // epilogue: stores + fused s_src/s_dst dots for the hg half (nt>=8)
    int doAttn = (nt >= 8);
    int hh = (coloff >> 8) & 3;
    int hcbase = coloff & 255;
    const float* a0p = attn + (size_t)hh * 256;
    const float* a1p = attn + (size_t)(4 + hh) * 256;
#pragma unroll
    for (int mi = 0; mi < 4; mi++) {
        int gr = mt * 128 + wm * 64 + mi * 16 + (lane >> 2);
        float s0 = 0.f, d0 = 0.f, s1 = 0.f, d1 = 0.f;
#pragma unroll
        for (int ni = 0; ni < 4; ni++) {
            int cl = wn * 32 + ni * 8 + ((lane & 3) << 1);
            int gc = coloff + cl;
            if (gr < M)
                *(float2*)(C + (size_t)gr * HIDD + gc) = make_float2(acc[mi][ni][0], acc[mi][ni][1]);
            if (gr + 8 < M)
                *(float2*)(C + (size_t)(gr + 8) * HIDD + gc) = make_float2(acc[mi][ni][2], acc[mi][ni][3]);
            if (doAttn) {
                int cw = hcbase + cl;
                float2 av = *(const float2*)(a0p + cw);
                float2 bv = *(const float2*)(a1p + cw);
                s0 += acc[mi][ni][0] * av.x + acc[mi][ni][1] * av.y;
                d0 += acc[mi][ni][0] * bv.x + acc[mi][ni][1] * bv.y;
                s1 += acc[mi][ni][2] * av.x + acc[mi][ni][3] * av.y;
                d1 += acc[mi][ni][2] * bv.x + acc[mi][ni][3] * bv.y;
            }
        }
        if (doAttn) {
#pragma unroll
            for (int o = 1; o < 4; o <<= 1) {
                s0 += __shfl_xor_sync(0xFFFFFFFFu, s0, o);
                d0 += __shfl_xor_sync(0xFFFFFFFFu, d0, o);
                s1 += __shfl_xor_sync(0xFFFFFFFFu, s1, o);
                d1 += __shfl_xor_sync(0xFFFFFFFFu, d1, o);
            }
            if ((lane & 3) == 0) {
                if (gr < M) {
                    atomicAdd(&ssrc[gr * 4 + hh], s0);
                    atomicAdd(&sdst[gr * 4 + hh], d0);
                }
                if (gr + 8 < M) {
                    atomicAdd(&ssrc[(gr + 8) * 4 + hh], s1);
                    atomicAdd(&sdst[(gr + 8) * 4 + hh], d1);
                }
            }
        }
    }
}

// ---------------- CSR build ----------------
__global__ void k_init(int* deg, int* cur) {
    int i = blockIdx.x * blockDim.x + threadIdx.x;
    if (i < NN) { deg[i] = 0; cur[i] = 0; }
}
__global__ void k_hist(const int* __restrict__ dst, int* __restrict__ deg) {
    int e = blockIdx.x * blockDim.x + threadIdx.x;
    if (e < EE) atomicAdd(&deg[dst[e]], 1);
}
__global__ void k_scan(const int* __restrict__ deg, int* __restrict__ off, int n) {
    __shared__ int sh[1024];
    __shared__ int carry;
    int t = threadIdx.x;
    if (t == 0) { carry = 0; off[0] = 0; }
    __syncthreads();
    for (int base = 0; base < n; base += 1024) {
        int v = (base + t < n) ? deg[base + t] : 0;
        sh[t] = v;
        __syncthreads();
        for (int d = 1; d < 1024; d <<= 1) {
            int add = (t >= d) ? sh[t - d] : 0;
            __syncthreads();
            sh[t] += add;
            __syncthreads();
        }
        if (base + t < n) off[base + t + 1] = carry + sh[t];
        __syncthreads();
        if (t == 0) carry += sh[1023];
        __syncthreads();
    }
}
__global__ void k_scatter(const int* __restrict__ dst, const int* __restrict__ off,
                          int* __restrict__ cur, int* __restrict__ eid) {
    int e = blockIdx.x * blockDim.x + threadIdx.x;
    if (e >= EE) return;
    int d = dst[e];
    int p = atomicAdd(&cur[d], 1);
    eid[off[d] + p] = e;
}

// ---------------- layer-3 tiny GEMM (BN inline, fp32) ----------------
__global__ __launch_bounds__(128) void k_gemm_small(
    const float* __restrict__ h, const float* __restrict__ scale,
    const float* __restrict__ shift,
    const float* __restrict__ lw, const float* __restrict__ wg,
    float* __restrict__ lin, float* __restrict__ hg)
{
    int n = blockIdx.x, t = threadIdx.x;
    const float* hr = h + (size_t)n * HIDD;
    float a0 = 0, a1 = 0, a2 = 0, a3 = 0;
    for (int k = t; k < HIDD; k += 128) {
        float a = hr[k] * scale[k] + shift[k];
        a0 += a * lw[k * 2];
        a1 += a * lw[k * 2 + 1];
        a2 += a * wg[k * 2];
        a3 += a * wg[k * 2 + 1];
    }
#pragma unroll
    for (int s = 16; s; s >>= 1) {
        a0 += __shfl_down_sync(0xFFFFFFFFu, a0, s);
        a1 += __shfl_down_sync(0xFFFFFFFFu, a1, s);
        a2 += __shfl_down_sync(0xFFFFFFFFu, a2, s);
        a3 += __shfl_down_sync(0xFFFFFFFFu, a3, s);
    }
    __shared__ float sm[4][4];
    if ((t & 31) == 0) {
        sm[t >> 5][0] = a0; sm[t >> 5][1] = a1; sm[t >> 5][2] = a2; sm[t >> 5][3] = a3;
    }
    __syncthreads();
    if (t == 0) {
        lin[(size_t)n * 2]     = sm[0][0] + sm[1][0] + sm[2][0] + sm[3][0];
        lin[(size_t)n * 2 + 1] = sm[0][1] + sm[1][1] + sm[2][1] + sm[3][1];
        hg [(size_t)n * 2]     = sm[0][2] + sm[1][2] + sm[2][2] + sm[3][2];
        hg [(size_t)n * 2 + 1] = sm[0][3] + sm[1][3] + sm[2][3] + sm[3][3];
    }
}

// ---------------- GAT pieces ----------------
__global__ void k_ve(const float* __restrict__ We, const float* __restrict__ attn,
                     float* __restrict__ ve, int H, int O) {
    int t = threadIdx.x;
    if (t >= H * EDK) return;
    int h = t / EDK, k = t % EDK;
    const float* a2 = attn + (size_t)(2 * H + h) * O;
    const float* w = We + (size_t)k * H * O + (size_t)h * O;
    float s = 0.f;
    for (int d = 0; d < O; d++) s += w[d] * a2[d];
    ve[k * H + h] = s;
}

__global__ void k_sdots(const float* __restrict__ hg, const float* __restrict__ attn,
                        float* __restrict__ ssrc, float* __restrict__ sdst, int H, int O) {
    int gw = (blockIdx.x * blockDim.x + threadIdx.x) >> 5;
    int lane = threadIdx.x & 31;
    if (gw >= NN * H) return;
    int n = gw / H, h = gw % H;
    const float* hr = hg + (size_t)n * H * O + (size_t)h * O;
    const float* a0 = attn + (size_t)h * O;
    const float* a1 = attn + (size_t)(H + h) * O;
    float d0 = 0.f, d1 = 0.f;
    for (int d = lane; d < O; d += 32) {
        float v = hr[d];
        d0 += v * a0[d];
        d1 += v * a1[d];
    }
#pragma unroll
    for (int s = 16; s; s >>= 1) {
        d0 += __shfl_down_sync(0xFFFFFFFFu, d0, s);
        d1 += __shfl_down_sync(0xFFFFFFFFu, d1, s);
    }
    if (lane == 0) { ssrc[gw] = d0; sdst[gw] = d1; }
}

// fused logits + softmax, H=4 (thread per dst node)
__global__ __launch_bounds__(256) void k_attn4(
    const int* __restrict__ off, const int* __restrict__ eid,
    const int* __restrict__ ei, const float* __restrict__ ea,
    const float* __restrict__ ssrc, const float* __restrict__ sdst,
    const float* __restrict__ ve, const float* __restrict__ at,
    float4* __restrict__ w4)
{
    __shared__ float sve[EDK * 4];
    __shared__ float sat[4];
    if (threadIdx.x < EDK * 4) sve[threadIdx.x] = ve[threadIdx.x];
    if (threadIdx.x < 4) sat[threadIdx.x] = at[threadIdx.x];
    __syncthreads();
    int n = blockIdx.x * blockDim.x + threadIdx.x;
    if (n >= NN) return;
    int d0 = off[n], d1 = off[n + 1];
    if (d0 == d1) return;
    float4 sd = *(const float4*)(sdst + (size_t)n * 4);
    float4 m = make_float4(-INFINITY, -INFINITY, -INFINITY, -INFINITY);
    for (int i = d0; i < d1; i++) {
        int e = eid[i];
        int s = ei[e];
        float4 ss = *(const float4*)(ssrc + (size_t)s * 4);
        const float4* row = (const float4*)(ea + (size_t)e * EAC);
        float4 r0 = row[0], r1 = row[1], r2 = row[2];
        float t = r0.x;
        float ef[10] = {r0.y, r0.z, r0.w, r1.x, r1.y, r1.z, r1.w, r2.x, r2.y, r2.z};
        float4 l;
        float* lp = (float*)&l;
#pragma unroll
        for (int h = 0; h < 4; h++) {
            float se = 0.f;
#pragma unroll
            for (int k = 0; k < EDK; k++) se += ef[k] * sve[k * 4 + h];
            float v = ((float*)&ss)[h] + ((float*)&sd)[h] + se + t * sat[h];
            lp[h] = (v > 0.f) ? v : 0.2f * v;
        }
        w4[e] = l;
        m.x = fmaxf(m.x, l.x); m.y = fmaxf(m.y, l.y);
        m.z = fmaxf(m.z, l.z); m.w = fmaxf(m.w, l.w);
    }
    float4 s = make_float4(0.f, 0.f, 0.f, 0.f);
    for (int i = d0; i < d1; i++) {
        float4 v = w4[eid[i]];
        v.x = expf(v.x - m.x); v.y = expf(v.y - m.y);
        v.z = expf(v.z - m.z); v.w = expf(v.w - m.w);
        w4[eid[i]] = v;
        s.x += v.x; s.y += v.y; s.z += v.z; s.w += v.w;
    }
    float4 inv = make_float4(1.f / (s.x + 1e-16f), 1.f / (s.y + 1e-16f),
                             1.f / (s.z + 1e-16f), 1.f / (s.w + 1e-16f));
    for (int i = d0; i < d1; i++) {
        float4 v = w4[eid[i]];
        v.x *= inv.x; v.y *= inv.y; v.z *= inv.z; v.w *= inv.w;
        w4[eid[i]] = v;
    }
}

// fused logits + softmax, H=1
__global__ __launch_bounds__(256) void k_attn1(
    const int* __restrict__ off, const int* __restrict__ eid,
    const int* __restrict__ ei, const float* __restrict__ ea,
    const float* __restrict__ ssrc, const float* __restrict__ sdst,
    const float* __restrict__ ve, const float* __restrict__ at,
    float* __restrict__ logw)
{
    __shared__ float sve[EDK];
    __shared__ float sat0;
    if (threadIdx.x < EDK) sve[threadIdx.x] = ve[threadIdx.x];
    if (threadIdx.x == 0) sat0 = at[0];
    __syncthreads();
    int n = blockIdx.x * blockDim.x + threadIdx.x;
    if (n >= NN) return;
    int d0 = off[n], d1 = off[n + 1];
    if (d0 == d1) return;
    float sd = sdst[n];
    float m = -INFINITY;
    for (int i = d0; i < d1; i++) {
        int e = eid[i];
        int s = ei[e];
        const float4* row = (const float4*)(ea + (size_t)e * EAC);
        float4 r0 = row[0], r1 = row[1], r2 = row[2];
        float t = r0.x;
        float ef[10] = {r0.y, r0.z, r0.w, r1.x, r1.y, r1.z, r1.w, r2.x, r2.y, r2.z};
        float se = 0.f;
#pragma unroll
        for (int k = 0; k < EDK; k++) se += ef[k] * sve[k];
        float v = ssrc[s] + sd + se + t * sat0;
        v = (v > 0.f) ? v : 0.2f * v;
        logw[e] = v;
        m = fmaxf(m, v);
    }
    float s = 0.f;
    for (int i = d0; i < d1; i++) {
        float p = expf(logw[eid[i]] - m);
        logw[eid[i]] = p;
        s += p;
    }
    float inv = 1.f / (s + 1e-16f);
    for (int i = d0; i < d1; i++) logw[eid[i]] *= inv;
}

__global__ __launch_bounds__(256) void k_agg_big(
    const float* __restrict__ hg, const float* __restrict__ w,
    const int* __restrict__ off, const int* __restrict__ eid,
    const float* __restrict__ ea, const int* __restrict__ src,
    const float* __restrict__ We, const float* __restrict__ lin,
    const float* __restrict__ lb, const float* __restrict__ cb,
    float* __restrict__ out)
{
    int n = blockIdx.x;
    int t = threadIdx.x;
    __shared__ float qs[40];
    if (t < 40) qs[t] = 0.f;
    float acc0 = 0.f, acc1 = 0.f, acc2 = 0.f, acc3 = 0.f;
    int d0 = off[n], d1 = off[n + 1];
    for (int i = d0; i < d1; i++) {
        int e = eid[i];
        int s = src[e];
        float4 wv = *(const float4*)(w + (size_t)e * 4);
        const float* hr = hg + (size_t)s * 1024;
        acc0 += wv.x * hr[t];
        acc1 += wv.y * hr[t + 256];
        acc2 += wv.z * hr[t + 512];
        acc3 += wv.w * hr[t + 768];
        if (t < 40) {
            int h = t / 10, k = t % 10;
            float wh = (h == 0) ? wv.x : (h == 1) ? wv.y : (h == 2) ? wv.z : wv.w;
            qs[t] += wh * ea[(size_t)e * EAC + 1 + k];
        }
    }
    __syncthreads();
    float acch[4] = {acc0, acc1, acc2, acc3};
#pragma unroll
    for (int h = 0; h < 4; h++) {
        int f = h * 256 + t;
        float et = 0.f;
#pragma unroll
        for (int k = 0; k < 10; k++) et += qs[h * 10 + k] * We[k * 1024 + f];
        float v = lin[(size_t)n * 1024 + f] + lb[f] + cb[f] + acch[h] + et;
        out[(size_t)n * 1024 + f] = fmaxf(v, 0.f);
    }
}

__global__ void k_agg_small(
    const float* __restrict__ hg, const float* __restrict__ w,
    const int* __restrict__ off, const int* __restrict__ eid,
    const float* __restrict__ ea, const int* __restrict__ src,
    const float* __restrict__ We, const float* __restrict__ lin,
    const float* __restrict__ lb, const float* __restrict__ cb,
    float* __restrict__ out)
{
    int n = blockIdx.x * blockDim.x + threadIdx.x;
    if (n >= NN) return;
    float a0 = 0.f, a1 = 0.f;
    float q[10];
#pragma unroll
    for (int k = 0; k < 10; k++) q[k] = 0.f;
    int d0 = off[n], d1 = off[n + 1];
    for (int i = d0; i < d1; i++) {
        int e = eid[i];
        int s = src[e];
        float wv = w[e];
        a0 += wv * hg[(size_t)s * 2];
        a1 += wv * hg[(size_t)s * 2 + 1];
        const float* row = ea + (size_t)e * EAC;
#pragma unroll
        for (int k = 0; k < 10; k++) q[k] += wv * row[1 + k];
    }
    float e0 = 0.f, e1 = 0.f;
#pragma unroll
    for (int k = 0; k < 10; k++) { e0 += q[k] * We[k * 2]; e1 += q[k] * We[k * 2 + 1]; }
    float v0 = lin[(size_t)n * 2] + lb[0] + cb[0] + a0 + e0;
    float v1 = lin[(size_t)n * 2 + 1] + lb[1] + cb[1] + a1 + e1;
    out[(size_t)n * 2] = fmaxf(v0, 0.f);
    out[(size_t)n * 2 + 1] = fmaxf(v1, 0.f);
}

// ---------------- host driver ----------------
static inline int cdiv(int a, int b) { return (a + b - 1) / b; }

struct Scratch {
    float *lin, *hg, *h, *logw, *ssrc, *sdst, *scale, *shift, *ve, *p1, *p2;
    int *deg, *off, *cur, *eid;
    __half *Ah, *B1h, *B1l, *B2h, *B2l;
};

extern "C" void kernel_launch(void* const* d_in, const int* in_sizes, int n_in,
                              void* d_out, int out_size)
{
    const float* x  = (const float*)d_in[0];
    const int*   ei = (const int*)d_in[1];
    const float* ea = (const float*)d_in[2];

    const float *Wg[3], *We[3], *attn[3], *at[3], *cb[3];
    const float *lw[3], *lb[3], *gg[3], *bb[3];

    if (in_sizes[8] == 1048576) {
        for (int i = 0; i < 3; i++) {
            Wg[i]   = (const float*)d_in[3 + 5 * i];
            We[i]   = (const float*)d_in[4 + 5 * i];
            attn[i] = (const float*)d_in[5 + 5 * i];
            at[i]   = (const float*)d_in[6 + 5 * i];
            cb[i]   = (const float*)d_in[7 + 5 * i];
            lw[i]   = (const float*)d_in[18 + 4 * i];
            lb[i]   = (const float*)d_in[19 + 4 * i];
            gg[i]   = (const float*)d_in[20 + 4 * i];
            bb[i]   = (const float*)d_in[21 + 4 * i];
        }
    } else {
        for (int i = 0; i < 3; i++) {
            Wg[i]   = (const float*)d_in[3 + 9 * i];
            We[i]   = (const float*)d_in[4 + 9 * i];
            attn[i] = (const float*)d_in[5 + 9 * i];
            at[i]   = (const float*)d_in[6 + 9 * i];
            cb[i]   = (const float*)d_in[7 + 9 * i];
            lw[i]   = (const float*)d_in[8 + 9 * i];
            lb[i]   = (const float*)d_in[9 + 9 * i];
            gg[i]   = (const float*)d_in[10 + 9 * i];
            bb[i]   = (const float*)d_in[11 + 9 * i];
        }
    }

    Scratch S;
    cudaGetSymbolAddress((void**)&S.lin, g_lin);
    cudaGetSymbolAddress((void**)&S.hg, g_hg);
    cudaGetSymbolAddress((void**)&S.h, g_h);
    cudaGetSymbolAddress((void**)&S.logw, g_logw);
    cudaGetSymbolAddress((void**)&S.ssrc, g_ssrc);
    cudaGetSymbolAddress((void**)&S.sdst, g_sdst);
    cudaGetSymbolAddress((void**)&S.p1, g_part1);
    cudaGetSymbolAddress((void**)&S.p2, g_part2);
    cudaGetSymbolAddress((void**)&S.scale, g_scale);
    cudaGetSymbolAddress((void**)&S.shift, g_shift);
    cudaGetSymbolAddress((void**)&S.ve, g_ve);
    cudaGetSymbolAddress((void**)&S.deg, g_deg);
    cudaGetSymbolAddress((void**)&S.off, g_off);
    cudaGetSymbolAddress((void**)&S.cur, g_cur);
    cudaGetSymbolAddress((void**)&S.eid, g_eid);
    cudaGetSymbolAddress((void**)&S.Ah, g_Ah);
    cudaGetSymbolAddress((void**)&S.B1h, g_B1h);
    cudaGetSymbolAddress((void**)&S.B1l, g_B1l);
    cudaGetSymbolAddress((void**)&S.B2h, g_B2h);
    cudaGetSymbolAddress((void**)&S.B2l, g_B2l);

    cudaFuncSetAttribute(gemm_mma, cudaFuncAttributeMaxDynamicSharedMemorySize, GT_SMEM);

    // ======== layer 1 ========
    {
        int F = F1, Kp = 192;
        k_bnstat<<<dim3(cdiv(F, 256), BNCH), 256>>>(x, S.p1, S.p2, F);
        k_bnfin<<<cdiv(F, 256), 256>>>(S.p1, S.p2, gg[0], bb[0], S.scale, S.shift, F);
        size_t tp = (size_t)NN * Kp + (size_t)NN * 8;
        k_prep<<<(int)((tp + 255) / 256), 256>>>(x, S.scale, S.shift, S.Ah, S.ssrc, S.sdst, F, Kp);
        k_prepB_t<<<dim3(Kp / 32, 32, 2), dim3(32, 8)>>>(lw[0], Wg[0], S.B1h, S.B1l, S.B2h, S.B2l, F, Kp);
        gemm_mma<<<dim3(16, cdiv(NN, 128)), 256, GT_SMEM>>>(
            S.Ah, Kp, S.B1h, S.B1l, S.B2h, S.B2l, S.lin, S.hg, NN,
            attn[0], S.ssrc, S.sdst);
        k_init<<<cdiv(NN, 256), 256>>>(S.deg, S.cur);
        k_hist<<<cdiv(EE, 256), 256>>>(ei + EE, S.deg);
        k_scan<<<1, 1024>>>(S.deg, S.off, NN);
        k_scatter<<<cdiv(EE, 256), 256>>>(ei + EE, S.off, S.cur, S.eid);
        k_ve<<<1, 64>>>(We[0], attn[0], S.ve, 4, 256);
        k_attn4<<<cdiv(NN, 256), 256>>>(S.off, S.eid, ei, ea, S.ssrc, S.sdst, S.ve, at[0], (float4*)S.logw);
        k_agg_big<<<NN, 256>>>(S.hg, S.logw, S.off, S.eid, ea, ei, We[0], S.lin, lb[0], cb[0], S.h);
    }
    // ======== layer 2 ========
    {
        int F = HIDD, Kp = HIDD;
        k_bnstat<<<dim3(cdiv(F, 256), BNCH), 256>>>(S.h, S.p1, S.p2, F);
        k_bnfin<<<cdiv(F, 256), 256>>>(S.p1, S.p2, gg[1], bb[1], S.scale, S.shift, F);
        size_t tp = (size_t)NN * Kp + (size_t)NN * 8;
        k_prep<<<(int)((tp + 255) / 256), 256>>>(S.h, S.scale, S.shift, S.Ah, S.ssrc, S.sdst, F, Kp);
        k_prepB_t<<<dim3(Kp / 32, 32, 2), dim3(32, 8)>>>(lw[1], Wg[1], S.B1h, S.B1l, S.B2h, S.B2l, F, Kp);
        gemm_mma<<<dim3(16, cdiv(NN, 128)), 256, GT_SMEM>>>(
            S.Ah, Kp, S.B1h, S.B1l, S.B2h, S.B2l, S.lin, S.hg, NN,
            attn[1], S.ssrc, S.sdst);
        k_ve<<<1, 64>>>(We[1], attn[1], S.ve, 4, 256);
        k_attn4<<<cdiv(NN, 256), 256>>>(S.off, S.eid, ei, ea, S.ssrc, S.sdst, S.ve, at[1], (float4*)S.logw);
        k_agg_big<<<NN, 256>>>(S.hg, S.logw, S.off, S.eid, ea, ei, We[1], S.lin, lb[1], cb[1], S.h);
    }
    // ======== layer 3 ========
    {
        k_bnstat<<<dim3(cdiv(HIDD, 256), BNCH), 256>>>(S.h, S.p1, S.p2, HIDD);
        k_bnfin<<<cdiv(HIDD, 256), 256>>>(S.p1, S.p2, gg[2], bb[2], S.scale, S.shift, HIDD);
        k_gemm_small<<<NN, 128>>>(S.h, S.scale, S.shift, lw[2], Wg[2], S.lin, S.hg);
        k_ve<<<1, 64>>>(We[2], attn[2], S.ve, 1, 2);
        k_sdots<<<cdiv(NN * 1 * 32, 256), 256>>>(S.hg, attn[2], S.ssrc, S.sdst, 1, 2);
        k_attn1<<<cdiv(NN, 256), 256>>>(S.off, S.eid, ei, ea, S.ssrc, S.sdst, S.ve, at[2], S.logw);
        k_agg_small<<<cdiv(NN, 256), 256>>>(S.hg, S.logw, S.off, S.eid, ea, ei, We[2], S.lin, lb[2], cb[2], (float*)d_out);
    }
}

// round 14
// speedup vs baseline: 1.2513x; 1.0356x over previous
#include <cuda_runtime.h>
#include <cuda_bf16.h>
#include <cuda_fp16.h>
#include <cstdint>
#include <math.h>

#define NN   20000
#define EE   100000
#define F1   167
#define HIDD 1024
#define EDK  10
#define EAC  12
#define BNCH 40

// ---------------- scratch (device globals) ----------------
__device__ float g_lin[(size_t)NN * HIDD];
__device__ __half g_hg[(size_t)NN * HIDD];
__device__ float g_hg3[(size_t)NN * 2];
__device__ float g_h  [(size_t)NN * HIDD];
__device__ float g_logw[(size_t)EE * 4];
__device__ float g_ssrc[(size_t)NN * 4];
__device__ float g_sdst[(size_t)NN * 4];
__device__ float g_part1[BNCH * HIDD];
__device__ float g_part2[BNCH * HIDD];
__device__ float g_scale[HIDD];
__device__ float g_shift[HIDD];
__device__ float g_ve[EDK * 4];
__device__ int   g_deg[NN];
__device__ int   g_off[NN + 1];
__device__ int   g_cur[NN];
__device__ int   g_eid[EE];
__device__ __half g_Ah[(size_t)NN * HIDD];
__device__ __half g_B1h[(size_t)HIDD * HIDD];
__device__ __half g_B1l[(size_t)HIDD * HIDD];
__device__ __half g_B2h[(size_t)HIDD * HIDD];
__device__ __half g_B2l[(size_t)HIDD * HIDD];

// ---------------- BatchNorm: partials ----------------
__global__ void k_bnstat(const float* __restrict__ x, float* __restrict__ p1,
                         float* __restrict__ p2, int F) {
    int c = blockIdx.x * blockDim.x + threadIdx.x;
    if (c >= F) return;
    int chunk = (NN + BNCH - 1) / BNCH;
    int r0 = blockIdx.y * chunk;
    int r1 = r0 + chunk; if (r1 > NN) r1 = NN;
    float a = 0.f, b = 0.f;
    for (int r = r0; r < r1; r++) {
        float v = x[(size_t)r * F + c];
        a += v; b += v * v;
    }
    p1[blockIdx.y * F + c] = a;
    p2[blockIdx.y * F + c] = b;
}

__global__ void k_bnfin(const float* __restrict__ p1, const float* __restrict__ p2,
                        const float* __restrict__ g, const float* __restrict__ b,
                        float* __restrict__ scale, float* __restrict__ shift, int F) {
    int c = blockIdx.x * blockDim.x + threadIdx.x;
    if (c >= F) return;
    float a = 0.f, s = 0.f;
    for (int y = 0; y < BNCH; y++) { a += p1[y * F + c]; s += p2[y * F + c]; }
    float invN = 1.f / (float)NN;
    float mu = a * invN;
    float var = s * invN - mu * mu;
    float rstd = rsqrtf(var + 1e-5f);
    float sc = rstd * g[c];
    scale[c] = sc;
    shift[c] = b[c] - mu * sc;
}

// ---------------- prep A (fp16, BN fused) + zero ssrc/sdst ----------------
__global__ void k_prep(const float* __restrict__ x, const float* __restrict__ scale,
                       const float* __restrict__ shift, __half* __restrict__ Ah,
                       float* __restrict__ ssrc, float* __restrict__ sdst,
                       int F, int Kp) {
    size_t na = (size_t)NN * Kp;
    size_t i = (size_t)blockIdx.x * blockDim.x + threadIdx.x;
    if (i < na) {
        int m = (int)(i / Kp), k = (int)(i % Kp);
        float v = 0.f;
        if (k < F) v = x[(size_t)m * F + k] * scale[k] + shift[k];
        Ah[i] = __float2half_rn(v);
    } else if (i < na + (size_t)NN * 4) {
        ssrc[i - na] = 0.f;
    } else if (i < na + (size_t)NN * 8) {
        sdst[i - na - (size_t)NN * 4] = 0.f;
    }
}

// ---------------- prep B: coalesced transpose + fp16 split ----------------
__global__ void k_prepB_t(const float* __restrict__ W1, const float* __restrict__ W2,
                          __half* __restrict__ B1h, __half* __restrict__ B1l,
                          __half* __restrict__ B2h, __half* __restrict__ B2l,
                          int F, int Kp) {
    __shared__ float tile[32][33];
    const float* W = blockIdx.z ? W2 : W1;
    __half* Bh = blockIdx.z ? B2h : B1h;
    __half* Bl = blockIdx.z ? B2l : B1l;
    int k0 = blockIdx.x * 32, n0 = blockIdx.y * 32;
    int tx = threadIdx.x, ty = threadIdx.y;
#pragma unroll
    for (int r = ty; r < 32; r += 8) {
        int k = k0 + r;
        tile[r][tx] = (k < F) ? W[(size_t)k * HIDD + n0 + tx] : 0.f;
    }
    __syncthreads();
#pragma unroll
    for (int r = ty; r < 32; r += 8) {
        int n = n0 + r, k = k0 + tx;
        float v = tile[tx][r];
        __half h = __float2half_rn(v);
        Bh[(size_t)n * Kp + k] = h;
        Bl[(size_t)n * Kp + k] = __float2half_rn(v - __half2float(h));
    }
}

// ---------------- mma.sync helpers ----------------
__device__ __forceinline__ uint32_t smem_u32(const void* p) {
    uint32_t a;
    asm("{ .reg .u64 t; cvta.to.shared.u64 t, %1; cvt.u32.u64 %0, t; }" : "=r"(a) : "l"(p));
    return a;
}
__device__ __forceinline__ void sts128(uint32_t addr, uint4 v) {
    asm volatile("st.shared.v4.b32 [%0], {%1,%2,%3,%4};"
                 :: "r"(addr), "r"(v.x), "r"(v.y), "r"(v.z), "r"(v.w) : "memory");
}
__device__ __forceinline__ void cpasync16(uint32_t s, const void* g) {
    asm volatile("cp.async.cg.shared.global [%0], [%1], 16;" :: "r"(s), "l"(g));
}
#define CP_COMMIT() asm volatile("cp.async.commit_group;" ::: "memory")
#define CP_WAIT0()  asm volatile("cp.async.wait_group 0;" ::: "memory")
#define SWZ(x) ((x) ^ (((x) >> 3) & 0x70))

#define LDSM4(r0, r1, r2, r3, addr) \
    asm volatile("ldmatrix.sync.aligned.m8n8.x4.shared.b16 {%0,%1,%2,%3}, [%4];" \
                 : "=r"(r0), "=r"(r1), "=r"(r2), "=r"(r3) : "r"(addr))

#define MMA_F16(d, a0, a1, a2, a3, b0, b1) \
    asm volatile("mma.sync.aligned.m16n8k16.row.col.f32.f16.f16.f32 " \
                 "{%0,%1,%2,%3}, {%4,%5,%6,%7}, {%8,%9}, {%0,%1,%2,%3};" \
                 : "+f"((d)[0]), "+f"((d)[1]), "+f"((d)[2]), "+f"((d)[3]) \
                 : "r"(a0), "r"(a1), "r"(a2), "r"(a3), "r"(b0), "r"(b1))

// ---------------- fp16 2-pass GEMM: 128x128 tile, K-chunk 64, 2-stage, 2 CTA/SM --
// nt 0-7 -> C1 (lin, fp32); nt 8-15 -> C2 (hg, fp16) + fused attn dots.
#define STAGE_BYTES 49152   // Ah 16K | Bh 16K | Bl 16K  (128B rows, SW128)
#define GT_SMEM (2 * STAGE_BYTES + 512)

__global__ __launch_bounds__(256, 2) void gemm_mma(
    const __half* __restrict__ Ah, int Kp,
    const __half* __restrict__ B1h, const __half* __restrict__ B1l,
    const __half* __restrict__ B2h, const __half* __restrict__ B2l,
    float* __restrict__ C1, __half* __restrict__ C2, int M,
    const float* __restrict__ attn, float* __restrict__ ssrc, float* __restrict__ sdst)
{
    extern __shared__ char smraw[];
    uint32_t sb = (smem_u32(smraw) + 255) & ~255u;
    int tid = threadIdx.x, lane = tid & 31, wid = tid >> 5;
    int nt = blockIdx.x, mt = blockIdx.y;

    const __half *Bh, *Bl;
    int coloff;
    if (nt < 8) { Bh = B1h; Bl = B1l; coloff = nt * 128; }
    else        { Bh = B2h; Bl = B2l; coloff = (nt - 8) * 128; }

    int wm = wid & 1, wn = wid >> 1;   // 2 x 4 warp grid; warp tile 64x32

    float acc[4][4][4];
#pragma unroll
    for (int a = 0; a < 4; a++)
#pragma unroll
        for (int b = 0; b < 4; b++)
#pragma unroll
            for (int cc = 0; cc < 4; cc++) acc[a][b][cc] = 0.f;

    // raw (un-swizzled) ldmatrix base offsets within a 16KB (128 x 128B) region
    uint32_t rawA[4];   // [mi]
    uint32_t rawB[2];   // [pp]
#pragma unroll
    for (int mi = 0; mi < 4; mi++) {
        int row = wm * 64 + mi * 16 + (lane & 15);
        rawA[mi] = (uint32_t)(row * 128 + (lane >> 4) * 16);
    }
#pragma unroll
    for (int p = 0; p < 2; p++) {
        int row = wn * 32 + p * 16 + ((lane >> 4) << 3) + (lane & 7);
        rawB[p] = (uint32_t)(row * 128 + (((lane >> 3) & 1) << 4));
    }

    int q = tid & 7;          // 16B segment within 128B row
    int rr = tid >> 3;        // 0..31
    int chunks = Kp >> 6;     // K-chunk = 64

    auto load_stage = [&](int c) {
        uint32_t base = sb + (uint32_t)(c & 1) * STAGE_BYTES;
        uint32_t bAh = base, bBh = base + 16384, bBl = base + 32768;
        size_t kel = (size_t)c * 64 + q * 8;
#pragma unroll
        for (int i = 0; i < 4; i++) {
            int row = rr + i * 32;
            uint32_t soff = SWZ((uint32_t)(row * 128 + q * 16));
            int m = mt * 128 + row;
            if (m < M) {
                cpasync16(bAh + soff, Ah + (size_t)m * Kp + kel);
            } else {
                uint4 z = make_uint4(0, 0, 0, 0);
                sts128(bAh + soff, z);
            }
            int nr = coloff + row;
            cpasync16(bBh + soff, Bh + (size_t)nr * Kp + kel);
            cpasync16(bBl + soff, Bl + (size_t)nr * Kp + kel);
        }
        CP_COMMIT();
    };

    load_stage(0);

    for (int c = 0; c < chunks; c++) {
        CP_WAIT0();
        __syncthreads();
        if (c + 1 < chunks) load_stage(c + 1);

        uint32_t cur = sb + (uint32_t)(c & 1) * STAGE_BYTES;
        uint32_t cAh = cur, cBh = cur + 16384, cBl = cur + 32768;
#pragma unroll
        for (int k16 = 0; k16 < 4; k16++) {
            uint32_t kb = (uint32_t)k16 * 32;
            uint32_t af0[4], af1[4], af2[4], af3[4];
#pragma unroll
            for (int mi = 0; mi < 4; mi++)
                LDSM4(af0[mi], af1[mi], af2[mi], af3[mi], cAh + SWZ(rawA[mi] + kb));
            uint32_t bh0[4], bh1[4], bl0[4], bl1[4];
#pragma unroll
            for (int pp = 0; pp < 2; pp++) {
                uint32_t addr = SWZ(rawB[pp] + kb);
                uint32_t r0_, r1_, r2_, r3_;
                LDSM4(r0_, r1_, r2_, r3_, cBh + addr);
                bh0[pp * 2] = r0_; bh1[pp * 2] = r1_;
                bh0[pp * 2 + 1] = r2_; bh1[pp * 2 + 1] = r3_;
                LDSM4(r0_, r1_, r2_, r3_, cBl + addr);
                bl0[pp * 2] = r0_; bl1[pp * 2] = r1_;
                bl0[pp * 2 + 1] = r2_; bl1[pp * 2 + 1] = r3_;
            }
#pragma unroll
            for (int mi = 0; mi < 4; mi++)
#pragma unroll
                for (int ni = 0; ni < 4; ni++)
                    MMA_F16(acc[mi][ni], af0[mi], af1[mi], af2[mi], af3[mi], bh0[ni], bh1[ni]);
#pragma unroll
            for (int mi = 0; mi < 4; mi++)
#pragma unroll
                for (int ni = 0; ni < 4; ni++)
                    MMA_F16(acc[mi][ni], af0[mi], af1[mi], af2[mi], af3[mi], bl0[ni], bl1[ni]);
        }
    }

    // epilogue
    int doAttn = (nt >= 8);
    int hh = (coloff >> 8) & 3;
    int hcbase = coloff & 255;
    const float* a0p = attn + (size_t)hh * 256;
    const float* a1p = attn + (size_t)(4 + hh) * 256;
#pragma unroll
    for (int mi = 0; mi < 4; mi++) {
        int gr = mt * 128 + wm * 64 + mi * 16 + (lane >> 2);
        float s0 = 0.f, d0 = 0.f, s1 = 0.f, d1 = 0.f;
#pragma unroll
        for (int ni = 0; ni < 4; ni++) {
            int cl = wn * 32 + ni * 8 + ((lane & 3) << 1);
            int gc = coloff + cl;
            if (!doAttn) {
                if (gr < M)
                    *(float2*)(C1 + (size_t)gr * HIDD + gc) = make_float2(acc[mi][ni][0], acc[mi][ni][1]);
                if (gr + 8 < M)
                    *(float2*)(C1 + (size_t)(gr + 8) * HIDD + gc) = make_float2(acc[mi][ni][2], acc[mi][ni][3]);
            } else {
                if (gr < M)
                    *(__half2*)(C2 + (size_t)gr * HIDD + gc) =
                        __floats2half2_rn(acc[mi][ni][0], acc[mi][ni][1]);
                if (gr + 8 < M)
                    *(__half2*)(C2 + (size_t)(gr + 8) * HIDD + gc) =
                        __floats2half2_rn(acc[mi][ni][2], acc[mi][ni][3]);
                int cw = hcbase + cl;
                float2 av = *(const float2*)(a0p + cw);
                float2 bv = *(const float2*)(a1p + cw);
                s0 += acc[mi][ni][0] * av.x + acc[mi][ni][1] * av.y;
                d0 += acc[mi][ni][0] * bv.x + acc[mi][ni][1] * bv.y;
                s1 += acc[mi][ni][2] * av.x + acc[mi][ni][3] * av.y;
                d1 += acc[mi][ni][2] * bv.x + acc[mi][ni][3] * bv.y;
            }
        }
        if (doAttn) {
#pragma unroll
            for (int o = 1; o < 4; o <<= 1) {
                s0 += __shfl_xor_sync(0xFFFFFFFFu, s0, o);
                d0 += __shfl_xor_sync(0xFFFFFFFFu, d0, o);
                s1 += __shfl_xor_sync(0xFFFFFFFFu, s1, o);
                d1 += __shfl_xor_sync(0xFFFFFFFFu, d1, o);
            }
            if ((lane & 3) == 0) {
                if (gr < M) {
                    atomicAdd(&ssrc[gr * 4 + hh], s0);
                    atomicAdd(&sdst[gr * 4 + hh], d0);
                }
                if (gr + 8 < M) {
                    atomicAdd(&ssrc[(gr + 8) * 4 + hh], s1);
                    atomicAdd(&sdst[(gr + 8) * 4 + hh], d1);
                }
            }
        }
    }
}

// ---------------- CSR build ----------------
__global__ void k_init(int* deg, int* cur) {
    int i = blockIdx.x * blockDim.x + threadIdx.x;
    if (i < NN) { deg[i] = 0; cur[i] = 0; }
}
__global__ void k_hist(const int* __restrict__ dst, int* __restrict__ deg) {
    int e = blockIdx.x * blockDim.x + threadIdx.x;
    if (e < EE) atomicAdd(&deg[dst[e]], 1);
}
__global__ void k_scan(const int* __restrict__ deg, int* __restrict__ off, int n) {
    __shared__ int sh[1024];
    __shared__ int carry;
    int t = threadIdx.x;
    if (t == 0) { carry = 0; off[0] = 0; }
    __syncthreads();
    for (int base = 0; base < n; base += 1024) {
        int v = (base + t < n) ? deg[base + t] : 0;
        sh[t] = v;
        __syncthreads();
        for (int d = 1; d < 1024; d <<= 1) {
            int add = (t >= d) ? sh[t - d] : 0;
            __syncthreads();
            sh[t] += add;
            __syncthreads();
        }
        if (base + t < n) off[base + t + 1] = carry + sh[t];
        __syncthreads();
        if (t == 0) carry += sh[1023];
        __syncthreads();
    }
}
__global__ void k_scatter(const int* __restrict__ dst, const int* __restrict__ off,
                          int* __restrict__ cur, int* __restrict__ eid) {
    int e = blockIdx.x * blockDim.x + threadIdx.x;
    if (e >= EE) return;
    int d = dst[e];
    int p = atomicAdd(&cur[d], 1);
    eid[off[d] + p] = e;
}

// ---------------- layer-3 tiny GEMM (BN inline, fp32) ----------------
__global__ __launch_bounds__(128) void k_gemm_small(
    const float* __restrict__ h, const float* __restrict__ scale,
    const float* __restrict__ shift,
    const float* __restrict__ lw, const float* __restrict__ wg,
    float* __restrict__ lin, float* __restrict__ hg3)
{
    int n = blockIdx.x, t = threadIdx.x;
    const float* hr = h + (size_t)n * HIDD;
    float a0 = 0, a1 = 0, a2 = 0, a3 = 0;
    for (int k = t; k < HIDD; k += 128) {
        float a = hr[k] * scale[k] + shift[k];
        a0 += a * lw[k * 2];
        a1 += a * lw[k * 2 + 1];
        a2 += a * wg[k * 2];
        a3 += a * wg[k * 2 + 1];
    }
#pragma unroll
    for (int s = 16; s; s >>= 1) {
        a0 += __shfl_down_sync(0xFFFFFFFFu, a0, s);
        a1 += __shfl_down_sync(0xFFFFFFFFu, a1, s);
        a2 += __shfl_down_sync(0xFFFFFFFFu, a2, s);
        a3 += __shfl_down_sync(0xFFFFFFFFu, a3, s);
    }
    __shared__ float sm[4][4];
    if ((t & 31) == 0) {
        sm[t >> 5][0] = a0; sm[t >> 5][1] = a1; sm[t >> 5][2] = a2; sm[t >> 5][3] = a3;
    }
    __syncthreads();
    if (t == 0) {
        lin[(size_t)n * 2]     = sm[0][0] + sm[1][0] + sm[2][0] + sm[3][0];
        lin[(size_t)n * 2 + 1] = sm[0][1] + sm[1][1] + sm[2][1] + sm[3][1];
        hg3[(size_t)n * 2]     = sm[0][2] + sm[1][2] + sm[2][2] + sm[3][2];
        hg3[(size_t)n * 2 + 1] = sm[0][3] + sm[1][3] + sm[2][3] + sm[3][3];
    }
}

// ---------------- GAT pieces ----------------
__global__ void k_ve(const float* __restrict__ We, const float* __restrict__ attn,
                     float* __restrict__ ve, int H, int O) {
    int t = threadIdx.x;
    if (t >= H * EDK) return;
    int h = t / EDK, k = t % EDK;
    const float* a2 = attn + (size_t)(2 * H + h) * O;
    const float* w = We + (size_t)k * H * O + (size_t)h * O;
    float s = 0.f;
    for (int d = 0; d < O; d++) s += w[d] * a2[d];
    ve[k * H + h] = s;
}

// layer-3 s_src/s_dst from fp32 hg3 (O=2)
__global__ void k_sdots3(const float* __restrict__ hg3, const float* __restrict__ attn,
                         float* __restrict__ ssrc, float* __restrict__ sdst) {
    int n = blockIdx.x * blockDim.x + threadIdx.x;
    if (n >= NN) return;
    float v0 = hg3[(size_t)n * 2], v1 = hg3[(size_t)n * 2 + 1];
    ssrc[n] = v0 * attn[0] + v1 * attn[1];
    sdst[n] = v0 * attn[2] + v1 * attn[3];
}

// fused logits + softmax, H=4
__global__ __launch_bounds__(256) void k_attn4(
    const int* __restrict__ off, const int* __restrict__ eid,
    const int* __restrict__ ei, const float* __restrict__ ea,
    const float* __restrict__ ssrc, const float* __restrict__ sdst,
    const float* __restrict__ ve, const float* __restrict__ at,
    float4* __restrict__ w4)
{
    __shared__ float sve[EDK * 4];
    __shared__ float sat[4];
    if (threadIdx.x < EDK * 4) sve[threadIdx.x] = ve[threadIdx.x];
    if (threadIdx.x < 4) sat[threadIdx.x] = at[threadIdx.x];
    __syncthreads();
    int n = blockIdx.x * blockDim.x + threadIdx.x;
    if (n >= NN) return;
    int d0 = off[n], d1 = off[n + 1];
    if (d0 == d1) return;
    float4 sd = *(const float4*)(sdst + (size_t)n * 4);
    float4 m = make_float4(-INFINITY, -INFINITY, -INFINITY, -INFINITY);
    for (int i = d0; i < d1; i++) {
        int e = eid[i];
        int s = ei[e];
        float4 ss = *(const float4*)(ssrc + (size_t)s * 4);
        const float4* row = (const float4*)(ea + (size_t)e * EAC);
        float4 r0 = row[0], r1 = row[1], r2 = row[2];
        float t = r0.x;
        float ef[10] = {r0.y, r0.z, r0.w, r1.x, r1.y, r1.z, r1.w, r2.x, r2.y, r2.z};
        float4 l;
        float* lp = (float*)&l;
#pragma unroll
        for (int h = 0; h < 4; h++) {
            float se = 0.f;
#pragma unroll
            for (int k = 0; k < EDK; k++) se += ef[k] * sve[k * 4 + h];
            float v = ((float*)&ss)[h] + ((float*)&sd)[h] + se + t * sat[h];
            lp[h] = (v > 0.f) ? v : 0.2f * v;
        }
        w4[e] = l;
        m.x = fmaxf(m.x, l.x); m.y = fmaxf(m.y, l.y);
        m.z = fmaxf(m.z, l.z); m.w = fmaxf(m.w, l.w);
    }
    float4 s = make_float4(0.f, 0.f, 0.f, 0.f);
    for (int i = d0; i < d1; i++) {
        float4 v = w4[eid[i]];
        v.x = expf(v.x - m.x); v.y = expf(v.y - m.y);
        v.z = expf(v.z - m.z); v.w = expf(v.w - m.w);
        w4[eid[i]] = v;
        s.x += v.x; s.y += v.y; s.z += v.z; s.w += v.w;
    }
    float4 inv = make_float4(1.f / (s.x + 1e-16f), 1.f / (s.y + 1e-16f),
                             1.f / (s.z + 1e-16f), 1.f / (s.w + 1e-16f));
    for (int i = d0; i < d1; i++) {
        float4 v = w4[eid[i]];
        v.x *= inv.x; v.y *= inv.y; v.z *= inv.z; v.w *= inv.w;
        w4[eid[i]] = v;
    }
}

// fused logits + softmax, H=1
__global__ __launch_bounds__(256) void k_attn1(
    const int* __restrict__ off, const int* __restrict__ eid,
    const int* __restrict__ ei, const float* __restrict__ ea,
    const float* __restrict__ ssrc, const float* __restrict__ sdst,
    const float* __restrict__ ve, const float* __restrict__ at,
    float* __restrict__ logw)
{
    __shared__ float sve[EDK];
    __shared__ float sat0;
    if (threadIdx.x < EDK) sve[threadIdx.x] = ve[threadIdx.x];
    if (threadIdx.x == 0) sat0 = at[0];
    __syncthreads();
    int n = blockIdx.x * blockDim.x + threadIdx.x;
    if (n >= NN) return;
    int d0 = off[n], d1 = off[n + 1];
    if (d0 == d1) return;
    float sd = sdst[n];
    float m = -INFINITY;
    for (int i = d0; i < d1; i++) {
        int e = eid[i];
        int s = ei[e];
        const float4* row = (const float4*)(ea + (size_t)e * EAC);
        float4 r0 = row[0], r1 = row[1], r2 = row[2];
        float t = r0.x;
        float ef[10] = {r0.y, r0.z, r0.w, r1.x, r1.y, r1.z, r1.w, r2.x, r2.y, r2.z};
        float se = 0.f;
#pragma unroll
        for (int k = 0; k < EDK; k++) se += ef[k] * sve[k];
        float v = ssrc[s] + sd + se + t * sat0;
        v = (v > 0.f) ? v : 0.2f * v;
        logw[e] = v;
        m = fmaxf(m, v);
    }
    float s = 0.f;
    for (int i = d0; i < d1; i++) {
        float p = expf(logw[eid[i]] - m);
        logw[eid[i]] = p;
        s += p;
    }
    float inv = 1.f / (s + 1e-16f);
    for (int i = d0; i < d1; i++) logw[eid[i]] *= inv;
}

__global__ __launch_bounds__(256) void k_agg_big(
    const __half* __restrict__ hg, const float* __restrict__ w,
    const int* __restrict__ off, const int* __restrict__ eid,
    const float* __restrict__ ea, const int* __restrict__ src,
    const float* __restrict__ We, const float* __restrict__ lin,
    const float* __restrict__ lb, const float* __restrict__ cb,
    float* __restrict__ out)
{
    int n = blockIdx.x;
    int t = threadIdx.x;
    __shared__ float qs[40];
    if (t < 40) qs[t] = 0.f;
    float acc0 = 0.f, acc1 = 0.f, acc2 = 0.f, acc3 = 0.f;
    int d0 = off[n], d1 = off[n + 1];
    for (int i = d0; i < d1; i++) {
        int e = eid[i];
        int s = src[e];
        float4 wv = *(const float4*)(w + (size_t)e * 4);
        const __half* hr = hg + (size_t)s * 1024;
        acc0 += wv.x * __half2float(hr[t]);
        acc1 += wv.y * __half2float(hr[t + 256]);
        acc2 += wv.z * __half2float(hr[t + 512]);
        acc3 += wv.w * __half2float(hr[t + 768]);
        if (t < 40) {
            int h = t / 10, k = t % 10;
            float wh = (h == 0) ? wv.x : (h == 1) ? wv.y : (h == 2) ? wv.z : wv.w;
            qs[t] += wh * ea[(size_t)e * EAC + 1 + k];
        }
    }
    __syncthreads();
    float acch[4] = {acc0, acc1, acc2, acc3};
#pragma unroll
    for (int h = 0; h < 4; h++) {
        int f = h * 256 + t;
        float et = 0.f;
#pragma unroll
        for (int k = 0; k < 10; k++) et += qs[h * 10 + k] * We[k * 1024 + f];
        float v = lin[(size_t)n * 1024 + f] + lb[f] + cb[f] + acch[h] + et;
        out[(size_t)n * 1024 + f] = fmaxf(v, 0.f);
    }
}

__global__ void k_agg_small(
    const float* __restrict__ hg3, const float* __restrict__ w,
    const int* __restrict__ off, const int* __restrict__ eid,
    const float* __restrict__ ea, const int* __restrict__ src,
    const float* __restrict__ We, const float* __restrict__ lin,
    const float* __restrict__ lb, const float* __restrict__ cb,
    float* __restrict__ out)
{
    int n = blockIdx.x * blockDim.x + threadIdx.x;
    if (n >= NN) return;
    float a0 = 0.f, a1 = 0.f;
    float q[10];
#pragma unroll
    for (int k = 0; k < 10; k++) q[k] = 0.f;
    int d0 = off[n], d1 = off[n + 1];
    for (int i = d0; i < d1; i++) {
        int e = eid[i];
        int s = src[e];
        float wv = w[e];
        a0 += wv * hg3[(size_t)s * 2];
        a1 += wv * hg3[(size_t)s * 2 + 1];
        const float* row = ea + (size_t)e * EAC;
#pragma unroll
        for (int k = 0; k < 10; k++) q[k] += wv * row[1 + k];
    }
    float e0 = 0.f, e1 = 0.f;
#pragma unroll
    for (int k = 0; k < 10; k++) { e0 += q[k] * We[k * 2]; e1 += q[k] * We[k * 2 + 1]; }
    float v0 = lin[(size_t)n * 2] + lb[0] + cb[0] + a0 + e0;
    float v1 = lin[(size_t)n * 2 + 1] + lb[1] + cb[1] + a1 + e1;
    out[(size_t)n * 2] = fmaxf(v0, 0.f);
    out[(size_t)n * 2 + 1] = fmaxf(v1, 0.f);
}

// ---------------- host driver ----------------
static inline int cdiv(int a, int b) { return (a + b - 1) / b; }

struct Scratch {
    float *lin, *hg3, *h, *logw, *ssrc, *sdst, *scale, *shift, *ve, *p1, *p2;
    __half *hg;
    int *deg, *off, *cur, *eid;
    __half *Ah, *B1h, *B1l, *B2h, *B2l;
};

extern "C" void kernel_launch(void* const* d_in, const int* in_sizes, int n_in,
                              void* d_out, int out_size)
{
    const float* x  = (const float*)d_in[0];
    const int*   ei = (const int*)d_in[1];
    const float* ea = (const float*)d_in[2];

    const float *Wg[3], *We[3], *attn[3], *at[3], *cb[3];
    const float *lw[3], *lb[3], *gg[3], *bb[3];

    if (in_sizes[8] == 1048576) {
        for (int i = 0; i < 3; i++) {
            Wg[i]   = (const float*)d_in[3 + 5 * i];
            We[i]   = (const float*)d_in[4 + 5 * i];
            attn[i] = (const float*)d_in[5 + 5 * i];
            at[i]   = (const float*)d_in[6 + 5 * i];
            cb[i]   = (const float*)d_in[7 + 5 * i];
            lw[i]   = (const float*)d_in[18 + 4 * i];
            lb[i]   = (const float*)d_in[19 + 4 * i];
            gg[i]   = (const float*)d_in[20 + 4 * i];
            bb[i]   = (const float*)d_in[21 + 4 * i];
        }
    } else {
        for (int i = 0; i < 3; i++) {
            Wg[i]   = (const float*)d_in[3 + 9 * i];
            We[i]   = (const float*)d_in[4 + 9 * i];
            attn[i] = (const float*)d_in[5 + 9 * i];
            at[i]   = (const float*)d_in[6 + 9 * i];
            cb[i]   = (const float*)d_in[7 + 9 * i];
            lw[i]   = (const float*)d_in[8 + 9 * i];
            lb[i]   = (const float*)d_in[9 + 9 * i];
            gg[i]   = (const float*)d_in[10 + 9 * i];
            bb[i]   = (const float*)d_in[11 + 9 * i];
        }
    }

    Scratch S;
    cudaGetSymbolAddress((void**)&S.lin, g_lin);
    cudaGetSymbolAddress((void**)&S.hg, g_hg);
    cudaGetSymbolAddress((void**)&S.hg3, g_hg3);
    cudaGetSymbolAddress((void**)&S.h, g_h);
    cudaGetSymbolAddress((void**)&S.logw, g_logw);
    cudaGetSymbolAddress((void**)&S.ssrc, g_ssrc);
    cudaGetSymbolAddress((void**)&S.sdst, g_sdst);
    cudaGetSymbolAddress((void**)&S.p1, g_part1);
    cudaGetSymbolAddress((void**)&S.p2, g_part2);
    cudaGetSymbolAddress((void**)&S.scale, g_scale);
    cudaGetSymbolAddress((void**)&S.shift, g_shift);
    cudaGetSymbolAddress((void**)&S.ve, g_ve);
    cudaGetSymbolAddress((void**)&S.deg, g_deg);
    cudaGetSymbolAddress((void**)&S.off, g_off);
    cudaGetSymbolAddress((void**)&S.cur, g_cur);
    cudaGetSymbolAddress((void**)&S.eid, g_eid);
    cudaGetSymbolAddress((void**)&S.Ah, g_Ah);
    cudaGetSymbolAddress((void**)&S.B1h, g_B1h);
    cudaGetSymbolAddress((void**)&S.B1l, g_B1l);
    cudaGetSymbolAddress((void**)&S.B2h, g_B2h);
    cudaGetSymbolAddress((void**)&S.B2l, g_B2l);

    cudaFuncSetAttribute(gemm_mma, cudaFuncAttributeMaxDynamicSharedMemorySize, GT_SMEM);

    // ======== layer 1 ========
    {
        int F = F1, Kp = 192;
        k_bnstat<<<dim3(cdiv(F, 256), BNCH), 256>>>(x, S.p1, S.p2, F);
        k_bnfin<<<cdiv(F, 256), 256>>>(S.p1, S.p2, gg[0], bb[0], S.scale, S.shift, F);
        size_t tp = (size_t)NN * Kp + (size_t)NN * 8;
        k_prep<<<(int)((tp + 255) / 256), 256>>>(x, S.scale, S.shift, S.Ah, S.ssrc, S.sdst, F, Kp);
        k_prepB_t<<<dim3(Kp / 32, 32, 2), dim3(32, 8)>>>(lw[0], Wg[0], S.B1h, S.B1l, S.B2h, S.B2l, F, Kp);
        gemm_mma<<<dim3(16, cdiv(NN, 128)), 256, GT_SMEM>>>(
            S.Ah, Kp, S.B1h, S.B1l, S.B2h, S.B2l, S.lin, S.hg, NN,
            attn[0], S.ssrc, S.sdst);
        k_init<<<cdiv(NN, 256), 256>>>(S.deg, S.cur);
        k_hist<<<cdiv(EE, 256), 256>>>(ei + EE, S.deg);
        k_scan<<<1, 1024>>>(S.deg, S.off, NN);
        k_scatter<<<cdiv(EE, 256), 256>>>(ei + EE, S.off, S.cur, S.eid);
        k_ve<<<1, 64>>>(We[0], attn[0], S.ve, 4, 256);
        k_attn4<<<cdiv(NN, 256), 256>>>(S.off, S.eid, ei, ea, S.ssrc, S.sdst, S.ve, at[0], (float4*)S.logw);
        k_agg_big<<<NN, 256>>>(S.hg, S.logw, S.off, S.eid, ea, ei, We[0], S.lin, lb[0], cb[0], S.h);
    }
    // ======== layer 2 ========
    {
        int F = HIDD, Kp = HIDD;
        k_bnstat<<<dim3(cdiv(F, 256), BNCH), 256>>>(S.h, S.p1, S.p2, F);
        k_bnfin<<<cdiv(F, 256), 256>>>(S.p1, S.p2, gg[1], bb[1], S.scale, S.shift, F);
        size_t tp = (size_t)NN * Kp + (size_t)NN * 8;
        k_prep<<<(int)((tp + 255) / 256), 256>>>(S.h, S.scale, S.shift, S.Ah, S.ssrc, S.sdst, F, Kp);
        k_prepB_t<<<dim3(Kp / 32, 32, 2), dim3(32, 8)>>>(lw[1], Wg[1], S.B1h, S.B1l, S.B2h, S.B2l, F, Kp);
        gemm_mma<<<dim3(16, cdiv(NN, 128)), 256, GT_SMEM>>>(
            S.Ah, Kp, S.B1h, S.B1l, S.B2h, S.B2l, S.lin, S.hg, NN,
            attn[1], S.ssrc, S.sdst);
        k_ve<<<1, 64>>>(We[1], attn[1], S.ve, 4, 256);
        k_attn4<<<cdiv(NN, 256), 256>>>(S.off, S.eid, ei, ea, S.ssrc, S.sdst, S.ve, at[1], (float4*)S.logw);
        k_agg_big<<<NN, 256>>>(S.hg, S.logw, S.off, S.eid, ea, ei, We[1], S.lin, lb[1], cb[1], S.h);
    }
    // ======== layer 3 ========
    {
        k_bnstat<<<dim3(cdiv(HIDD, 256), BNCH), 256>>>(S.h, S.p1, S.p2, HIDD);
        k_bnfin<<<cdiv(HIDD, 256), 256>>>(S.p1, S.p2, gg[2], bb[2], S.scale, S.shift, HIDD);
        k_gemm_small<<<NN, 128>>>(S.h, S.scale, S.shift, lw[2], Wg[2], S.lin, S.hg3);
        k_ve<<<1, 64>>>(We[2], attn[2], S.ve, 1, 2);
        k_sdots3<<<cdiv(NN, 256), 256>>>(S.hg3, attn[2], S.ssrc, S.sdst);
        k_attn1<<<cdiv(NN, 256), 256>>>(S.off, S.eid, ei, ea, S.ssrc, S.sdst, S.ve, at[2], S.logw);
        k_agg_small<<<cdiv(NN, 256), 256>>>(S.hg3, S.logw, S.off, S.eid, ea, ei, We[2], S.lin, lb[2], cb[2], (float*)d_out);
    }
}

// round 15
// speedup vs baseline: 1.3944x; 1.1143x over previous
#include <cuda_runtime.h>
#include <cuda_bf16.h>
#include <cuda_fp16.h>
#include <cstdint>
#include <math.h>

#define NN   20000
#define EE   100000
#define F1   167
#define HIDD 1024
#define EDK  10
#define EAC  12
#define BNCH 40

// ---------------- scratch (device globals) ----------------
__device__ __half g_lin[(size_t)NN * HIDD];
__device__ __half g_hg[(size_t)NN * HIDD];
__device__ float g_hg3[(size_t)NN * 2];
__device__ float g_h  [(size_t)NN * HIDD];
__device__ float g_logw[(size_t)EE * 4];
__device__ float g_ssrc[(size_t)NN * 4];
__device__ float g_sdst[(size_t)NN * 4];
__device__ float g_part1[BNCH * HIDD];
__device__ float g_part2[BNCH * HIDD];
__device__ float g_scale[HIDD];
__device__ float g_shift[HIDD];
__device__ float g_ve[EDK * 4];
__device__ int   g_deg[NN];
__device__ int   g_off[NN + 1];
__device__ int   g_cur[NN];
__device__ int   g_eid[EE];
__device__ __half g_Ah[(size_t)NN * HIDD];
__device__ __half g_B1h[(size_t)HIDD * HIDD];
__device__ __half g_B1l[(size_t)HIDD * HIDD];
__device__ __half g_B2h[(size_t)HIDD * HIDD];
__device__ __half g_B2l[(size_t)HIDD * HIDD];

// ---------------- BatchNorm: partials ----------------
__global__ void k_bnstat(const float* __restrict__ x, float* __restrict__ p1,
                         float* __restrict__ p2, int F) {
    int c = blockIdx.x * blockDim.x + threadIdx.x;
    if (c >= F) return;
    int chunk = (NN + BNCH - 1) / BNCH;
    int r0 = blockIdx.y * chunk;
    int r1 = r0 + chunk; if (r1 > NN) r1 = NN;
    float a = 0.f, b = 0.f;
    for (int r = r0; r < r1; r++) {
        float v = x[(size_t)r * F + c];
        a += v; b += v * v;
    }
    p1[blockIdx.y * F + c] = a;
    p2[blockIdx.y * F + c] = b;
}

__global__ void k_bnfin(const float* __restrict__ p1, const float* __restrict__ p2,
                        const float* __restrict__ g, const float* __restrict__ b,
                        float* __restrict__ scale, float* __restrict__ shift, int F) {
    int c = blockIdx.x * blockDim.x + threadIdx.x;
    if (c >= F) return;
    float a = 0.f, s = 0.f;
    for (int y = 0; y < BNCH; y++) { a += p1[y * F + c]; s += p2[y * F + c]; }
    float invN = 1.f / (float)NN;
    float mu = a * invN;
    float var = s * invN - mu * mu;
    float rstd = rsqrtf(var + 1e-5f);
    float sc = rstd * g[c];
    scale[c] = sc;
    shift[c] = b[c] - mu * sc;
}

// ---------------- prep A (fp16, BN fused) + zero ssrc/sdst ----------------
__global__ void k_prep(const float* __restrict__ x, const float* __restrict__ scale,
                       const float* __restrict__ shift, __half* __restrict__ Ah,
                       float* __restrict__ ssrc, float* __restrict__ sdst,
                       int F, int Kp) {
    size_t na = (size_t)NN * Kp;
    size_t i = (size_t)blockIdx.x * blockDim.x + threadIdx.x;
    if (i < na) {
        int m = (int)(i / Kp), k = (int)(i % Kp);
        float v = 0.f;
        if (k < F) v = x[(size_t)m * F + k] * scale[k] + shift[k];
        Ah[i] = __float2half_rn(v);
    } else if (i < na + (size_t)NN * 4) {
        ssrc[i - na] = 0.f;
    } else if (i < na + (size_t)NN * 8) {
        sdst[i - na - (size_t)NN * 4] = 0.f;
    }
}

// ---------------- prep B: coalesced transpose + fp16 split ----------------
__global__ void k_prepB_t(const float* __restrict__ W1, const float* __restrict__ W2,
                          __half* __restrict__ B1h, __half* __restrict__ B1l,
                          __half* __restrict__ B2h, __half* __restrict__ B2l,
                          int F, int Kp) {
    __shared__ float tile[32][33];
    const float* W = blockIdx.z ? W2 : W1;
    __half* Bh = blockIdx.z ? B2h : B1h;
    __half* Bl = blockIdx.z ? B2l : B1l;
    int k0 = blockIdx.x * 32, n0 = blockIdx.y * 32;
    int tx = threadIdx.x, ty = threadIdx.y;
#pragma unroll
    for (int r = ty; r < 32; r += 8) {
        int k = k0 + r;
        tile[r][tx] = (k < F) ? W[(size_t)k * HIDD + n0 + tx] : 0.f;
    }
    __syncthreads();
#pragma unroll
    for (int r = ty; r < 32; r += 8) {
        int n = n0 + r, k = k0 + tx;
        float v = tile[tx][r];
        __half h = __float2half_rn(v);
        Bh[(size_t)n * Kp + k] = h;
        Bl[(size_t)n * Kp + k] = __float2half_rn(v - __half2float(h));
    }
}

// ---------------- mma.sync helpers ----------------
__device__ __forceinline__ uint32_t smem_u32(const void* p) {
    uint32_t a;
    asm("{ .reg .u64 t; cvta.to.shared.u64 t, %1; cvt.u32.u64 %0, t; }" : "=r"(a) : "l"(p));
    return a;
}
__device__ __forceinline__ void sts128(uint32_t addr, uint4 v) {
    asm volatile("st.shared.v4.b32 [%0], {%1,%2,%3,%4};"
                 :: "r"(addr), "r"(v.x), "r"(v.y), "r"(v.z), "r"(v.w) : "memory");
}
__device__ __forceinline__ void cpasync16(uint32_t s, const void* g) {
    asm volatile("cp.async.cg.shared.global [%0], [%1], 16;" :: "r"(s), "l"(g));
}
#define CP_COMMIT() asm volatile("cp.async.commit_group;" ::: "memory")
#define CP_WAIT0()  asm volatile("cp.async.wait_group 0;" ::: "memory")
#define SWZ(x) ((x) ^ (((x) >> 3) & 0x70))

#define LDSM4(r0, r1, r2, r3, addr) \
    asm volatile("ldmatrix.sync.aligned.m8n8.x4.shared.b16 {%0,%1,%2,%3}, [%4];" \
                 : "=r"(r0), "=r"(r1), "=r"(r2), "=r"(r3) : "r"(addr))

#define MMA_F16(d, a0, a1, a2, a3, b0, b1) \
    asm volatile("mma.sync.aligned.m16n8k16.row.col.f32.f16.f16.f32 " \
                 "{%0,%1,%2,%3}, {%4,%5,%6,%7}, {%8,%9}, {%0,%1,%2,%3};" \
                 : "+f"((d)[0]), "+f"((d)[1]), "+f"((d)[2]), "+f"((d)[3]) \
                 : "r"(a0), "r"(a1), "r"(a2), "r"(a3), "r"(b0), "r"(b1))

// ---------------- fp16 2-pass GEMM: 128x128 tile, K-chunk 64, 2-stage, 2 CTA/SM --
// nt 0-7 -> C1 (lin, fp16); nt 8-15 -> C2 (hg, fp16) + fused attn dots.
#define STAGE_BYTES 49152   // Ah 16K | Bh 16K | Bl 16K  (128B rows, SW128)
#define GT_SMEM (2 * STAGE_BYTES + 512)

__global__ __launch_bounds__(256, 2) void gemm_mma(
    const __half* __restrict__ Ah, int Kp,
    const __half* __restrict__ B1h, const __half* __restrict__ B1l,
    const __half* __restrict__ B2h, const __half* __restrict__ B2l,
    __half* __restrict__ C1, __half* __restrict__ C2, int M,
    const float* __restrict__ attn, float* __restrict__ ssrc, float* __restrict__ sdst)
{
    extern __shared__ char smraw[];
    uint32_t sb = (smem_u32(smraw) + 255) & ~255u;
    int tid = threadIdx.x, lane = tid & 31, wid = tid >> 5;
    int nt = blockIdx.x, mt = blockIdx.y;

    const __half *Bh, *Bl;
    __half* C;
    int coloff;
    if (nt < 8) { Bh = B1h; Bl = B1l; C = C1; coloff = nt * 128; }
    else        { Bh = B2h; Bl = B2l; C = C2; coloff = (nt - 8) * 128; }

    int wm = wid & 1, wn = wid >> 1;   // 2 x 4 warp grid; warp tile 64x32

    float acc[4][4][4];
#pragma unroll
    for (int a = 0; a < 4; a++)
#pragma unroll
        for (int b = 0; b < 4; b++)
#pragma unroll
            for (int cc = 0; cc < 4; cc++) acc[a][b][cc] = 0.f;

    uint32_t rawA[4];
    uint32_t rawB[2];
#pragma unroll
    for (int mi = 0; mi < 4; mi++) {
        int row = wm * 64 + mi * 16 + (lane & 15);
        rawA[mi] = (uint32_t)(row * 128 + (lane >> 4) * 16);
    }
#pragma unroll
    for (int p = 0; p < 2; p++) {
        int row = wn * 32 + p * 16 + ((lane >> 4) << 3) + (lane & 7);
        rawB[p] = (uint32_t)(row * 128 + (((lane >> 3) & 1) << 4));
    }

    int q = tid & 7;
    int rr = tid >> 3;
    int chunks = Kp >> 6;

    auto load_stage = [&](int c) {
        uint32_t base = sb + (uint32_t)(c & 1) * STAGE_BYTES;
        uint32_t bAh = base, bBh = base + 16384, bBl = base + 32768;
        size_t kel = (size_t)c * 64 + q * 8;
#pragma unroll
        for (int i = 0; i < 4; i++) {
            int row = rr + i * 32;
            uint32_t soff = SWZ((uint32_t)(row * 128 + q * 16));
            int m = mt * 128 + row;
            if (m < M) {
                cpasync16(bAh + soff, Ah + (size_t)m * Kp + kel);
            } else {
                uint4 z = make_uint4(0, 0, 0, 0);
                sts128(bAh + soff, z);
            }
            int nr = coloff + row;
            cpasync16(bBh + soff, Bh + (size_t)nr * Kp + kel);
            cpasync16(bBl + soff, Bl + (size_t)nr * Kp + kel);
        }
        CP_COMMIT();
    };

    load_stage(0);

    for (int c = 0; c < chunks; c++) {
        CP_WAIT0();
        __syncthreads();
        if (c + 1 < chunks) load_stage(c + 1);

        uint32_t cur = sb + (uint32_t)(c & 1) * STAGE_BYTES;
        uint32_t cAh = cur, cBh = cur + 16384, cBl = cur + 32768;
#pragma unroll
        for (int k16 = 0; k16 < 4; k16++) {
            uint32_t kb = (uint32_t)k16 * 32;
            uint32_t af0[4], af1[4], af2[4], af3[4];
#pragma unroll
            for (int mi = 0; mi < 4; mi++)
                LDSM4(af0[mi], af1[mi], af2[mi], af3[mi], cAh + SWZ(rawA[mi] + kb));
            uint32_t bh0[4], bh1[4], bl0[4], bl1[4];
#pragma unroll
            for (int pp = 0; pp < 2; pp++) {
                uint32_t addr = SWZ(rawB[pp] + kb);
                uint32_t r0_, r1_, r2_, r3_;
                LDSM4(r0_, r1_, r2_, r3_, cBh + addr);
                bh0[pp * 2] = r0_; bh1[pp * 2] = r1_;
                bh0[pp * 2 + 1] = r2_; bh1[pp * 2 + 1] = r3_;
                LDSM4(r0_, r1_, r2_, r3_, cBl + addr);
                bl0[pp * 2] = r0_; bl1[pp * 2] = r1_;
                bl0[pp * 2 + 1] = r2_; bl1[pp * 2 + 1] = r3_;
            }
#pragma unroll
            for (int mi = 0; mi < 4; mi++)
#pragma unroll
                for (int ni = 0; ni < 4; ni++)
                    MMA_F16(acc[mi][ni], af0[mi], af1[mi], af2[mi], af3[mi], bh0[ni], bh1[ni]);
#pragma unroll
            for (int mi = 0; mi < 4; mi++)
#pragma unroll
                for (int ni = 0; ni < 4; ni++)
                    MMA_F16(acc[mi][ni], af0[mi], af1[mi], af2[mi], af3[mi], bl0[ni], bl1[ni]);
        }
    }

    // epilogue: half2 stores; attn dots on the hg half (nt>=8)
    int doAttn = (nt >= 8);
    int hh = (coloff >> 8) & 3;
    int hcbase = coloff & 255;
    const float* a0p = attn + (size_t)hh * 256;
    const float* a1p = attn + (size_t)(4 + hh) * 256;
#pragma unroll
    for (int mi = 0; mi < 4; mi++) {
        int gr = mt * 128 + wm * 64 + mi * 16 + (lane >> 2);
        float s0 = 0.f, d0 = 0.f, s1 = 0.f, d1 = 0.f;
#pragma unroll
        for (int ni = 0; ni < 4; ni++) {
            int cl = wn * 32 + ni * 8 + ((lane & 3) << 1);
            int gc = coloff + cl;
            if (gr < M)
                *(__half2*)(C + (size_t)gr * HIDD + gc) =
                    __floats2half2_rn(acc[mi][ni][0], acc[mi][ni][1]);
            if (gr + 8 < M)
                *(__half2*)(C + (size_t)(gr + 8) * HIDD + gc) =
                    __floats2half2_rn(acc[mi][ni][2], acc[mi][ni][3]);
            if (doAttn) {
                int cw = hcbase + cl;
                float2 av = *(const float2*)(a0p + cw);
                float2 bv = *(const float2*)(a1p + cw);
                s0 += acc[mi][ni][0] * av.x + acc[mi][ni][1] * av.y;
                d0 += acc[mi][ni][0] * bv.x + acc[mi][ni][1] * bv.y;
                s1 += acc[mi][ni][2] * av.x + acc[mi][ni][3] * av.y;
                d1 += acc[mi][ni][2] * bv.x + acc[mi][ni][3] * bv.y;
            }
        }
        if (doAttn) {
#pragma unroll
            for (int o = 1; o < 4; o <<= 1) {
                s0 += __shfl_xor_sync(0xFFFFFFFFu, s0, o);
                d0 += __shfl_xor_sync(0xFFFFFFFFu, d0, o);
                s1 += __shfl_xor_sync(0xFFFFFFFFu, s1, o);
                d1 += __shfl_xor_sync(0xFFFFFFFFu, d1, o);
            }
            if ((lane & 3) == 0) {
                if (gr < M) {
                    atomicAdd(&ssrc[gr * 4 + hh], s0);
                    atomicAdd(&sdst[gr * 4 + hh], d0);
                }
                if (gr + 8 < M) {
                    atomicAdd(&ssrc[(gr + 8) * 4 + hh], s1);
                    atomicAdd(&sdst[(gr + 8) * 4 + hh], d1);
                }
            }
        }
    }
}

// ---------------- CSR build ----------------
__global__ void k_init(int* deg, int* cur) {
    int i = blockIdx.x * blockDim.x + threadIdx.x;
    if (i < NN) { deg[i] = 0; cur[i] = 0; }
}
__global__ void k_hist(const int* __restrict__ dst, int* __restrict__ deg) {
    int e = blockIdx.x * blockDim.x + threadIdx.x;
    if (e < EE) atomicAdd(&deg[dst[e]], 1);
}
__global__ void k_scan(const int* __restrict__ deg, int* __restrict__ off, int n) {
    __shared__ int sh[1024];
    __shared__ int carry;
    int t = threadIdx.x;
    if (t == 0) { carry = 0; off[0] = 0; }
    __syncthreads();
    for (int base = 0; base < n; base += 1024) {
        int v = (base + t < n) ? deg[base + t] : 0;
        sh[t] = v;
        __syncthreads();
        for (int d = 1; d < 1024; d <<= 1) {
            int add = (t >= d) ? sh[t - d] : 0;
            __syncthreads();
            sh[t] += add;
            __syncthreads();
        }
        if (base + t < n) off[base + t + 1] = carry + sh[t];
        __syncthreads();
        if (t == 0) carry += sh[1023];
        __syncthreads();
    }
}
__global__ void k_scatter(const int* __restrict__ dst, const int* __restrict__ off,
                          int* __restrict__ cur, int* __restrict__ eid) {
    int e = blockIdx.x * blockDim.x + threadIdx.x;
    if (e >= EE) return;
    int d = dst[e];
    int p = atomicAdd(&cur[d], 1);
    eid[off[d] + p] = e;
}

// ---------------- layer-3 tiny GEMM (BN inline, fp32; lin -> lin3 float) --------
__global__ __launch_bounds__(128) void k_gemm_small(
    const float* __restrict__ h, const float* __restrict__ scale,
    const float* __restrict__ shift,
    const float* __restrict__ lw, const float* __restrict__ wg,
    float* __restrict__ lin3, float* __restrict__ hg3)
{
    int n = blockIdx.x, t = threadIdx.x;
    const float* hr = h + (size_t)n * HIDD;
    float a0 = 0, a1 = 0, a2 = 0, a3 = 0;
    for (int k = t; k < HIDD; k += 128) {
        float a = hr[k] * scale[k] + shift[k];
        a0 += a * lw[k * 2];
        a1 += a * lw[k * 2 + 1];
        a2 += a * wg[k * 2];
        a3 += a * wg[k * 2 + 1];
    }
#pragma unroll
    for (int s = 16; s; s >>= 1) {
        a0 += __shfl_down_sync(0xFFFFFFFFu, a0, s);
        a1 += __shfl_down_sync(0xFFFFFFFFu, a1, s);
        a2 += __shfl_down_sync(0xFFFFFFFFu, a2, s);
        a3 += __shfl_down_sync(0xFFFFFFFFu, a3, s);
    }
    __shared__ float sm[4][4];
    if ((t & 31) == 0) {
        sm[t >> 5][0] = a0; sm[t >> 5][1] = a1; sm[t >> 5][2] = a2; sm[t >> 5][3] = a3;
    }
    __syncthreads();
    if (t == 0) {
        lin3[(size_t)n * 2]     = sm[0][0] + sm[1][0] + sm[2][0] + sm[3][0];
        lin3[(size_t)n * 2 + 1] = sm[0][1] + sm[1][1] + sm[2][1] + sm[3][1];
        hg3[(size_t)n * 2]      = sm[0][2] + sm[1][2] + sm[2][2] + sm[3][2];
        hg3[(size_t)n * 2 + 1]  = sm[0][3] + sm[1][3] + sm[2][3] + sm[3][3];
    }
}

// ---------------- GAT pieces ----------------
__global__ void k_ve(const float* __restrict__ We, const float* __restrict__ attn,
                     float* __restrict__ ve, int H, int O) {
    int t = threadIdx.x;
    if (t >= H * EDK) return;
    int h = t / EDK, k = t % EDK;
    const float* a2 = attn + (size_t)(2 * H + h) * O;
    const float* w = We + (size_t)k * H * O + (size_t)h * O;
    float s = 0.f;
    for (int d = 0; d < O; d++) s += w[d] * a2[d];
    ve[k * H + h] = s;
}

__global__ void k_sdots3(const float* __restrict__ hg3, const float* __restrict__ attn,
                         float* __restrict__ ssrc, float* __restrict__ sdst) {
    int n = blockIdx.x * blockDim.x + threadIdx.x;
    if (n >= NN) return;
    float v0 = hg3[(size_t)n * 2], v1 = hg3[(size_t)n * 2 + 1];
    ssrc[n] = v0 * attn[0] + v1 * attn[1];
    sdst[n] = v0 * attn[2] + v1 * attn[3];
}

// fused logits + softmax, H=4
__global__ __launch_bounds__(256) void k_attn4(
    const int* __restrict__ off, const int* __restrict__ eid,
    const int* __restrict__ ei, const float* __restrict__ ea,
    const float* __restrict__ ssrc, const float* __restrict__ sdst,
    const float* __restrict__ ve, const float* __restrict__ at,
    float4* __restrict__ w4)
{
    __shared__ float sve[EDK * 4];
    __shared__ float sat[4];
    if (threadIdx.x < EDK * 4) sve[threadIdx.x] = ve[threadIdx.x];
    if (threadIdx.x < 4) sat[threadIdx.x] = at[threadIdx.x];
    __syncthreads();
    int n = blockIdx.x * blockDim.x + threadIdx.x;
    if (n >= NN) return;
    int d0 = off[n], d1 = off[n + 1];
    if (d0 == d1) return;
    float4 sd = *(const float4*)(sdst + (size_t)n * 4);
    float4 m = make_float4(-INFINITY, -INFINITY, -INFINITY, -INFINITY);
    for (int i = d0; i < d1; i++) {
        int e = eid[i];
        int s = ei[e];
        float4 ss = *(const float4*)(ssrc + (size_t)s * 4);
        const float4* row = (const float4*)(ea + (size_t)e * EAC);
        float4 r0 = row[0], r1 = row[1], r2 = row[2];
        float t = r0.x;
        float ef[10] = {r0.y, r0.z, r0.w, r1.x, r1.y, r1.z, r1.w, r2.x, r2.y, r2.z};
        float4 l;
        float* lp = (float*)&l;
#pragma unroll
        for (int h = 0; h < 4; h++) {
            float se = 0.f;
#pragma unroll
            for (int k = 0; k < EDK; k++) se += ef[k] * sve[k * 4 + h];
            float v = ((float*)&ss)[h] + ((float*)&sd)[h] + se + t * sat[h];
            lp[h] = (v > 0.f) ? v : 0.2f * v;
        }
        w4[e] = l;
        m.x = fmaxf(m.x, l.x); m.y = fmaxf(m.y, l.y);
        m.z = fmaxf(m.z, l.z); m.w = fmaxf(m.w, l.w);
    }
    float4 s = make_float4(0.f, 0.f, 0.f, 0.f);
    for (int i = d0; i < d1; i++) {
        float4 v = w4[eid[i]];
        v.x = expf(v.x - m.x); v.y = expf(v.y - m.y);
        v.z = expf(v.z - m.z); v.w = expf(v.w - m.w);
        w4[eid[i]] = v;
        s.x += v.x; s.y += v.y; s.z += v.z; s.w += v.w;
    }
    float4 inv = make_float4(1.f / (s.x + 1e-16f), 1.f / (s.y + 1e-16f),
                             1.f / (s.z + 1e-16f), 1.f / (s.w + 1e-16f));
    for (int i = d0; i < d1; i++) {
        float4 v = w4[eid[i]];
        v.x *= inv.x; v.y *= inv.y; v.z *= inv.z; v.w *= inv.w;
        w4[eid[i]] = v;
    }
}

// fused logits + softmax, H=1
__global__ __launch_bounds__(256) void k_attn1(
    const int* __restrict__ off, const int* __restrict__ eid,
    const int* __restrict__ ei, const float* __restrict__ ea,
    const float* __restrict__ ssrc, const float* __restrict__ sdst,
    const float* __restrict__ ve, const float* __restrict__ at,
    float* __restrict__ logw)
{
    __shared__ float sve[EDK];
    __shared__ float sat0;
    if (threadIdx.x < EDK) sve[threadIdx.x] = ve[threadIdx.x];
    if (threadIdx.x == 0) sat0 = at[0];
    __syncthreads();
    int n = blockIdx.x * blockDim.x + threadIdx.x;
    if (n >= NN) return;
    int d0 = off[n], d1 = off[n + 1];
    if (d0 == d1) return;
    float sd = sdst[n];
    float m = -INFINITY;
    for (int i = d0; i < d1; i++) {
        int e = eid[i];
        int s = ei[e];
        const float4* row = (const float4*)(ea + (size_t)e * EAC);
        float4 r0 = row[0], r1 = row[1], r2 = row[2];
        float t = r0.x;
        float ef[10] = {r0.y, r0.z, r0.w, r1.x, r1.y, r1.z, r1.w, r2.x, r2.y, r2.z};
        float se = 0.f;
#pragma unroll
        for (int k = 0; k < EDK; k++) se += ef[k] * sve[k];
        float v = ssrc[s] + sd + se + t * sat0;
        v = (v > 0.f) ? v : 0.2f * v;
        logw[e] = v;
        m = fmaxf(m, v);
    }
    float s = 0.f;
    for (int i = d0; i < d1; i++) {
        float p = expf(logw[eid[i]] - m);
        logw[eid[i]] = p;
        s += p;
    }
    float inv = 1.f / (s + 1e-16f);
    for (int i = d0; i < d1; i++) logw[eid[i]] *= inv;
}

// ---------------- aggregation + epilogue (half2-vectorized) ----------------
__global__ __launch_bounds__(256) void k_agg_big(
    const __half* __restrict__ hg, const float* __restrict__ w,
    const int* __restrict__ off, const int* __restrict__ eid,
    const float* __restrict__ ea, const int* __restrict__ src,
    const float* __restrict__ We, const __half* __restrict__ lin,
    const float* __restrict__ lb, const float* __restrict__ cb,
    float* __restrict__ out)
{
    int n = blockIdx.x;
    int t = threadIdx.x;
    __shared__ float qs[40];
    if (t < 40) qs[t] = 0.f;
    // thread t handles half2 pairs t (cols 2t,2t+1; head t>>7) and t+256 (cols 512+2t..; head 2+(t>>7))
    int h0 = t >> 7;
    float2 acc0 = make_float2(0.f, 0.f), acc1 = make_float2(0.f, 0.f);
    int d0 = off[n], d1 = off[n + 1];
    for (int i = d0; i < d1; i++) {
        int e = eid[i];
        int s = src[e];
        float4 wv = *(const float4*)(w + (size_t)e * 4);
        const __half2* hr = (const __half2*)(hg + (size_t)s * 1024);
        float2 v0 = __half22float2(hr[t]);
        float2 v1 = __half22float2(hr[t + 256]);
        float w0 = (h0 == 0) ? wv.x : wv.y;
        float w1 = (h0 == 0) ? wv.z : wv.w;
        acc0.x += w0 * v0.x; acc0.y += w0 * v0.y;
        acc1.x += w1 * v1.x; acc1.y += w1 * v1.y;
        if (t < 40) {
            int h = t / 10, k = t % 10;
            float wh = (h == 0) ? wv.x : (h == 1) ? wv.y : (h == 2) ? wv.z : wv.w;
            qs[t] += wh * ea[(size_t)e * EAC + 1 + k];
        }
    }
    __syncthreads();
    int f0 = 2 * t;          // head h0
    int f1 = 512 + 2 * t;    // head h1 = 2 + h0
    int h1 = 2 + h0;
    float e0x = 0.f, e0y = 0.f, e1x = 0.f, e1y = 0.f;
#pragma unroll
    for (int k = 0; k < 10; k++) {
        float q0 = qs[h0 * 10 + k], q1 = qs[h1 * 10 + k];
        float2 w0 = *(const float2*)(We + (size_t)k * 1024 + f0);
        float2 w1 = *(const float2*)(We + (size_t)k * 1024 + f1);
        e0x += q0 * w0.x; e0y += q0 * w0.y;
        e1x += q1 * w1.x; e1y += q1 * w1.y;
    }
    const __half2* ln = (const __half2*)(lin + (size_t)n * 1024);
    float2 l0 = __half22float2(ln[t]);
    float2 l1 = __half22float2(ln[t + 256]);
    float* on = out + (size_t)n * 1024;
    on[f0]     = fmaxf(l0.x + lb[f0] + cb[f0] + acc0.x + e0x, 0.f);
    on[f0 + 1] = fmaxf(l0.y + lb[f0 + 1] + cb[f0 + 1] + acc0.y + e0y, 0.f);
    on[f1]     = fmaxf(l1.x + lb[f1] + cb[f1] + acc1.x + e1x, 0.f);
    on[f1 + 1] = fmaxf(l1.y + lb[f1 + 1] + cb[f1 + 1] + acc1.y + e1y, 0.f);
}

__global__ void k_agg_small(
    const float* __restrict__ hg3, const float* __restrict__ w,
    const int* __restrict__ off, const int* __restrict__ eid,
    const float* __restrict__ ea, const int* __restrict__ src,
    const float* __restrict__ We, const float* __restrict__ lin3,
    const float* __restrict__ lb, const float* __restrict__ cb,
    float* __restrict__ out)
{
    int n = blockIdx.x * blockDim.x + threadIdx.x;
    if (n >= NN) return;
    float a0 = 0.f, a1 = 0.f;
    float q[10];
#pragma unroll
    for (int k = 0; k < 10; k++) q[k] = 0.f;
    int d0 = off[n], d1 = off[n + 1];
    for (int i = d0; i < d1; i++) {
        int e = eid[i];
        int s = src[e];
        float wv = w[e];
        a0 += wv * hg3[(size_t)s * 2];
        a1 += wv * hg3[(size_t)s * 2 + 1];
        const float* row = ea + (size_t)e * EAC;
#pragma unroll
        for (int k = 0; k < 10; k++) q[k] += wv * row[1 + k];
    }
    float e0 = 0.f, e1 = 0.f;
#pragma unroll
    for (int k = 0; k < 10; k++) { e0 += q[k] * We[k * 2]; e1 += q[k] * We[k * 2 + 1]; }
    float v0 = lin3[(size_t)n * 2] + lb[0] + cb[0] + a0 + e0;
    float v1 = lin3[(size_t)n * 2 + 1] + lb[1] + cb[1] + a1 + e1;
    out[(size_t)n * 2] = fmaxf(v0, 0.f);
    out[(size_t)n * 2 + 1] = fmaxf(v1, 0.f);
}

// ---------------- host driver ----------------
static inline int cdiv(int a, int b) { return (a + b - 1) / b; }

struct Scratch {
    float *hg3, *h, *logw, *ssrc, *sdst, *scale, *shift, *ve, *p1, *p2;
    __half *lin, *hg;
    int *deg, *off, *cur, *eid;
    __half *Ah, *B1h, *B1l, *B2h, *B2l;
};

extern "C" void kernel_launch(void* const* d_in, const int* in_sizes, int n_in,
                              void* d_out, int out_size)
{
    const float* x  = (const float*)d_in[0];
    const int*   ei = (const int*)d_in[1];
    const float* ea = (const float*)d_in[2];

    const float *Wg[3], *We[3], *attn[3], *at[3], *cb[3];
    const float *lw[3], *lb[3], *gg[3], *bb[3];

    if (in_sizes[8] == 1048576) {
        for (int i = 0; i < 3; i++) {
            Wg[i]   = (const float*)d_in[3 + 5 * i];
            We[i]   = (const float*)d_in[4 + 5 * i];
            attn[i] = (const float*)d_in[5 + 5 * i];
            at[i]   = (const float*)d_in[6 + 5 * i];
            cb[i]   = (const float*)d_in[7 + 5 * i];
            lw[i]   = (const float*)d_in[18 + 4 * i];
            lb[i]   = (const float*)d_in[19 + 4 * i];
            gg[i]   = (const float*)d_in[20 + 4 * i];
            bb[i]   = (const float*)d_in[21 + 4 * i];
        }
    } else {
        for (int i = 0; i < 3; i++) {
            Wg[i]   = (const float*)d_in[3 + 9 * i];
            We[i]   = (const float*)d_in[4 + 9 * i];
            attn[i] = (const float*)d_in[5 + 9 * i];
            at[i]   = (const float*)d_in[6 + 9 * i];
            cb[i]   = (const float*)d_in[7 + 9 * i];
            lw[i]   = (const float*)d_in[8 + 9 * i];
            lb[i]   = (const float*)d_in[9 + 9 * i];
            gg[i]   = (const float*)d_in[10 + 9 * i];
            bb[i]   = (const float*)d_in[11 + 9 * i];
        }
    }

    Scratch S;
    cudaGetSymbolAddress((void**)&S.lin, g_lin);
    cudaGetSymbolAddress((void**)&S.hg, g_hg);
    cudaGetSymbolAddress((void**)&S.hg3, g_hg3);
    cudaGetSymbolAddress((void**)&S.h, g_h);
    cudaGetSymbolAddress((void**)&S.logw, g_logw);
    cudaGetSymbolAddress((void**)&S.ssrc, g_ssrc);
    cudaGetSymbolAddress((void**)&S.sdst, g_sdst);
    cudaGetSymbolAddress((void**)&S.p1, g_part1);
    cudaGetSymbolAddress((void**)&S.p2, g_part2);
    cudaGetSymbolAddress((void**)&S.scale, g_scale);
    cudaGetSymbolAddress((void**)&S.shift, g_shift);
    cudaGetSymbolAddress((void**)&S.ve, g_ve);
    cudaGetSymbolAddress((void**)&S.deg, g_deg);
    cudaGetSymbolAddress((void**)&S.off, g_off);
    cudaGetSymbolAddress((void**)&S.cur, g_cur);
    cudaGetSymbolAddress((void**)&S.eid, g_eid);
    cudaGetSymbolAddress((void**)&S.Ah, g_Ah);
    cudaGetSymbolAddress((void**)&S.B1h, g_B1h);
    cudaGetSymbolAddress((void**)&S.B1l, g_B1l);
    cudaGetSymbolAddress((void**)&S.B2h, g_B2h);
    cudaGetSymbolAddress((void**)&S.B2l, g_B2l);

    cudaFuncSetAttribute(gemm_mma, cudaFuncAttributeMaxDynamicSharedMemorySize, GT_SMEM);

    // ======== layer 1 ========
    {
        int F = F1, Kp = 192;
        k_bnstat<<<dim3(cdiv(F, 256), BNCH), 256>>>(x, S.p1, S.p2, F);
        k_bnfin<<<cdiv(F, 256), 256>>>(S.p1, S.p2, gg[0], bb[0], S.scale, S.shift, F);
        size_t tp = (size_t)NN * Kp + (size_t)NN * 8;
        k_prep<<<(int)((tp + 255) / 256), 256>>>(x, S.scale, S.shift, S.Ah, S.ssrc, S.sdst, F, Kp);
        k_prepB_t<<<dim3(Kp / 32, 32, 2), dim3(32, 8)>>>(lw[0], Wg[0], S.B1h, S.B1l, S.B2h, S.B2l, F, Kp);
        gemm_mma<<<dim3(16, cdiv(NN, 128)), 256, GT_SMEM>>>(
            S.Ah, Kp, S.B1h, S.B1l, S.B2h, S.B2l, S.lin, S.hg, NN,
            attn[0], S.ssrc, S.sdst);
        k_init<<<cdiv(NN, 256), 256>>>(S.deg, S.cur);
        k_hist<<<cdiv(EE, 256), 256>>>(ei + EE, S.deg);
        k_scan<<<1, 1024>>>(S.deg, S.off, NN);
        k_scatter<<<cdiv(EE, 256), 256>>>(ei + EE, S.off, S.cur, S.eid);
        k_ve<<<1, 64>>>(We[0], attn[0], S.ve, 4, 256);
        k_attn4<<<cdiv(NN, 256), 256>>>(S.off, S.eid, ei, ea, S.ssrc, S.sdst, S.ve, at[0], (float4*)S.logw);
        k_agg_big<<<NN, 256>>>(S.hg, S.logw, S.off, S.eid, ea, ei, We[0], S.lin, lb[0], cb[0], S.h);
    }
    // ======== layer 2 ========
    {
        int F = HIDD, Kp = HIDD;
        k_bnstat<<<dim3(cdiv(F, 256), BNCH), 256>>>(S.h, S.p1, S.p2, F);
        k_bnfin<<<cdiv(F, 256), 256>>>(S.p1, S.p2, gg[1], bb[1], S.scale, S.shift, F);
        size_t tp = (size_t)NN * Kp + (size_t)NN * 8;
        k_prep<<<(int)((tp + 255) / 256), 256>>>(S.h, S.scale, S.shift, S.Ah, S.ssrc, S.sdst, F, Kp);
        k_prepB_t<<<dim3(Kp / 32, 32, 2), dim3(32, 8)>>>(lw[1], Wg[1], S.B1h, S.B1l, S.B2h, S.B2l, F, Kp);
        gemm_mma<<<dim3(16, cdiv(NN, 128)), 256, GT_SMEM>>>(
            S.Ah, Kp, S.B1h, S.B1l, S.B2h, S.B2l, S.lin, S.hg, NN,
            attn[1], S.ssrc, S.sdst);
        k_ve<<<1, 64>>>(We[1], attn[1], S.ve, 4, 256);
        k_attn4<<<cdiv(NN, 256), 256>>>(S.off, S.eid, ei, ea, S.ssrc, S.sdst, S.ve, at[1], (float4*)S.logw);
        k_agg_big<<<NN, 256>>>(S.hg, S.logw, S.off, S.eid, ea, ei, We[1], S.lin, lb[1], cb[1], S.h);
    }
    // ======== layer 3 (lin3 reuses p1, free after bnfin) ========
    {
        k_bnstat<<<dim3(cdiv(HIDD, 256), BNCH), 256>>>(S.h, S.p1, S.p2, HIDD);
        k_bnfin<<<cdiv(HIDD, 256), 256>>>(S.p1, S.p2, gg[2], bb[2], S.scale, S.shift, HIDD);
        float* lin3 = S.p1;
        k_gemm_small<<<NN, 128>>>(S.h, S.scale, S.shift, lw[2], Wg[2], lin3, S.hg3);
        k_ve<<<1, 64>>>(We[2], attn[2], S.ve, 1, 2);
        k_sdots3<<<cdiv(NN, 256), 256>>>(S.hg3, attn[2], S.ssrc, S.sdst);
        k_attn1<<<cdiv(NN, 256), 256>>>(S.off, S.eid, ei, ea, S.ssrc, S.sdst, S.ve, at[2], S.logw);
        k_agg_small<<<cdiv(NN, 256), 256>>>(S.hg3, S.logw, S.off, S.eid, ea, ei, We[2], lin3, lb[2], cb[2], (float*)d_out);
    }
}

// round 16
// speedup vs baseline: 1.5002x; 1.0759x over previous
#include <cuda_runtime.h>
#include <cuda_bf16.h>
#include <cuda_fp16.h>
#include <cstdint>
#include <math.h>

#define NN   20000
#define EE   100000
#define F1   167
#define HIDD 1024
#define EDK  10
#define EAC  12
#define BNCH 40

// ---------------- scratch (device globals) ----------------
__device__ __half g_lin[(size_t)NN * HIDD];
__device__ __half g_hg[(size_t)NN * HIDD];
__device__ float g_hg3[(size_t)NN * 2];
__device__ float g_h  [(size_t)NN * HIDD];
__device__ float g_logw[(size_t)EE * 4];
__device__ float g_ssrc[(size_t)NN * 4];
__device__ float g_sdst[(size_t)NN * 4];
__device__ float g_part1[BNCH * HIDD];
__device__ float g_part2[BNCH * HIDD];
__device__ float g_scale[HIDD];
__device__ float g_shift[HIDD];
__device__ float g_ve[EDK * 4];
__device__ int   g_deg[NN];
__device__ int   g_off[NN + 1];
__device__ int   g_cur[NN];
__device__ int   g_eid[EE];
__device__ __half g_Ah[(size_t)NN * HIDD];
__device__ __half g_B1h[(size_t)HIDD * HIDD];
__device__ __half g_B1l[(size_t)HIDD * HIDD];
__device__ __half g_B2h[(size_t)HIDD * HIDD];
__device__ __half g_B2l[(size_t)HIDD * HIDD];

// ---------------- BatchNorm: partials ----------------
__global__ void k_bnstat(const float* __restrict__ x, float* __restrict__ p1,
                         float* __restrict__ p2, int F) {
    int c = blockIdx.x * blockDim.x + threadIdx.x;
    if (c >= F) return;
    int chunk = (NN + BNCH - 1) / BNCH;
    int r0 = blockIdx.y * chunk;
    int r1 = r0 + chunk; if (r1 > NN) r1 = NN;
    float a = 0.f, b = 0.f;
    for (int r = r0; r < r1; r++) {
        float v = x[(size_t)r * F + c];
        a += v; b += v * v;
    }
    p1[blockIdx.y * F + c] = a;
    p2[blockIdx.y * F + c] = b;
}

__global__ void k_bnfin(const float* __restrict__ p1, const float* __restrict__ p2,
                        const float* __restrict__ g, const float* __restrict__ b,
                        float* __restrict__ scale, float* __restrict__ shift, int F) {
    int c = blockIdx.x * blockDim.x + threadIdx.x;
    if (c >= F) return;
    float a = 0.f, s = 0.f;
    for (int y = 0; y < BNCH; y++) { a += p1[y * F + c]; s += p2[y * F + c]; }
    float invN = 1.f / (float)NN;
    float mu = a * invN;
    float var = s * invN - mu * mu;
    float rstd = rsqrtf(var + 1e-5f);
    float sc = rstd * g[c];
    scale[c] = sc;
    shift[c] = b[c] - mu * sc;
}

// ---------------- prep A (fp16, BN fused) + zero ssrc/sdst ----------------
__global__ void k_prep(const float* __restrict__ x, const float* __restrict__ scale,
                       const float* __restrict__ shift, __half* __restrict__ Ah,
                       float* __restrict__ ssrc, float* __restrict__ sdst,
                       int F, int Kp) {
    size_t na = (size_t)NN * Kp;
    size_t i = (size_t)blockIdx.x * blockDim.x + threadIdx.x;
    if (i < na) {
        int m = (int)(i / Kp), k = (int)(i % Kp);
        float v = 0.f;
        if (k < F) v = x[(size_t)m * F + k] * scale[k] + shift[k];
        Ah[i] = __float2half_rn(v);
    } else if (i < na + (size_t)NN * 4) {
        ssrc[i - na] = 0.f;
    } else if (i < na + (size_t)NN * 8) {
        sdst[i - na - (size_t)NN * 4] = 0.f;
    }
}

// ---------------- prep B: coalesced transpose + fp16 split ----------------
__global__ void k_prepB_t(const float* __restrict__ W1, const float* __restrict__ W2,
                          __half* __restrict__ B1h, __half* __restrict__ B1l,
                          __half* __restrict__ B2h, __half* __restrict__ B2l,
                          int F, int Kp) {
    __shared__ float tile[32][33];
    const float* W = blockIdx.z ? W2 : W1;
    __half* Bh = blockIdx.z ? B2h : B1h;
    __half* Bl = blockIdx.z ? B2l : B1l;
    int k0 = blockIdx.x * 32, n0 = blockIdx.y * 32;
    int tx = threadIdx.x, ty = threadIdx.y;
#pragma unroll
    for (int r = ty; r < 32; r += 8) {
        int k = k0 + r;
        tile[r][tx] = (k < F) ? W[(size_t)k * HIDD + n0 + tx] : 0.f;
    }
    __syncthreads();
#pragma unroll
    for (int r = ty; r < 32; r += 8) {
        int n = n0 + r, k = k0 + tx;
        float v = tile[tx][r];
        __half h = __float2half_rn(v);
        Bh[(size_t)n * Kp + k] = h;
        Bl[(size_t)n * Kp + k] = __float2half_rn(v - __half2float(h));
    }
}

// ---------------- mma.sync helpers ----------------
__device__ __forceinline__ uint32_t smem_u32(const void* p) {
    uint32_t a;
    asm("{ .reg .u64 t; cvta.to.shared.u64 t, %1; cvt.u32.u64 %0, t; }" : "=r"(a) : "l"(p));
    return a;
}
__device__ __forceinline__ void sts128(uint32_t addr, uint4 v) {
    asm volatile("st.shared.v4.b32 [%0], {%1,%2,%3,%4};"
                 :: "r"(addr), "r"(v.x), "r"(v.y), "r"(v.z), "r"(v.w) : "memory");
}
__device__ __forceinline__ void cpasync16(uint32_t s, const void* g) {
    asm volatile("cp.async.cg.shared.global [%0], [%1], 16;" :: "r"(s), "l"(g));
}
#define CP_COMMIT() asm volatile("cp.async.commit_group;" ::: "memory")
#define CP_WAIT0()  asm volatile("cp.async.wait_group 0;" ::: "memory")
#define SWZ(x) ((x) ^ (((x) >> 3) & 0x70))

#define LDSM4(r0, r1, r2, r3, addr) \
    asm volatile("ldmatrix.sync.aligned.m8n8.x4.shared.b16 {%0,%1,%2,%3}, [%4];" \
                 : "=r"(r0), "=r"(r1), "=r"(r2), "=r"(r3) : "r"(addr))

#define MMA_F16(d, a0, a1, a2, a3, b0, b1) \
    asm volatile("mma.sync.aligned.m16n8k16.row.col.f32.f16.f16.f32 " \
                 "{%0,%1,%2,%3}, {%4,%5,%6,%7}, {%8,%9}, {%0,%1,%2,%3};" \
                 : "+f"((d)[0]), "+f"((d)[1]), "+f"((d)[2]), "+f"((d)[3]) \
                 : "r"(a0), "r"(a1), "r"(a2), "r"(a3), "r"(b0), "r"(b1))

// ---------------- fp16 GEMM: 128x128 tile, K-chunk 64, 2-stage, 2 CTA/SM --------
// nt 0-7 -> C1 (lin, fp16, SINGLE pass); nt 8-15 -> C2 (hg, fp16, 2-pass) + attn dots.
#define STAGE_BYTES 49152   // Ah 16K | Bh 16K | Bl 16K
#define GT_SMEM (2 * STAGE_BYTES + 512)

__global__ __launch_bounds__(256, 2) void gemm_mma(
    const __half* __restrict__ Ah, int Kp,
    const __half* __restrict__ B1h, const __half* __restrict__ B1l,
    const __half* __restrict__ B2h, const __half* __restrict__ B2l,
    __half* __restrict__ C1, __half* __restrict__ C2, int M,
    const float* __restrict__ attn, float* __restrict__ ssrc, float* __restrict__ sdst)
{
    extern __shared__ char smraw[];
    uint32_t sb = (smem_u32(smraw) + 255) & ~255u;
    int tid = threadIdx.x, lane = tid & 31, wid = tid >> 5;
    int nt = blockIdx.x, mt = blockIdx.y;

    const __half *Bh, *Bl;
    __half* C;
    int coloff;
    int twoPass = (nt >= 8);
    if (nt < 8) { Bh = B1h; Bl = B1l; C = C1; coloff = nt * 128; }
    else        { Bh = B2h; Bl = B2l; C = C2; coloff = (nt - 8) * 128; }

    int wm = wid & 1, wn = wid >> 1;   // 2 x 4 warp grid; warp tile 64x32

    float acc[4][4][4];
#pragma unroll
    for (int a = 0; a < 4; a++)
#pragma unroll
        for (int b = 0; b < 4; b++)
#pragma unroll
            for (int cc = 0; cc < 4; cc++) acc[a][b][cc] = 0.f;

    uint32_t rawA[4];
    uint32_t rawB[2];
#pragma unroll
    for (int mi = 0; mi < 4; mi++) {
        int row = wm * 64 + mi * 16 + (lane & 15);
        rawA[mi] = (uint32_t)(row * 128 + (lane >> 4) * 16);
    }
#pragma unroll
    for (int p = 0; p < 2; p++) {
        int row = wn * 32 + p * 16 + ((lane >> 4) << 3) + (lane & 7);
        rawB[p] = (uint32_t)(row * 128 + (((lane >> 3) & 1) << 4));
    }

    int q = tid & 7;
    int rr = tid >> 3;
    int chunks = Kp >> 6;

    auto load_stage = [&](int c) {
        uint32_t base = sb + (uint32_t)(c & 1) * STAGE_BYTES;
        uint32_t bAh = base, bBh = base + 16384, bBl = base + 32768;
        size_t kel = (size_t)c * 64 + q * 8;
#pragma unroll
        for (int i = 0; i < 4; i++) {
            int row = rr + i * 32;
            uint32_t soff = SWZ((uint32_t)(row * 128 + q * 16));
            int m = mt * 128 + row;
            if (m < M) {
                cpasync16(bAh + soff, Ah + (size_t)m * Kp + kel);
            } else {
                uint4 z = make_uint4(0, 0, 0, 0);
                sts128(bAh + soff, z);
            }
            int nr = coloff + row;
            cpasync16(bBh + soff, Bh + (size_t)nr * Kp + kel);
            if (twoPass) cpasync16(bBl + soff, Bl + (size_t)nr * Kp + kel);
        }
        CP_COMMIT();
    };

    load_stage(0);

    for (int c = 0; c < chunks; c++) {
        CP_WAIT0();
        __syncthreads();
        if (c + 1 < chunks) load_stage(c + 1);

        uint32_t cur = sb + (uint32_t)(c & 1) * STAGE_BYTES;
        uint32_t cAh = cur, cBh = cur + 16384, cBl = cur + 32768;
#pragma unroll
        for (int k16 = 0; k16 < 4; k16++) {
            uint32_t kb = (uint32_t)k16 * 32;
            uint32_t af0[4], af1[4], af2[4], af3[4];
#pragma unroll
            for (int mi = 0; mi < 4; mi++)
                LDSM4(af0[mi], af1[mi], af2[mi], af3[mi], cAh + SWZ(rawA[mi] + kb));
            uint32_t bh0[4], bh1[4];
#pragma unroll
            for (int pp = 0; pp < 2; pp++) {
                uint32_t addr = SWZ(rawB[pp] + kb);
                uint32_t r0_, r1_, r2_, r3_;
                LDSM4(r0_, r1_, r2_, r3_, cBh + addr);
                bh0[pp * 2] = r0_; bh1[pp * 2] = r1_;
                bh0[pp * 2 + 1] = r2_; bh1[pp * 2 + 1] = r3_;
            }
#pragma unroll
            for (int mi = 0; mi < 4; mi++)
#pragma unroll
                for (int ni = 0; ni < 4; ni++)
                    MMA_F16(acc[mi][ni], af0[mi], af1[mi], af2[mi], af3[mi], bh0[ni], bh1[ni]);
            if (twoPass) {
                uint32_t bl0[4], bl1[4];
#pragma unroll
                for (int pp = 0; pp < 2; pp++) {
                    uint32_t addr = SWZ(rawB[pp] + kb);
                    uint32_t r0_, r1_, r2_, r3_;
                    LDSM4(r0_, r1_, r2_, r3_, cBl + addr);
                    bl0[pp * 2] = r0_; bl1[pp * 2] = r1_;
                    bl0[pp * 2 + 1] = r2_; bl1[pp * 2 + 1] = r3_;
                }
#pragma unroll
                for (int mi = 0; mi < 4; mi++)
#pragma unroll
                    for (int ni = 0; ni < 4; ni++)
                        MMA_F16(acc[mi][ni], af0[mi], af1[mi], af2[mi], af3[mi], bl0[ni], bl1[ni]);
            }
        }
    }

    // epilogue: half2 stores; attn dots on the hg half (nt>=8)
    int doAttn = twoPass;
    int hh = (coloff >> 8) & 3;
    int hcbase = coloff & 255;
    const float* a0p = attn + (size_t)hh * 256;
    const float* a1p = attn + (size_t)(4 + hh) * 256;
#pragma unroll
    for (int mi = 0; mi < 4; mi++) {
        int gr = mt * 128 + wm * 64 + mi * 16 + (lane >> 2);
        float s0 = 0.f, d0 = 0.f, s1 = 0.f, d1 = 0.f;
#pragma unroll
        for (int ni = 0; ni < 4; ni++) {
            int cl = wn * 32 + ni * 8 + ((lane & 3) << 1);
            int gc = coloff + cl;
            if (gr < M)
                *(__half2*)(C + (size_t)gr * HIDD + gc) =
                    __floats2half2_rn(acc[mi][ni][0], acc[mi][ni][1]);
            if (gr + 8 < M)
                *(__half2*)(C + (size_t)(gr + 8) * HIDD + gc) =
                    __floats2half2_rn(acc[mi][ni][2], acc[mi][ni][3]);
            if (doAttn) {
                int cw = hcbase + cl;
                float2 av = *(const float2*)(a0p + cw);
                float2 bv = *(const float2*)(a1p + cw);
                s0 += acc[mi][ni][0] * av.x + acc[mi][ni][1] * av.y;
                d0 += acc[mi][ni][0] * bv.x + acc[mi][ni][1] * bv.y;
                s1 += acc[mi][ni][2] * av.x + acc[mi][ni][3] * av.y;
                d1 += acc[mi][ni][2] * bv.x + acc[mi][ni][3] * bv.y;
            }
        }
        if (doAttn) {
#pragma unroll
            for (int o = 1; o < 4; o <<= 1) {
                s0 += __shfl_xor_sync(0xFFFFFFFFu, s0, o);
                d0 += __shfl_xor_sync(0xFFFFFFFFu, d0, o);
                s1 += __shfl_xor_sync(0xFFFFFFFFu, s1, o);
                d1 += __shfl_xor_sync(0xFFFFFFFFu, d1, o);
            }
            if ((lane & 3) == 0) {
                if (gr < M) {
                    atomicAdd(&ssrc[gr * 4 + hh], s0);
                    atomicAdd(&sdst[gr * 4 + hh], d0);
                }
                if (gr + 8 < M) {
                    atomicAdd(&ssrc[(gr + 8) * 4 + hh], s1);
                    atomicAdd(&sdst[(gr + 8) * 4 + hh], d1);
                }
            }
        }
    }
}

// ---------------- CSR build ----------------
__global__ void k_init(int* deg, int* cur) {
    int i = blockIdx.x * blockDim.x + threadIdx.x;
    if (i < NN) { deg[i] = 0; cur[i] = 0; }
}
__global__ void k_hist(const int* __restrict__ dst, int* __restrict__ deg) {
    int e = blockIdx.x * blockDim.x + threadIdx.x;
    if (e < EE) atomicAdd(&deg[dst[e]], 1);
}
__global__ void k_scan(const int* __restrict__ deg, int* __restrict__ off, int n) {
    __shared__ int sh[1024];
    __shared__ int carry;
    int t = threadIdx.x;
    if (t == 0) { carry = 0; off[0] = 0; }
    __syncthreads();
    for (int base = 0; base < n; base += 1024) {
        int v = (base + t < n) ? deg[base + t] : 0;
        sh[t] = v;
        __syncthreads();
        for (int d = 1; d < 1024; d <<= 1) {
            int add = (t >= d) ? sh[t - d] : 0;
            __syncthreads();
            sh[t] += add;
            __syncthreads();
        }
        if (base + t < n) off[base + t + 1] = carry + sh[t];
        __syncthreads();
        if (t == 0) carry += sh[1023];
        __syncthreads();
    }
}
__global__ void k_scatter(const int* __restrict__ dst, const int* __restrict__ off,
                          int* __restrict__ cur, int* __restrict__ eid) {
    int e = blockIdx.x * blockDim.x + threadIdx.x;
    if (e >= EE) return;
    int d = dst[e];
    int p = atomicAdd(&cur[d], 1);
    eid[off[d] + p] = e;
}

// ---------------- layer-3 tiny GEMM ----------------
__global__ __launch_bounds__(128) void k_gemm_small(
    const float* __restrict__ h, const float* __restrict__ scale,
    const float* __restrict__ shift,
    const float* __restrict__ lw, const float* __restrict__ wg,
    float* __restrict__ lin3, float* __restrict__ hg3)
{
    int n = blockIdx.x, t = threadIdx.x;
    const float* hr = h + (size_t)n * HIDD;
    float a0 = 0, a1 = 0, a2 = 0, a3 = 0;
    for (int k = t; k < HIDD; k += 128) {
        float a = hr[k] * scale[k] + shift[k];
        a0 += a * lw[k * 2];
        a1 += a * lw[k * 2 + 1];
        a2 += a * wg[k * 2];
        a3 += a * wg[k * 2 + 1];
    }
#pragma unroll
    for (int s = 16; s; s >>= 1) {
        a0 += __shfl_down_sync(0xFFFFFFFFu, a0, s);
        a1 += __shfl_down_sync(0xFFFFFFFFu, a1, s);
        a2 += __shfl_down_sync(0xFFFFFFFFu, a2, s);
        a3 += __shfl_down_sync(0xFFFFFFFFu, a3, s);
    }
    __shared__ float sm[4][4];
    if ((t & 31) == 0) {
        sm[t >> 5][0] = a0; sm[t >> 5][1] = a1; sm[t >> 5][2] = a2; sm[t >> 5][3] = a3;
    }
    __syncthreads();
    if (t == 0) {
        lin3[(size_t)n * 2]     = sm[0][0] + sm[1][0] + sm[2][0] + sm[3][0];
        lin3[(size_t)n * 2 + 1] = sm[0][1] + sm[1][1] + sm[2][1] + sm[3][1];
        hg3[(size_t)n * 2]      = sm[0][2] + sm[1][2] + sm[2][2] + sm[3][2];
        hg3[(size_t)n * 2 + 1]  = sm[0][3] + sm[1][3] + sm[2][3] + sm[3][3];
    }
}

// ---------------- GAT pieces ----------------
__global__ void k_ve(const float* __restrict__ We, const float* __restrict__ attn,
                     float* __restrict__ ve, int H, int O) {
    int t = threadIdx.x;
    if (t >= H * EDK) return;
    int h = t / EDK, k = t % EDK;
    const float* a2 = attn + (size_t)(2 * H + h) * O;
    const float* w = We + (size_t)k * H * O + (size_t)h * O;
    float s = 0.f;
    for (int d = 0; d < O; d++) s += w[d] * a2[d];
    ve[k * H + h] = s;
}

__global__ void k_sdots3(const float* __restrict__ hg3, const float* __restrict__ attn,
                         float* __restrict__ ssrc, float* __restrict__ sdst) {
    int n = blockIdx.x * blockDim.x + threadIdx.x;
    if (n >= NN) return;
    float v0 = hg3[(size_t)n * 2], v1 = hg3[(size_t)n * 2 + 1];
    ssrc[n] = v0 * attn[0] + v1 * attn[1];
    sdst[n] = v0 * attn[2] + v1 * attn[3];
}

// fused logits + softmax, H=4
__global__ __launch_bounds__(256) void k_attn4(
    const int* __restrict__ off, const int* __restrict__ eid,
    const int* __restrict__ ei, const float* __restrict__ ea,
    const float* __restrict__ ssrc, const float* __restrict__ sdst,
    const float* __restrict__ ve, const float* __restrict__ at,
    float4* __restrict__ w4)
{
    __shared__ float sve[EDK * 4];
    __shared__ float sat[4];
    if (threadIdx.x < EDK * 4) sve[threadIdx.x] = ve[threadIdx.x];
    if (threadIdx.x < 4) sat[threadIdx.x] = at[threadIdx.x];
    __syncthreads();
    int n = blockIdx.x * blockDim.x + threadIdx.x;
    if (n >= NN) return;
    int d0 = off[n], d1 = off[n + 1];
    if (d0 == d1) return;
    float4 sd = *(const float4*)(sdst + (size_t)n * 4);
    float4 m = make_float4(-INFINITY, -INFINITY, -INFINITY, -INFINITY);
    for (int i = d0; i < d1; i++) {
        int e = eid[i];
        int s = ei[e];
        float4 ss = *(const float4*)(ssrc + (size_t)s * 4);
        const float4* row = (const float4*)(ea + (size_t)e * EAC);
        float4 r0 = row[0], r1 = row[1], r2 = row[2];
        float t = r0.x;
        float ef[10] = {r0.y, r0.z, r0.w, r1.x, r1.y, r1.z, r1.w, r2.x, r2.y, r2.z};
        float4 l;
        float* lp = (float*)&l;
#pragma unroll
        for (int h = 0; h < 4; h++) {
            float se = 0.f;
#pragma unroll
            for (int k = 0; k < EDK; k++) se += ef[k] * sve[k * 4 + h];
            float v = ((float*)&ss)[h] + ((float*)&sd)[h] + se + t * sat[h];
            lp[h] = (v > 0.f) ? v : 0.2f * v;
        }
        w4[e] = l;
        m.x = fmaxf(m.x, l.x); m.y = fmaxf(m.y, l.y);
        m.z = fmaxf(m.z, l.z); m.w = fmaxf(m.w, l.w);
    }
    float4 s = make_float4(0.f, 0.f, 0.f, 0.f);
    for (int i = d0; i < d1; i++) {
        float4 v = w4[eid[i]];
        v.x = expf(v.x - m.x); v.y = expf(v.y - m.y);
        v.z = expf(v.z - m.z); v.w = expf(v.w - m.w);
        w4[eid[i]] = v;
        s.x += v.x; s.y += v.y; s.z += v.z; s.w += v.w;
    }
    float4 inv = make_float4(1.f / (s.x + 1e-16f), 1.f / (s.y + 1e-16f),
                             1.f / (s.z + 1e-16f), 1.f / (s.w + 1e-16f));
    for (int i = d0; i < d1; i++) {
        float4 v = w4[eid[i]];
        v.x *= inv.x; v.y *= inv.y; v.z *= inv.z; v.w *= inv.w;
        w4[eid[i]] = v;
    }
}

// fused logits + softmax, H=1
__global__ __launch_bounds__(256) void k_attn1(
    const int* __restrict__ off, const int* __restrict__ eid,
    const int* __restrict__ ei, const float* __restrict__ ea,
    const float* __restrict__ ssrc, const float* __restrict__ sdst,
    const float* __restrict__ ve, const float* __restrict__ at,
    float* __restrict__ logw)
{
    __shared__ float sve[EDK];
    __shared__ float sat0;
    if (threadIdx.x < EDK) sve[threadIdx.x] = ve[threadIdx.x];
    if (threadIdx.x == 0) sat0 = at[0];
    __syncthreads();
    int n = blockIdx.x * blockDim.x + threadIdx.x;
    if (n >= NN) return;
    int d0 = off[n], d1 = off[n + 1];
    if (d0 == d1) return;
    float sd = sdst[n];
    float m = -INFINITY;
    for (int i = d0; i < d1; i++) {
        int e = eid[i];
        int s = ei[e];
        const float4* row = (const float4*)(ea + (size_t)e * EAC);
        float4 r0 = row[0], r1 = row[1], r2 = row[2];
        float t = r0.x;
        float ef[10] = {r0.y, r0.z, r0.w, r1.x, r1.y, r1.z, r1.w, r2.x, r2.y, r2.z};
        float se = 0.f;
#pragma unroll
        for (int k = 0; k < EDK; k++) se += ef[k] * sve[k];
        float v = ssrc[s] + sd + se + t * sat0;
        v = (v > 0.f) ? v : 0.2f * v;
        logw[e] = v;
        m = fmaxf(m, v);
    }
    float s = 0.f;
    for (int i = d0; i < d1; i++) {
        float p = expf(logw[eid[i]] - m);
        logw[eid[i]] = p;
        s += p;
    }
    float inv = 1.f / (s + 1e-16f);
    for (int i = d0; i < d1; i++) logw[eid[i]] *= inv;
}

// ---------------- aggregation + epilogue (half2-vectorized) ----------------
__global__ __launch_bounds__(256) void k_agg_big(
    const __half* __restrict__ hg, const float* __restrict__ w,
    const int* __restrict__ off, const int* __restrict__ eid,
    const float* __restrict__ ea, const int* __restrict__ src,
    const float* __restrict__ We, const __half* __restrict__ lin,
    const float* __restrict__ lb, const float* __restrict__ cb,
    float* __restrict__ out)
{
    int n = blockIdx.x;
    int t = threadIdx.x;
    __shared__ float qs[40];
    if (t < 40) qs[t] = 0.f;
    int h0 = t >> 7;
    float2 acc0 = make_float2(0.f, 0.f), acc1 = make_float2(0.f, 0.f);
    int d0 = off[n], d1 = off[n + 1];
    for (int i = d0; i < d1; i++) {
        int e = eid[i];
        int s = src[e];
        float4 wv = *(const float4*)(w + (size_t)e * 4);
        const __half2* hr = (const __half2*)(hg + (size_t)s * 1024);
        float2 v0 = __half22float2(hr[t]);
        float2 v1 = __half22float2(hr[t + 256]);
        float w0 = (h0 == 0) ? wv.x : wv.y;
        float w1 = (h0 == 0) ? wv.z : wv.w;
        acc0.x += w0 * v0.x; acc0.y += w0 * v0.y;
        acc1.x += w1 * v1.x; acc1.y += w1 * v1.y;
        if (t < 40) {
            int h = t / 10, k = t % 10;
            float wh = (h == 0) ? wv.x : (h == 1) ? wv.y : (h == 2) ? wv.z : wv.w;
            qs[t] += wh * ea[(size_t)e * EAC + 1 + k];
        }
    }
    __syncthreads();
    int f0 = 2 * t;
    int f1 = 512 + 2 * t;
    int h1 = 2 + h0;
    float e0x = 0.f, e0y = 0.f, e1x = 0.f, e1y = 0.f;
#pragma unroll
    for (int k = 0; k < 10; k++) {
        float q0 = qs[h0 * 10 + k], q1 = qs[h1 * 10 + k];
        float2 w0 = *(const float2*)(We + (size_t)k * 1024 + f0);
        float2 w1 = *(const float2*)(We + (size_t)k * 1024 + f1);
        e0x += q0 * w0.x; e0y += q0 * w0.y;
        e1x += q1 * w1.x; e1y += q1 * w1.y;
    }
    const __half2* ln = (const __half2*)(lin + (size_t)n * 1024);
    float2 l0 = __half22float2(ln[t]);
    float2 l1 = __half22float2(ln[t + 256]);
    float* on = out + (size_t)n * 1024;
    on[f0]     = fmaxf(l0.x + lb[f0] + cb[f0] + acc0.x + e0x, 0.f);
    on[f0 + 1] = fmaxf(l0.y + lb[f0 + 1] + cb[f0 + 1] + acc0.y + e0y, 0.f);
    on[f1]     = fmaxf(l1.x + lb[f1] + cb[f1] + acc1.x + e1x, 0.f);
    on[f1 + 1] = fmaxf(l1.y + lb[f1 + 1] + cb[f1 + 1] + acc1.y + e1y, 0.f);
}

__global__ void k_agg_small(
    const float* __restrict__ hg3, const float* __restrict__ w,
    const int* __restrict__ off, const int* __restrict__ eid,
    const float* __restrict__ ea, const int* __restrict__ src,
    const float* __restrict__ We, const float* __restrict__ lin3,
    const float* __restrict__ lb, const float* __restrict__ cb,
    float* __restrict__ out)
{
    int n = blockIdx.x * blockDim.x + threadIdx.x;
    if (n >= NN) return;
    float a0 = 0.f, a1 = 0.f;
    float q[10];
#pragma unroll
    for (int k = 0; k < 10; k++) q[k] = 0.f;
    int d0 = off[n], d1 = off[n + 1];
    for (int i = d0; i < d1; i++) {
        int e = eid[i];
        int s = src[e];
        float wv = w[e];
        a0 += wv * hg3[(size_t)s * 2];
        a1 += wv * hg3[(size_t)s * 2 + 1];
        const float* row = ea + (size_t)e * EAC;
#pragma unroll
        for (int k = 0; k < 10; k++) q[k] += wv * row[1 + k];
    }
    float e0 = 0.f, e1 = 0.f;
#pragma unroll
    for (int k = 0; k < 10; k++) { e0 += q[k] * We[k * 2]; e1 += q[k] * We[k * 2 + 1]; }
    float v0 = lin3[(size_t)n * 2] + lb[0] + cb[0] + a0 + e0;
    float v1 = lin3[(size_t)n * 2 + 1] + lb[1] + cb[1] + a1 + e1;
    out[(size_t)n * 2] = fmaxf(v0, 0.f);
    out[(size_t)n * 2 + 1] = fmaxf(v1, 0.f);
}

// ---------------- host driver ----------------
static inline int cdiv(int a, int b) { return (a + b - 1) / b; }

struct Scratch {
    float *hg3, *h, *logw, *ssrc, *sdst, *scale, *shift, *ve, *p1, *p2;
    __half *lin, *hg;
    int *deg, *off, *cur, *eid;
    __half *Ah, *B1h, *B1l, *B2h, *B2l;
};

extern "C" void kernel_launch(void* const* d_in, const int* in_sizes, int n_in,
                              void* d_out, int out_size)
{
    const float* x  = (const float*)d_in[0];
    const int*   ei = (const int*)d_in[1];
    const float* ea = (const float*)d_in[2];

    const float *Wg[3], *We[3], *attn[3], *at[3], *cb[3];
    const float *lw[3], *lb[3], *gg[3], *bb[3];

    if (in_sizes[8] == 1048576) {
        for (int i = 0; i < 3; i++) {
            Wg[i]   = (const float*)d_in[3 + 5 * i];
            We[i]   = (const float*)d_in[4 + 5 * i];
            attn[i] = (const float*)d_in[5 + 5 * i];
            at[i]   = (const float*)d_in[6 + 5 * i];
            cb[i]   = (const float*)d_in[7 + 5 * i];
            lw[i]   = (const float*)d_in[18 + 4 * i];
            lb[i]   = (const float*)d_in[19 + 4 * i];
            gg[i]   = (const float*)d_in[20 + 4 * i];
            bb[i]   = (const float*)d_in[21 + 4 * i];
        }
    } else {
        for (int i = 0; i < 3; i++) {
            Wg[i]   = (const float*)d_in[3 + 9 * i];
            We[i]   = (const float*)d_in[4 + 9 * i];
            attn[i] = (const float*)d_in[5 + 9 * i];
            at[i]   = (const float*)d_in[6 + 9 * i];
            cb[i]   = (const float*)d_in[7 + 9 * i];
            lw[i]   = (const float*)d_in[8 + 9 * i];
            lb[i]   = (const float*)d_in[9 + 9 * i];
            gg[i]   = (const float*)d_in[10 + 9 * i];
            bb[i]   = (const float*)d_in[11 + 9 * i];
        }
    }

    Scratch S;
    cudaGetSymbolAddress((void**)&S.lin, g_lin);
    cudaGetSymbolAddress((void**)&S.hg, g_hg);
    cudaGetSymbolAddress((void**)&S.hg3, g_hg3);
    cudaGetSymbolAddress((void**)&S.h, g_h);
    cudaGetSymbolAddress((void**)&S.logw, g_logw);
    cudaGetSymbolAddress((void**)&S.ssrc, g_ssrc);
    cudaGetSymbolAddress((void**)&S.sdst, g_sdst);
    cudaGetSymbolAddress((void**)&S.p1, g_part1);
    cudaGetSymbolAddress((void**)&S.p2, g_part2);
    cudaGetSymbolAddress((void**)&S.scale, g_scale);
    cudaGetSymbolAddress((void**)&S.shift, g_shift);
    cudaGetSymbolAddress((void**)&S.ve, g_ve);
    cudaGetSymbolAddress((void**)&S.deg, g_deg);
    cudaGetSymbolAddress((void**)&S.off, g_off);
    cudaGetSymbolAddress((void**)&S.cur, g_cur);
    cudaGetSymbolAddress((void**)&S.eid, g_eid);
    cudaGetSymbolAddress((void**)&S.Ah, g_Ah);
    cudaGetSymbolAddress((void**)&S.B1h, g_B1h);
    cudaGetSymbolAddress((void**)&S.B1l, g_B1l);
    cudaGetSymbolAddress((void**)&S.B2h, g_B2h);
    cudaGetSymbolAddress((void**)&S.B2l, g_B2l);

    cudaFuncSetAttribute(gemm_mma, cudaFuncAttributeMaxDynamicSharedMemorySize, GT_SMEM);

    // ======== layer 1 ========
    {
        int F = F1, Kp = 192;
        k_bnstat<<<dim3(cdiv(F, 256), BNCH), 256>>>(x, S.p1, S.p2, F);
        k_bnfin<<<cdiv(F, 256), 256>>>(S.p1, S.p2, gg[0], bb[0], S.scale, S.shift, F);
        size_t tp = (size_t)NN * Kp + (size_t)NN * 8;
        k_prep<<<(int)((tp + 255) / 256), 256>>>(x, S.scale, S.shift, S.Ah, S.ssrc, S.sdst, F, Kp);
        k_prepB_t<<<dim3(Kp / 32, 32, 2), dim3(32, 8)>>>(lw[0], Wg[0], S.B1h, S.B1l, S.B2h, S.B2l, F, Kp);
        gemm_mma<<<dim3(16, cdiv(NN, 128)), 256, GT_SMEM>>>(
            S.Ah, Kp, S.B1h, S.B1l, S.B2h, S.B2l, S.lin, S.hg, NN,
            attn[0], S.ssrc, S.sdst);
        k_init<<<cdiv(NN, 256), 256>>>(S.deg, S.cur);
        k_hist<<<cdiv(EE, 256), 256>>>(ei + EE, S.deg);
        k_scan<<<1, 1024>>>(S.deg, S.off, NN);
        k_scatter<<<cdiv(EE, 256), 256>>>(ei + EE, S.off, S.cur, S.eid);
        k_ve<<<1, 64>>>(We[0], attn[0], S.ve, 4, 256);
        k_attn4<<<cdiv(NN, 256), 256>>>(S.off, S.eid, ei, ea, S.ssrc, S.sdst, S.ve, at[0], (float4*)S.logw);
        k_agg_big<<<NN, 256>>>(S.hg, S.logw, S.off, S.eid, ea, ei, We[0], S.lin, lb[0], cb[0], S.h);
    }
    // ======== layer 2 ========
    {
        int F = HIDD, Kp = HIDD;
        k_bnstat<<<dim3(cdiv(F, 256), BNCH), 256>>>(S.h, S.p1, S.p2, F);
        k_bnfin<<<cdiv(F, 256), 256>>>(S.p1, S.p2, gg[1], bb[1], S.scale, S.shift, F);
        size_t tp = (size_t)NN * Kp + (size_t)NN * 8;
        k_prep<<<(int)((tp + 255) / 256), 256>>>(S.h, S.scale, S.shift, S.Ah, S.ssrc, S.sdst, F, Kp);
        k_prepB_t<<<dim3(Kp / 32, 32, 2), dim3(32, 8)>>>(lw[1], Wg[1], S.B1h, S.B1l, S.B2h, S.B2l, F, Kp);
        gemm_mma<<<dim3(16, cdiv(NN, 128)), 256, GT_SMEM>>>(
            S.Ah, Kp, S.B1h, S.B1l, S.B2h, S.B2l, S.lin, S.hg, NN,
            attn[1], S.ssrc, S.sdst);
        k_ve<<<1, 64>>>(We[1], attn[1], S.ve, 4, 256);
        k_attn4<<<cdiv(NN, 256), 256>>>(S.off, S.eid, ei, ea, S.ssrc, S.sdst, S.ve, at[1], (float4*)S.logw);
        k_agg_big<<<NN, 256>>>(S.hg, S.logw, S.off, S.eid, ea, ei, We[1], S.lin, lb[1], cb[1], S.h);
    }
    // ======== layer 3 ========
    {
        k_bnstat<<<dim3(cdiv(HIDD, 256), BNCH), 256>>>(S.h, S.p1, S.p2, HIDD);
        k_bnfin<<<cdiv(HIDD, 256), 256>>>(S.p1, S.p2, gg[2], bb[2], S.scale, S.shift, HIDD);
        float* lin3 = S.p1;
        k_gemm_small<<<NN, 128>>>(S.h, S.scale, S.shift, lw[2], Wg[2], lin3, S.hg3);
        k_ve<<<1, 64>>>(We[2], attn[2], S.ve, 1, 2);
        k_sdots3<<<cdiv(NN, 256), 256>>>(S.hg3, attn[2], S.ssrc, S.sdst);
        k_attn1<<<cdiv(NN, 256), 256>>>(S.off, S.eid, ei, ea, S.ssrc, S.sdst, S.ve, at[2], S.logw);
        k_agg_small<<<cdiv(NN, 256), 256>>>(S.hg3, S.logw, S.off, S.eid, ea, ei, We[2], lin3, lb[2], cb[2], (float*)d_out);
    }
}